// round 1
// baseline (speedup 1.0000x reference)
#include <cuda_runtime.h>
#include <math.h>

// ---------------------------------------------------------------------------
// DECO decomposed:
//   att  = (feat @ W_contact + b_c) @ Wv @ Wo            [16,1024]
//   cont = sigmoid(att @ W_cls + b_cls)                  [16,6890]   -> out[0:]
//   a    = att @ W_ft1[:1024] + b_ft1                    [16,512]
//   P    = pos_emb @ W_ft1[1024:]                        [6890,512]
//   preds[b,v,:] = relu(a[b]+P[v]) @ W_ft2 + b_ft2       [16,6890,133]
//   sem[b,c,v]   = (cont[b,v] > 0.5) ? preds[b,v,c] : 0  -> out[16*6890:]
// (softmax over a length-1 axis == 1, so Wq/Wk/W_scene are dead code)
// ---------------------------------------------------------------------------

#define BB   16
#define DF   1536
#define DD   1024
#define VV   6890
#define PDIM 256
#define HID  512
#define CC   133

__device__ float g_part[BB * DD];
__device__ float g_tmp [BB * DD];
__device__ float g_att [BB * DD];
__device__ float g_a   [BB * HID];
__device__ float g_P   [VV * HID];

// ---------------------------------------------------------------------------
// Small GEMM: out[16,N] = in[16,K] @ W[K,N] (+ bias). One thread per column.
// ---------------------------------------------------------------------------
__global__ void __launch_bounds__(128)
k_bgemm16(const float* __restrict__ in, const float* __restrict__ W,
          const float* __restrict__ bias, float* __restrict__ out,
          int K, int N)
{
    const int d = blockIdx.x * 128 + threadIdx.x;   // column (grid sized so d<N)
    __shared__ float ins[BB][33];
    float acc[BB];
#pragma unroll
    for (int b = 0; b < BB; b++) acc[b] = 0.f;

    for (int k0 = 0; k0 < K; k0 += 32) {
#pragma unroll
        for (int i = 0; i < 4; i++) {
            int e = threadIdx.x + 128 * i;      // 512 elems
            int b = e >> 5, kk = e & 31;
            ins[b][kk] = in[b * K + k0 + kk];
        }
        __syncthreads();
#pragma unroll 8
        for (int kk = 0; kk < 32; kk++) {
            float w = W[(size_t)(k0 + kk) * N + d];
#pragma unroll
            for (int b = 0; b < BB; b++)
                acc[b] = fmaf(ins[b][kk], w, acc[b]);
        }
        __syncthreads();
    }
    float bb = bias ? bias[d] : 0.f;
#pragma unroll
    for (int b = 0; b < BB; b++) out[b * N + d] = acc[b] + bb;
}

// ---------------------------------------------------------------------------
// cont = sigmoid(att @ W_cls + b_cls), written to out[0 : 16*6890]
// ---------------------------------------------------------------------------
__global__ void __launch_bounds__(128)
k_cont(const float* __restrict__ att, const float* __restrict__ Wc,
       const float* __restrict__ bc, float* __restrict__ out)
{
    const int v  = blockIdx.x * 128 + threadIdx.x;
    const int vc = v < VV ? v : VV - 1;
    __shared__ float ins[BB][33];
    float acc[BB];
#pragma unroll
    for (int b = 0; b < BB; b++) acc[b] = 0.f;

    for (int k0 = 0; k0 < DD; k0 += 32) {
#pragma unroll
        for (int i = 0; i < 4; i++) {
            int e = threadIdx.x + 128 * i;
            int b = e >> 5, kk = e & 31;
            ins[b][kk] = att[b * DD + k0 + kk];
        }
        __syncthreads();
#pragma unroll 8
        for (int kk = 0; kk < 32; kk++) {
            float w = Wc[(size_t)(k0 + kk) * VV + vc];
#pragma unroll
            for (int b = 0; b < BB; b++)
                acc[b] = fmaf(ins[b][kk], w, acc[b]);
        }
        __syncthreads();
    }
    if (v < VV) {
        float bb = bc[v];
#pragma unroll
        for (int b = 0; b < BB; b++) {
            float x = acc[b] + bb;
            out[b * VV + v] = 1.f / (1.f + expf(-x));
        }
    }
}

// ---------------------------------------------------------------------------
// P[6890,512] = pos_emb[6890,256] @ W_ft1[1024:1280, 512]
// 64x64 tile, BK=32, 256 threads, 4x4 per thread.
// rows via ty (for broadcast smem reads), cols via tx (coalesced stores).
// ---------------------------------------------------------------------------
__global__ void __launch_bounds__(256)
k_P(const float* __restrict__ pos, const float* __restrict__ W1,
    float* __restrict__ Pout)
{
    const int vbase = blockIdx.x * 64;
    const int hbase = blockIdx.y * 64;
    const int tid = threadIdx.x;
    const int tx = tid & 15;
    const int ty = tid >> 4;

    __shared__ float As[32][68];   // [p][row]
    __shared__ float Bs[32][64];   // [p][h]
    float acc[4][4];
#pragma unroll
    for (int i = 0; i < 4; i++)
#pragma unroll
        for (int j = 0; j < 4; j++) acc[i][j] = 0.f;

    for (int p0 = 0; p0 < PDIM; p0 += 32) {
#pragma unroll
        for (int i = 0; i < 8; i++) {          // 2048 elems
            int e = tid + 256 * i;
            int pp = e & 31, row = e >> 5;
            int v = vbase + row;
            As[pp][row] = (v < VV) ? pos[(size_t)v * PDIM + p0 + pp] : 0.f;
        }
#pragma unroll
        for (int i = 0; i < 8; i++) {          // 2048 elems
            int e = tid + 256 * i;
            int h = e & 63, pp = e >> 6;
            Bs[pp][h] = W1[(size_t)(DD + p0 + pp) * HID + hbase + h];
        }
        __syncthreads();
#pragma unroll 8
        for (int pp = 0; pp < 32; pp++) {
            float av[4], bv[4];
#pragma unroll
            for (int i = 0; i < 4; i++) av[i] = As[pp][ty * 4 + i];
#pragma unroll
            for (int j = 0; j < 4; j++) bv[j] = Bs[pp][tx + 16 * j];
#pragma unroll
            for (int i = 0; i < 4; i++)
#pragma unroll
                for (int j = 0; j < 4; j++)
                    acc[i][j] = fmaf(av[i], bv[j], acc[i][j]);
        }
        __syncthreads();
    }
#pragma unroll
    for (int i = 0; i < 4; i++) {
        int v = vbase + ty * 4 + i;
        if (v >= VV) continue;
#pragma unroll
        for (int j = 0; j < 4; j++)
            Pout[(size_t)v * HID + hbase + tx + 16 * j] = acc[i][j];
    }
}

// ---------------------------------------------------------------------------
// Main: per (b, 64-vertex tile): H = relu(a[b]+P[tile]) [64,512],
// preds = H @ W_ft2 [64,133], masked-scatter into sem[b, c, v].
// 256 threads: rows = tx + 16*i (coalesced v on stores), cols = ty*9 + j.
// ---------------------------------------------------------------------------
__global__ void __launch_bounds__(256)
k_sem(const float* __restrict__ A,   // g_a [16,512]
      const float* __restrict__ P,   // g_P [6890,512]
      const float* __restrict__ W2,  // [512,133]
      const float* __restrict__ b2,  // [133]
      const float* __restrict__ cont,// out[0:16*6890]
      float* __restrict__ sem)       // out + 16*6890
{
    const int b     = blockIdx.y;
    const int vbase = blockIdx.x * 64;
    const int tid = threadIdx.x;
    const int tx = tid & 15;
    const int ty = tid >> 4;

    __shared__ float a_s[HID];
    __shared__ float Hs[32][68];     // [kk][row]
    __shared__ float Ws[32][144];    // [kk][c]

    for (int i = tid; i < HID; i += 256) a_s[i] = A[b * HID + i];

    float acc[4][9];
#pragma unroll
    for (int i = 0; i < 4; i++)
#pragma unroll
        for (int j = 0; j < 9; j++) acc[i][j] = 0.f;

    float bj[9];
#pragma unroll
    for (int j = 0; j < 9; j++) {
        int c = ty * 9 + j;
        bj[j] = (c < CC) ? b2[c] : 0.f;
    }
    __syncthreads();

    for (int k0 = 0; k0 < HID; k0 += 32) {
        // H tile: relu(a + P), 64x32
#pragma unroll
        for (int i = 0; i < 8; i++) {
            int e = tid + 256 * i;
            int kk = e & 31, row = e >> 5;
            int v = vbase + row;
            float pv = (v < VV) ? P[(size_t)v * HID + k0 + kk] : 0.f;
            Hs[kk][row] = fmaxf(pv + a_s[k0 + kk], 0.f);
        }
        // W tile: 32 x 144 (133 real)
#pragma unroll
        for (int i = 0; i < 18; i++) {
            int e = tid + 256 * i;
            int c = e % 144, kk = e / 144;
            Ws[kk][c] = (c < CC) ? W2[(size_t)(k0 + kk) * CC + c] : 0.f;
        }
        __syncthreads();
#pragma unroll 8
        for (int kk = 0; kk < 32; kk++) {
            float hv[4];
#pragma unroll
            for (int i = 0; i < 4; i++) hv[i] = Hs[kk][tx + 16 * i];
#pragma unroll
            for (int j = 0; j < 9; j++) {
                float w = Ws[kk][ty * 9 + j];
#pragma unroll
                for (int i = 0; i < 4; i++)
                    acc[i][j] = fmaf(hv[i], w, acc[i][j]);
            }
        }
        __syncthreads();
    }

    // epilogue: mask + bias + transposed store sem[b, c, v]
#pragma unroll
    for (int i = 0; i < 4; i++) {
        int v = vbase + tx + 16 * i;
        if (v >= VV) continue;
        bool m = cont[b * VV + v] > 0.5f;
#pragma unroll
        for (int j = 0; j < 9; j++) {
            int c = ty * 9 + j;
            if (c < CC) {
                float val = m ? (acc[i][j] + bj[j]) : 0.f;
                sem[((size_t)b * CC + c) * VV + v] = val;
            }
        }
    }
}

// ---------------------------------------------------------------------------
extern "C" void kernel_launch(void* const* d_in, const int* in_sizes, int n_in,
                              void* d_out, int out_size)
{
    const float* features  = (const float*)d_in[0];
    // d_in[1]=W_scene, d_in[2]=b_scene, d_in[5]=Wq, d_in[6]=Wk: dead (softmax==1)
    const float* W_contact = (const float*)d_in[3];
    const float* b_contact = (const float*)d_in[4];
    const float* Wv        = (const float*)d_in[7];
    const float* Wo        = (const float*)d_in[8];
    const float* W_cls     = (const float*)d_in[9];
    const float* b_cls     = (const float*)d_in[10];
    const float* pos_emb   = (const float*)d_in[11];
    const float* W_ft1     = (const float*)d_in[12];
    const float* b_ft1     = (const float*)d_in[13];
    const float* W_ft2     = (const float*)d_in[14];
    const float* b_ft2     = (const float*)d_in[15];

    float* out  = (float*)d_out;
    float* cont = out;                  // [16, 6890]
    float* sem  = out + BB * VV;        // [16, 133, 6890]

    float *part, *tmp, *att, *a, *Pbuf;
    cudaGetSymbolAddress((void**)&part, g_part);
    cudaGetSymbolAddress((void**)&tmp,  g_tmp);
    cudaGetSymbolAddress((void**)&att,  g_att);
    cudaGetSymbolAddress((void**)&a,    g_a);
    cudaGetSymbolAddress((void**)&Pbuf, g_P);

    // att = (feat @ W_contact + b) @ Wv @ Wo
    k_bgemm16<<<DD / 128, 128>>>(features, W_contact, b_contact, part, DF, DD);
    k_bgemm16<<<DD / 128, 128>>>(part, Wv, nullptr, tmp, DD, DD);
    k_bgemm16<<<DD / 128, 128>>>(tmp,  Wo, nullptr, att, DD, DD);

    // cont
    k_cont<<<(VV + 127) / 128, 128>>>(att, W_cls, b_cls, cont);

    // a = att @ W_ft1[:1024] + b_ft1
    k_bgemm16<<<HID / 128, 128>>>(att, W_ft1, b_ft1, a, DD, HID);

    // P = pos_emb @ W_ft1[1024:]
    dim3 gP((VV + 63) / 64, HID / 64);
    k_P<<<gP, 256>>>(pos_emb, W_ft1, Pbuf);

    // main masked GEMM
    dim3 gS((VV + 63) / 64, BB);
    k_sem<<<gS, 256>>>(a, Pbuf, W_ft2, b_ft2, cont, sem);
}

// round 2
// speedup vs baseline: 3.0069x; 3.0069x over previous
#include <cuda_runtime.h>
#include <math.h>

// DECO decomposed (softmax over len-1 axis == 1 → Wq/Wk/W_scene dead):
//   att  = (feat @ W_contact + b_c) @ Wv @ Wo            [16,1024]
//   cont = sigmoid(att @ W_cls + b_cls)                  [16,6890]
//   a    = att @ W_ft1[:1024] + b_ft1                    [16,512]
//   P    = pos_emb @ W_ft1[1024:]                        [6890,512]
//   sem[b,c,v] = mask * (relu(a[b]+P[v]) @ W_ft2 + b2)[c]
// All heavy FMA work uses packed fma.rn.f32x2 (FFMA2).

#define BB   16
#define DF   1536
#define DD   1024
#define VV   6890
#define PDIM 256
#define HID  512
#define CC   133

typedef unsigned long long u64;

__device__ float g_part[BB * DD];
__device__ float g_tmp [BB * DD];
__device__ float g_att [BB * DD];
__device__ float g_a   [BB * HID];
__device__ float g_P   [VV * HID];

__device__ __forceinline__ u64 pk2(float lo, float hi) {
    u64 r; asm("mov.b64 %0, {%1, %2};" : "=l"(r) : "f"(lo), "f"(hi)); return r;
}
__device__ __forceinline__ void upk2(u64 v, float& lo, float& hi) {
    asm("mov.b64 {%0, %1}, %2;" : "=f"(lo), "=f"(hi) : "l"(v));
}
__device__ __forceinline__ u64 ffma2(u64 a, u64 b, u64 c) {
    u64 d; asm("fma.rn.f32x2 %0, %1, %2, %3;" : "=l"(d) : "l"(a), "l"(b), "l"(c));
    return d;
}

// ---------------------------------------------------------------------------
// Split-K skinny GEMM: out[16,N] = in[16,K] @ W[K,N] (+bias) (opt sigmoid).
// 512 threads = 32 cols x 16 K-slices. K staged to smem transposed in 128-k
// chunks; batch dim packed into f32x2. grid.x = ceil(N/32).
// ---------------------------------------------------------------------------
__global__ void __launch_bounds__(512)
k_skinny(const float* __restrict__ in, const float* __restrict__ W,
         const float* __restrict__ bias, float* __restrict__ out,
         int K, int N, int do_sig)
{
    __shared__ float in_s[128 * 18];        // [k][b] pad 18
    __shared__ float red[16 * 512];         // [slc][col][b]

    const int tid  = threadIdx.x;
    const int col  = tid & 31;
    const int slc  = tid >> 5;
    const int colg = blockIdx.x * 32 + col;
    const int colc = colg < N ? colg : N - 1;

    u64 acc2[8];
#pragma unroll
    for (int m = 0; m < 8; m++) acc2[m] = 0ull;

    for (int k0 = 0; k0 < K; k0 += 128) {
        __syncthreads();
#pragma unroll
        for (int i = 0; i < 4; i++) {
            int e = tid + 512 * i;          // 2048 elems
            int b = e >> 7, k = e & 127;
            in_s[k * 18 + b] = in[b * K + k0 + k];
        }
        __syncthreads();
#pragma unroll
        for (int kk = 0; kk < 8; kk++) {
            int k = slc * 8 + kk;
            float w = W[(size_t)(k0 + k) * N + colc];
            u64 w2 = pk2(w, w);
            const u64* ip = (const u64*)&in_s[k * 18];
#pragma unroll
            for (int m = 0; m < 8; m++)
                acc2[m] = ffma2(ip[m], w2, acc2[m]);
        }
    }
    // reduce across 16 slices
    float* rp = &red[slc * 512 + col * 16];
#pragma unroll
    for (int m = 0; m < 8; m++) {
        float lo, hi; upk2(acc2[m], lo, hi);
        rp[2 * m] = lo; rp[2 * m + 1] = hi;
    }
    __syncthreads();
    {
        int c = tid >> 4, b = tid & 15;
        float s = 0.f;
#pragma unroll
        for (int sl = 0; sl < 16; sl++) s += red[sl * 512 + c * 16 + b];
        int cg = blockIdx.x * 32 + c;
        if (cg < N) {
            float bb = bias ? bias[cg] : 0.f;
            float x = s + bb;
            if (do_sig) x = 1.f / (1.f + expf(-x));
            out[b * N + cg] = x;
        }
    }
}

// ---------------------------------------------------------------------------
// P[6890,512] = pos_emb[6890,256] @ W_ft1[1024:1280, :]
// 128 rows x 64 cols per block, 256 threads, col-pair f32x2, coalesced f2 stores.
// ---------------------------------------------------------------------------
__global__ void __launch_bounds__(256)
k_P(const float* __restrict__ pos, const float* __restrict__ W1,
    float* __restrict__ Pout)
{
    const int vbase = blockIdx.x * 128;
    const int hbase = blockIdx.y * 64;
    const int tid = threadIdx.x;
    const int tx = tid & 15;                // col-pair group
    const int ty = tid >> 4;                // 8 rows each

    __shared__ float As[32][130];           // [k][row]
    __shared__ float Bs[32][64];            // [k][h]

    u64 acc[8][2];
#pragma unroll
    for (int i = 0; i < 8; i++) { acc[i][0] = 0ull; acc[i][1] = 0ull; }

    for (int p0 = 0; p0 < PDIM; p0 += 32) {
#pragma unroll
        for (int i = 0; i < 16; i++) {      // 4096 elems
            int e = tid + 256 * i;
            int kk = e & 31, row = e >> 5;
            int v = vbase + row;
            As[kk][row] = (v < VV) ? pos[(size_t)v * PDIM + p0 + kk] : 0.f;
        }
#pragma unroll
        for (int i = 0; i < 8; i++) {       // 2048 elems
            int e = tid + 256 * i;
            int h = e & 63, kk = e >> 6;
            Bs[kk][h] = W1[(size_t)(DD + p0 + kk) * HID + hbase + h];
        }
        __syncthreads();
#pragma unroll
        for (int kk = 0; kk < 32; kk++) {
            u64 bw[2];
#pragma unroll
            for (int j = 0; j < 2; j++)
                bw[j] = *(const u64*)&Bs[kk][2 * (tx + 16 * j)];
#pragma unroll
            for (int i = 0; i < 8; i++) {
                float h = As[kk][ty * 8 + i];
                u64 h2 = pk2(h, h);
#pragma unroll
                for (int j = 0; j < 2; j++)
                    acc[i][j] = ffma2(h2, bw[j], acc[i][j]);
            }
        }
        __syncthreads();
    }
#pragma unroll
    for (int i = 0; i < 8; i++) {
        int v = vbase + ty * 8 + i;
        if (v >= VV) continue;
#pragma unroll
        for (int j = 0; j < 2; j++) {
            float lo, hi; upk2(acc[i][j], lo, hi);
            float2 st = make_float2(lo, hi);
            *(float2*)&Pout[(size_t)v * HID + hbase + 2 * (tx + 16 * j)] = st;
        }
    }
}

// ---------------------------------------------------------------------------
// Main GEMM: per (128-vertex tile, b): H = relu(a[b]+P) [128,512],
// preds = H @ W_ft2 [128,133]; mask; f2 stores into sem[b,c,v].
// Row-pair f32x2: thread owns row pairs {2p,2p+1}, p = tx+16i, cols ty*9+j.
// ---------------------------------------------------------------------------
__global__ void __launch_bounds__(256)
k_sem(const float* __restrict__ A,    // g_a [16,512]
      const float* __restrict__ P,    // g_P [6890,512]
      const float* __restrict__ W2,   // [512,133]
      const float* __restrict__ b2,   // [133]
      const float* __restrict__ cont, // out[0:16*6890]
      float* __restrict__ sem)        // out + 16*6890
{
    const int b     = blockIdx.y;
    const int vbase = blockIdx.x * 128;
    const int tid = threadIdx.x;
    const int tx = tid & 15;
    const int ty = tid >> 4;

    __shared__ float a_s[HID];
    __shared__ float Hs[32][130];     // [kk][row], even stride for f2 loads
    __shared__ float Ws[32][144];     // [kk][c]

    for (int i = tid; i < HID; i += 256) a_s[i] = A[b * HID + i];

    u64 acc[4][9];
#pragma unroll
    for (int i = 0; i < 4; i++)
#pragma unroll
        for (int j = 0; j < 9; j++) acc[i][j] = 0ull;

    __syncthreads();

    for (int k0 = 0; k0 < HID; k0 += 32) {
#pragma unroll
        for (int i = 0; i < 16; i++) {       // 4096 elems
            int e = tid + 256 * i;
            int kk = e & 31, row = e >> 5;
            int v = vbase + row;
            float pv = (v < VV) ? P[(size_t)v * HID + k0 + kk] : 0.f;
            Hs[kk][row] = fmaxf(pv + a_s[k0 + kk], 0.f);
        }
#pragma unroll
        for (int i = 0; i < 18; i++) {       // 4608 elems
            int e = tid + 256 * i;
            int c = e % 144, kk = e / 144;
            Ws[kk][c] = (c < CC) ? W2[(size_t)(k0 + kk) * CC + c] : 0.f;
        }
        __syncthreads();
#pragma unroll
        for (int kk = 0; kk < 32; kk++) {
            u64 hv[4];
#pragma unroll
            for (int i = 0; i < 4; i++)
                hv[i] = *(const u64*)&Hs[kk][2 * (tx + 16 * i)];
#pragma unroll
            for (int j = 0; j < 9; j++) {
                float w = Ws[kk][ty * 9 + j];
                u64 w2 = pk2(w, w);
#pragma unroll
                for (int i = 0; i < 4; i++)
                    acc[i][j] = ffma2(hv[i], w2, acc[i][j]);
            }
        }
        __syncthreads();
    }

    // epilogue: bias + mask + f2 stores (v0 even, VV even -> pair in-bounds)
#pragma unroll
    for (int i = 0; i < 4; i++) {
        int v0 = vbase + 2 * (tx + 16 * i);
        if (v0 >= VV) continue;
        float2 c2 = *(const float2*)&cont[b * VV + v0];
        float m0 = c2.x > 0.5f ? 1.f : 0.f;
        float m1 = c2.y > 0.5f ? 1.f : 0.f;
#pragma unroll
        for (int j = 0; j < 9; j++) {
            int c = ty * 9 + j;
            if (c < CC) {
                float lo, hi; upk2(acc[i][j], lo, hi);
                float2 st = make_float2(m0 * (lo + b2[c]), m1 * (hi + b2[c]));
                *(float2*)&sem[((size_t)b * CC + c) * VV + v0] = st;
            }
        }
    }
}

// ---------------------------------------------------------------------------
extern "C" void kernel_launch(void* const* d_in, const int* in_sizes, int n_in,
                              void* d_out, int out_size)
{
    const float* features  = (const float*)d_in[0];
    const float* W_contact = (const float*)d_in[3];
    const float* b_contact = (const float*)d_in[4];
    const float* Wv        = (const float*)d_in[7];
    const float* Wo        = (const float*)d_in[8];
    const float* W_cls     = (const float*)d_in[9];
    const float* b_cls     = (const float*)d_in[10];
    const float* pos_emb   = (const float*)d_in[11];
    const float* W_ft1     = (const float*)d_in[12];
    const float* b_ft1     = (const float*)d_in[13];
    const float* W_ft2     = (const float*)d_in[14];
    const float* b_ft2     = (const float*)d_in[15];

    float* out  = (float*)d_out;
    float* cont = out;                  // [16, 6890]
    float* sem  = out + BB * VV;        // [16, 133, 6890]

    float *part, *tmp, *att, *a, *Pbuf;
    cudaGetSymbolAddress((void**)&part, g_part);
    cudaGetSymbolAddress((void**)&tmp,  g_tmp);
    cudaGetSymbolAddress((void**)&att,  g_att);
    cudaGetSymbolAddress((void**)&a,    g_a);
    cudaGetSymbolAddress((void**)&Pbuf, g_P);

    // att = (feat @ W_contact + b) @ Wv @ Wo
    k_skinny<<<DD / 32, 512>>>(features, W_contact, b_contact, part, DF, DD, 0);
    k_skinny<<<DD / 32, 512>>>(part, Wv, nullptr, tmp, DD, DD, 0);
    k_skinny<<<DD / 32, 512>>>(tmp,  Wo, nullptr, att, DD, DD, 0);

    // cont = sigmoid(att @ W_cls + b_cls)
    k_skinny<<<(VV + 31) / 32, 512>>>(att, W_cls, b_cls, cont, DD, VV, 1);

    // a = att @ W_ft1[:1024] + b_ft1
    k_skinny<<<HID / 32, 512>>>(att, W_ft1, b_ft1, a, DD, HID, 0);

    // P = pos_emb @ W_ft1[1024:]
    dim3 gP((VV + 127) / 128, HID / 64);
    k_P<<<gP, 256>>>(pos_emb, W_ft1, Pbuf);

    // main masked GEMM
    dim3 gS((VV + 127) / 128, BB);
    k_sem<<<gS, 256>>>(a, Pbuf, W_ft2, b_ft2, cont, sem);
}

// round 4
// speedup vs baseline: 5.3788x; 1.7888x over previous
#include <cuda_runtime.h>
#include <cuda_bf16.h>
#include <math.h>

// DECO decomposed (len-1 softmax == 1 → Wq/Wk/W_scene dead):
//   att  = (feat @ W_contact + b_c) @ Wv @ Wo            [16,1024]
//   cont = sigmoid(att @ W_cls + b_cls)                  [16,6890]
//   a    = att @ W_ft1[:1024] + b_ft1                    [16,512]
//   P    = pos_emb @ W_ft1[1024:]                        [6890,512]
//   sem[b,c,v] = mask * (relu(a[b]+P[v]) @ W_ft2 + b2)[c]
// Main GEMM: mma.sync m16n8k16 bf16 (HMMA), split-bf16 3-term for fp32 accuracy.

#define BB   16
#define DF   1536
#define DD   1024
#define VV   6890
#define PDIM 256
#define HID  512
#define CC   133
#define NC   144          // padded N (18 n8-tiles)
#define LDH  72           // bf16 row stride (144 B) for H and B smem tiles

typedef unsigned long long u64;
typedef unsigned int u32;

__device__ float g_part[BB * DD];
__device__ float g_tmp [BB * DD];
__device__ float g_att [BB * DD];
__device__ float g_a   [BB * HID];
__device__ float g_P   [VV * HID];
// 16 B-chunk images (8 hi + 8 lo): [n=144][k=72 padded] bf16 each
__device__ __align__(16) __nv_bfloat16 g_Bimg[16 * NC * LDH];

__device__ __forceinline__ u64 pk2(float lo, float hi) {
    u64 r; asm("mov.b64 %0, {%1, %2};" : "=l"(r) : "f"(lo), "f"(hi)); return r;
}
__device__ __forceinline__ void upk2(u64 v, float& lo, float& hi) {
    asm("mov.b64 {%0, %1}, %2;" : "=f"(lo), "=f"(hi) : "l"(v));
}
__device__ __forceinline__ u64 ffma2(u64 a, u64 b, u64 c) {
    u64 d; asm("fma.rn.f32x2 %0, %1, %2, %3;" : "=l"(d) : "l"(a), "l"(b), "l"(c));
    return d;
}
__device__ __forceinline__ u32 smem_u32(const void* p) {
    u32 a; asm("{ .reg .u64 t; cvta.to.shared.u64 t, %1; cvt.u32.u64 %0, t; }"
               : "=r"(a) : "l"(p));
    return a;
}
__device__ __forceinline__ void ldm_x4(u32* r, u32 addr) {
    asm volatile("ldmatrix.sync.aligned.m8n8.x4.shared.b16 {%0,%1,%2,%3}, [%4];"
        : "=r"(r[0]), "=r"(r[1]), "=r"(r[2]), "=r"(r[3]) : "r"(addr));
}
__device__ __forceinline__ void ldm_x2(u32* r, u32 addr) {
    asm volatile("ldmatrix.sync.aligned.m8n8.x2.shared.b16 {%0,%1}, [%2];"
        : "=r"(r[0]), "=r"(r[1]) : "r"(addr));
}
__device__ __forceinline__ void mma_bf16(float* d, const u32* a, const u32* b) {
    asm volatile("mma.sync.aligned.m16n8k16.row.col.f32.bf16.bf16.f32 "
        "{%0,%1,%2,%3}, {%4,%5,%6,%7}, {%8,%9}, {%0,%1,%2,%3};"
        : "+f"(d[0]), "+f"(d[1]), "+f"(d[2]), "+f"(d[3])
        : "r"(a[0]), "r"(a[1]), "r"(a[2]), "r"(a[3]), "r"(b[0]), "r"(b[1]));
}

// smem layout for k_sem (bytes)
#define SM_AS   0                        // 512 f32
#define SM_HH   2048                     // 128 x 72 bf16 = 18432
#define SM_HL   (SM_HH + 18432)
#define SM_BH   (SM_HL + 18432)          // 144 x 72 bf16 = 20736
#define SM_BL   (SM_BH + 20736)
#define SM_TOT  (SM_BL + 20736)          // 80384

// ---------------------------------------------------------------------------
// Split-K skinny GEMM: out[16,N] = in[16,K] @ W[K,N] (+bias)
// ---------------------------------------------------------------------------
__global__ void __launch_bounds__(512)
k_skinny(const float* __restrict__ in, const float* __restrict__ W,
         const float* __restrict__ bias, float* __restrict__ out,
         int K, int N, int do_sig)
{
    __shared__ float in_s[128 * 18];
    __shared__ float red[16 * 512];

    const int tid  = threadIdx.x;
    const int col  = tid & 31;
    const int slc  = tid >> 5;
    const int colg = blockIdx.x * 32 + col;
    const int colc = colg < N ? colg : N - 1;

    u64 acc2[8];
#pragma unroll
    for (int m = 0; m < 8; m++) acc2[m] = 0ull;

    for (int k0 = 0; k0 < K; k0 += 128) {
        __syncthreads();
#pragma unroll
        for (int i = 0; i < 4; i++) {
            int e = tid + 512 * i;
            int b = e >> 7, k = e & 127;
            in_s[k * 18 + b] = in[b * K + k0 + k];
        }
        __syncthreads();
#pragma unroll
        for (int kk = 0; kk < 8; kk++) {
            int k = slc * 8 + kk;
            float w = W[(size_t)(k0 + k) * N + colc];
            u64 w2 = pk2(w, w);
            const u64* ip = (const u64*)&in_s[k * 18];
#pragma unroll
            for (int m = 0; m < 8; m++)
                acc2[m] = ffma2(ip[m], w2, acc2[m]);
        }
    }
    float* rp = &red[slc * 512 + col * 16];
#pragma unroll
    for (int m = 0; m < 8; m++) {
        float lo, hi; upk2(acc2[m], lo, hi);
        rp[2 * m] = lo; rp[2 * m + 1] = hi;
    }
    __syncthreads();
    {
        int c = tid >> 4, b = tid & 15;
        float s = 0.f;
#pragma unroll
        for (int sl = 0; sl < 16; sl++) s += red[sl * 512 + c * 16 + b];
        int cg = blockIdx.x * 32 + c;
        if (cg < N) {
            float bb = bias ? bias[cg] : 0.f;
            float x = s + bb;
            if (do_sig) x = 1.f / (1.f + expf(-x));
            out[b * N + cg] = x;
        }
    }
}

// ---------------------------------------------------------------------------
// cont = sigmoid(att @ W_cls + b_cls); float2 col pairs.
// 256 thr = 16 col-pairs x 16 K-slices; grid 216.
// ---------------------------------------------------------------------------
__global__ void __launch_bounds__(256)
k_cont2(const float* __restrict__ att, const float* __restrict__ Wc,
        const float* __restrict__ bc, float* __restrict__ out)
{
    __shared__ float in_s[128 * 18];
    __shared__ float red[16 * 32 * 16];

    const int tid = threadIdx.x;
    const int cp  = tid & 15;
    const int slc = tid >> 4;
    const int col0 = blockIdx.x * 32 + 2 * cp;
    const int colc = col0 <= VV - 2 ? col0 : VV - 2;

    u64 acc[2][8];
#pragma unroll
    for (int j = 0; j < 2; j++)
#pragma unroll
        for (int m = 0; m < 8; m++) acc[j][m] = 0ull;

    for (int k0 = 0; k0 < DD; k0 += 128) {
        __syncthreads();
#pragma unroll
        for (int i = 0; i < 8; i++) {
            int e = tid + 256 * i;
            int b = e >> 7, k = e & 127;
            in_s[k * 18 + b] = att[b * DD + k0 + k];
        }
        __syncthreads();
#pragma unroll
        for (int kk = 0; kk < 8; kk++) {
            int k = slc * 8 + kk;
            float2 w = *(const float2*)&Wc[(size_t)(k0 + k) * VV + colc];
            u64 w0 = pk2(w.x, w.x), w1 = pk2(w.y, w.y);
            const u64* ip = (const u64*)&in_s[k * 18];
#pragma unroll
            for (int m = 0; m < 8; m++) {
                acc[0][m] = ffma2(ip[m], w0, acc[0][m]);
                acc[1][m] = ffma2(ip[m], w1, acc[1][m]);
            }
        }
    }
#pragma unroll
    for (int j = 0; j < 2; j++) {
        float* rp = &red[slc * 512 + (2 * cp + j) * 16];
#pragma unroll
        for (int m = 0; m < 8; m++) {
            float lo, hi; upk2(acc[j][m], lo, hi);
            rp[2 * m] = lo; rp[2 * m + 1] = hi;
        }
    }
    __syncthreads();
    for (int o = tid; o < 512; o += 256) {
        int c = o >> 4, b = o & 15;
        float s = 0.f;
#pragma unroll
        for (int sl = 0; sl < 16; sl++) s += red[sl * 512 + c * 16 + b];
        int cg = blockIdx.x * 32 + c;
        if (cg < VV)
            out[b * VV + cg] = 1.f / (1.f + expf(-(s + bc[cg])));
    }
}

// ---------------------------------------------------------------------------
// P[6890,512] = pos_emb[6890,256] @ W_ft1[1024:1280,:]  (fp32, FFMA2)
// ---------------------------------------------------------------------------
__global__ void __launch_bounds__(256)
k_P(const float* __restrict__ pos, const float* __restrict__ W1,
    float* __restrict__ Pout)
{
    const int vbase = blockIdx.x * 128;
    const int hbase = blockIdx.y * 64;
    const int tid = threadIdx.x;
    const int tx = tid & 15;
    const int ty = tid >> 4;

    __shared__ float As[32][130];
    __shared__ float Bs[32][64];

    u64 acc[8][2];
#pragma unroll
    for (int i = 0; i < 8; i++) { acc[i][0] = 0ull; acc[i][1] = 0ull; }

    for (int p0 = 0; p0 < PDIM; p0 += 32) {
#pragma unroll
        for (int i = 0; i < 16; i++) {
            int e = tid + 256 * i;
            int kk = e & 31, row = e >> 5;
            int v = vbase + row;
            As[kk][row] = (v < VV) ? pos[(size_t)v * PDIM + p0 + kk] : 0.f;
        }
#pragma unroll
        for (int i = 0; i < 8; i++) {
            int e = tid + 256 * i;
            int h = e & 63, kk = e >> 6;
            Bs[kk][h] = W1[(size_t)(DD + p0 + kk) * HID + hbase + h];
        }
        __syncthreads();
#pragma unroll
        for (int kk = 0; kk < 32; kk++) {
            u64 bw[2];
#pragma unroll
            for (int j = 0; j < 2; j++)
                bw[j] = *(const u64*)&Bs[kk][2 * (tx + 16 * j)];
#pragma unroll
            for (int i = 0; i < 8; i++) {
                float h = As[kk][ty * 8 + i];
                u64 h2 = pk2(h, h);
#pragma unroll
                for (int j = 0; j < 2; j++)
                    acc[i][j] = ffma2(h2, bw[j], acc[i][j]);
            }
        }
        __syncthreads();
    }
#pragma unroll
    for (int i = 0; i < 8; i++) {
        int v = vbase + ty * 8 + i;
        if (v >= VV) continue;
#pragma unroll
        for (int j = 0; j < 2; j++) {
            float lo, hi; upk2(acc[i][j], lo, hi);
            *(float2*)&Pout[(size_t)v * HID + hbase + 2 * (tx + 16 * j)]
                = make_float2(lo, hi);
        }
    }
}

// ---------------------------------------------------------------------------
// Build 16 B chunk images from W_ft2 [512,133]: img&7 = k-chunk, img>=8 = lo.
// Layout [n=0..143][k=0..71] bf16, rows n>=133 / k>=64 zero.
// ---------------------------------------------------------------------------
__global__ void k_prepW(const float* __restrict__ W2,
                        __nv_bfloat16* __restrict__ Bimg)
{
    const int img = blockIdx.x;
    const int c = img & 7;
    const bool lo = img >= 8;
    for (int e = threadIdx.x; e < NC * LDH; e += 256) {
        int n = e / LDH, k = e % LDH;
        float w = (n < CC && k < 64) ? W2[(size_t)(c * 64 + k) * CC + n] : 0.f;
        __nv_bfloat16 h = __float2bfloat16(w);
        __nv_bfloat16 val = lo ? __float2bfloat16(w - __bfloat162float(h)) : h;
        Bimg[(size_t)img * (NC * LDH) + e] = val;
    }
}

// ---------------------------------------------------------------------------
// Main GEMM via mma.sync bf16. CTA = (128-v tile, b), 256 thr = 4m x 2n warps.
// Per 64-k chunk: producer splits relu(a+P) -> Hh/Hl smem; copy Bh/Bl images;
// 4 k16 steps x (2 mt x 9 nt x 3 terms) MMA. Epilogue from registers.
// ---------------------------------------------------------------------------
__global__ void __launch_bounds__(256, 2)
k_sem_mma(const float* __restrict__ A,    // g_a [16,512]
          const float* __restrict__ P,    // g_P [6890,512]
          const __nv_bfloat16* __restrict__ Bimg,
          const float* __restrict__ b2,   // [133]
          const float* __restrict__ cont, // out[0:16*6890]
          float* __restrict__ sem)        // out + 16*6890
{
    extern __shared__ char smem[];
    const u32 sb = smem_u32(smem);
    const int tid = threadIdx.x;
    const int wid = tid >> 5;
    const int l   = tid & 31;
    const int b = blockIdx.y;
    const int vbase = blockIdx.x * 128;

    const int wm = wid & 3;       // m-group: rows wm*32..+32 (2 m16 tiles)
    const int wn = wid >> 2;      // n-group: cols wn*72..+72 (9 n8 tiles)

    float* a_sm = (float*)(smem + SM_AS);
    for (int i = tid; i < HID; i += 256) a_sm[i] = A[b * HID + i];

    // producer indexing
    const int r = tid & 127;
    const int half = tid >> 7;
    const int v = vbase + r;
    const bool vok = v < VV;
    const size_t prow = (size_t)v * HID;

    // ldmatrix lane address components (byte offsets, row stride 144B)
    const u32 aln  = (u32)((l & 15) * 144 + (l >> 4) * 16);
    const u32 bln  = (u32)((l & 7) * 144 + ((l >> 3) & 1) * 16 + ((l >> 4) & 1) * (8 * 144));
    const u32 bln2 = (u32)((l & 7) * 144 + ((l >> 3) & 1) * 16);

    const u32 ahA = sb + SM_HH + (u32)(wm * 32 * 144) + aln;
    const u32 alA = sb + SM_HL + (u32)(wm * 32 * 144) + aln;
    const u32 bhA = sb + SM_BH + (u32)(wn * 72 * 144) + bln;
    const u32 blA = sb + SM_BL + (u32)(wn * 72 * 144) + bln;
    const u32 b8h = sb + SM_BH + (u32)((wn * 72 + 64) * 144) + bln2;
    const u32 b8l = sb + SM_BL + (u32)((wn * 72 + 64) * 144) + bln2;

    float acc[2][9][4];
#pragma unroll
    for (int i = 0; i < 2; i++)
#pragma unroll
        for (int j = 0; j < 9; j++)
#pragma unroll
            for (int q = 0; q < 4; q++) acc[i][j][q] = 0.f;

    __syncthreads();

    for (int ch = 0; ch < 8; ch++) {
        const int k0 = ch * 64;
        // --- producer: relu(a+P) -> split bf16 hi/lo, 16B stores
#pragma unroll
        for (int kb = 0; kb < 2; kb++) {
            const int k = half * 32 + kb * 16;
            float x[16];
#pragma unroll
            for (int q = 0; q < 4; q++) {
                float4 p4 = vok ? *(const float4*)(P + prow + k0 + k + 4 * q)
                                : make_float4(0.f, 0.f, 0.f, 0.f);
                x[4*q+0] = fmaxf(p4.x + a_sm[k0 + k + 4*q + 0], 0.f);
                x[4*q+1] = fmaxf(p4.y + a_sm[k0 + k + 4*q + 1], 0.f);
                x[4*q+2] = fmaxf(p4.z + a_sm[k0 + k + 4*q + 2], 0.f);
                x[4*q+3] = fmaxf(p4.w + a_sm[k0 + k + 4*q + 3], 0.f);
            }
            u32 hw[8], lw[8];
#pragma unroll
            for (int i = 0; i < 8; i++) {
                __nv_bfloat16 h0 = __float2bfloat16(x[2*i]);
                __nv_bfloat16 h1 = __float2bfloat16(x[2*i+1]);
                __nv_bfloat16 l0 = __float2bfloat16(x[2*i]   - __bfloat162float(h0));
                __nv_bfloat16 l1 = __float2bfloat16(x[2*i+1] - __bfloat162float(h1));
                hw[i] = (u32)__bfloat16_as_ushort(h0) | ((u32)__bfloat16_as_ushort(h1) << 16);
                lw[i] = (u32)__bfloat16_as_ushort(l0) | ((u32)__bfloat16_as_ushort(l1) << 16);
            }
            const u32 soff = (u32)(r * 144 + k * 2);
            asm volatile("st.shared.v4.b32 [%0], {%1,%2,%3,%4};"
                :: "r"(sb + SM_HH + soff), "r"(hw[0]), "r"(hw[1]), "r"(hw[2]), "r"(hw[3]) : "memory");
            asm volatile("st.shared.v4.b32 [%0], {%1,%2,%3,%4};"
                :: "r"(sb + SM_HH + soff + 16), "r"(hw[4]), "r"(hw[5]), "r"(hw[6]), "r"(hw[7]) : "memory");
            asm volatile("st.shared.v4.b32 [%0], {%1,%2,%3,%4};"
                :: "r"(sb + SM_HL + soff), "r"(lw[0]), "r"(lw[1]), "r"(lw[2]), "r"(lw[3]) : "memory");
            asm volatile("st.shared.v4.b32 [%0], {%1,%2,%3,%4};"
                :: "r"(sb + SM_HL + soff + 16), "r"(lw[4]), "r"(lw[5]), "r"(lw[6]), "r"(lw[7]) : "memory");
        }
        // --- B hi/lo chunk copy (1296 uint4 each)
        {
            const uint4* sH = (const uint4*)(Bimg + (size_t)ch * (NC * LDH));
            const uint4* sL = (const uint4*)(Bimg + (size_t)(ch + 8) * (NC * LDH));
            uint4* dH = (uint4*)(smem + SM_BH);
            uint4* dL = (uint4*)(smem + SM_BL);
            for (int e = tid; e < 1296; e += 256) { dH[e] = sH[e]; dL[e] = sL[e]; }
        }
        __syncthreads();
        // --- MMA: 4 k16 steps
#pragma unroll
        for (int ks = 0; ks < 4; ks++) {
            const u32 ko = (u32)(ks * 32);
            u32 ah[2][4], al[2][4];
#pragma unroll
            for (int mt = 0; mt < 2; mt++) {
                ldm_x4(ah[mt], ahA + (u32)(mt * 16 * 144) + ko);
                ldm_x4(al[mt], alA + (u32)(mt * 16 * 144) + ko);
            }
#pragma unroll
            for (int p = 0; p < 4; p++) {
                u32 bh[4], bl[4];
                ldm_x4(bh, bhA + (u32)(p * 16 * 144) + ko);
                ldm_x4(bl, blA + (u32)(p * 16 * 144) + ko);
#pragma unroll
                for (int mt = 0; mt < 2; mt++)
#pragma unroll
                    for (int t = 0; t < 2; t++) {
                        float* d = acc[mt][p * 2 + t];
                        mma_bf16(d, ah[mt], &bh[2 * t]);
                        mma_bf16(d, ah[mt], &bl[2 * t]);
                        mma_bf16(d, al[mt], &bh[2 * t]);
                    }
            }
            {   // single n-tile 8
                u32 sh[2], sl2[2];
                ldm_x2(sh, b8h + ko);
                ldm_x2(sl2, b8l + ko);
#pragma unroll
                for (int mt = 0; mt < 2; mt++) {
                    float* d = acc[mt][8];
                    mma_bf16(d, ah[mt], sh);
                    mma_bf16(d, ah[mt], sl2);
                    mma_bf16(d, al[mt], sh);
                }
            }
        }
        __syncthreads();
    }

    // --- epilogue: bias + mask + store sem[b, col, v]
    const int g = l >> 2, tg = l & 3;
#pragma unroll
    for (int mt = 0; mt < 2; mt++) {
        const int r0 = wm * 32 + mt * 16 + g;
        const int v0 = vbase + r0, v1 = v0 + 8;
        const bool ok0 = v0 < VV, ok1 = v1 < VV;
        const float m0 = (ok0 && cont[b * VV + v0] > 0.5f) ? 1.f : 0.f;
        const float m1 = (ok1 && cont[b * VV + v1] > 0.5f) ? 1.f : 0.f;
#pragma unroll
        for (int nt = 0; nt < 9; nt++) {
            const int cbase = wn * 72 + nt * 8 + tg * 2;
#pragma unroll
            for (int q = 0; q < 2; q++) {
                const int col = cbase + q;
                if (col >= CC) continue;
                const float bias = __ldg(&b2[col]);
                if (ok0) sem[((size_t)b * CC + col) * VV + v0] = m0 * (acc[mt][nt][q] + bias);
                if (ok1) sem[((size_t)b * CC + col) * VV + v1] = m1 * (acc[mt][nt][2 + q] + bias);
            }
        }
    }
}

// ---------------------------------------------------------------------------
extern "C" void kernel_launch(void* const* d_in, const int* in_sizes, int n_in,
                              void* d_out, int out_size)
{
    const float* features  = (const float*)d_in[0];
    const float* W_contact = (const float*)d_in[3];
    const float* b_contact = (const float*)d_in[4];
    const float* Wv        = (const float*)d_in[7];
    const float* Wo        = (const float*)d_in[8];
    const float* W_cls     = (const float*)d_in[9];
    const float* b_cls     = (const float*)d_in[10];
    const float* pos_emb   = (const float*)d_in[11];
    const float* W_ft1     = (const float*)d_in[12];
    const float* b_ft1     = (const float*)d_in[13];
    const float* W_ft2     = (const float*)d_in[14];
    const float* b_ft2     = (const float*)d_in[15];

    float* out  = (float*)d_out;
    float* cont = out;                  // [16, 6890]
    float* sem  = out + BB * VV;        // [16, 133, 6890]

    float *part, *tmp, *att, *a, *Pbuf;
    __nv_bfloat16* Bimg;
    cudaGetSymbolAddress((void**)&part, g_part);
    cudaGetSymbolAddress((void**)&tmp,  g_tmp);
    cudaGetSymbolAddress((void**)&att,  g_att);
    cudaGetSymbolAddress((void**)&a,    g_a);
    cudaGetSymbolAddress((void**)&Pbuf, g_P);
    cudaGetSymbolAddress((void**)&Bimg, g_Bimg);

    cudaFuncSetAttribute(k_sem_mma, cudaFuncAttributeMaxDynamicSharedMemorySize, SM_TOT);

    // independent prep first
    k_prepW<<<16, 256>>>(W_ft2, Bimg);
    dim3 gP((VV + 127) / 128, HID / 64);
    k_P<<<gP, 256>>>(pos_emb, W_ft1, Pbuf);

    // att = (feat @ W_contact + b) @ Wv @ Wo
    k_skinny<<<DD / 32, 512>>>(features, W_contact, b_contact, part, DF, DD, 0);
    k_skinny<<<DD / 32, 512>>>(part, Wv, nullptr, tmp, DD, DD, 0);
    k_skinny<<<DD / 32, 512>>>(tmp,  Wo, nullptr, att, DD, DD, 0);

    // cont = sigmoid(att @ W_cls + b_cls)
    k_cont2<<<(VV + 31) / 32, 256>>>(att, W_cls, b_cls, cont);

    // a = att @ W_ft1[:1024] + b_ft1
    k_skinny<<<HID / 32, 512>>>(att, W_ft1, b_ft1, a, DD, HID, 0);

    // main masked GEMM on HMMA
    dim3 gS((VV + 127) / 128, BB);
    k_sem_mma<<<gS, 256, SM_TOT>>>(a, Pbuf, Bimg, b_ft2, cont, sem);
}

// round 5
// speedup vs baseline: 5.9230x; 1.1012x over previous
#include <cuda_runtime.h>
#include <cuda_fp16.h>
#include <math.h>

// DECO decomposed (len-1 softmax == 1 → Wq/Wk/W_scene dead):
//   att  = (feat @ W_contact + b_c) @ Wv @ Wo            [16,1024]
//   cont = sigmoid(att @ W_cls + b_cls)                  [16,6890]
//   a    = att @ W_ft1[:1024] + b_ft1                    [16,512]
//   P    = pos_emb @ W_ft1[1024:]                        [6890,512]
//   sem[b,c,v] = mask * (relu(a[b]+P[v]) @ W_ft2 + b2)[c]
// Main GEMM: mma.sync m16n8k16 fp16, 2-term split: Hh*W + Hl*W
// (H exact to ~2^-22 as fp16 hi+lo; W single fp16, rel err ~2^-12).

#define BB   16
#define DF   1536
#define DD   1024
#define VV   6890
#define PDIM 256
#define HID  512
#define CC   133
#define NC   144          // padded N (18 n8-tiles)
#define LDH  72           // fp16 row stride (144 B) for H and B smem tiles

typedef unsigned long long u64;
typedef unsigned int u32;

__device__ float g_part[BB * DD];
__device__ float g_tmp [BB * DD];
__device__ float g_att [BB * DD];
__device__ float g_a   [BB * HID];
__device__ float g_P   [VV * HID];
// 8 B-chunk images (fp16): [n=144][k=72 padded] each
__device__ __align__(16) __half g_Bimg[8 * NC * LDH];

__device__ __forceinline__ u64 pk2(float lo, float hi) {
    u64 r; asm("mov.b64 %0, {%1, %2};" : "=l"(r) : "f"(lo), "f"(hi)); return r;
}
__device__ __forceinline__ void upk2(u64 v, float& lo, float& hi) {
    asm("mov.b64 {%0, %1}, %2;" : "=f"(lo), "=f"(hi) : "l"(v));
}
__device__ __forceinline__ u64 ffma2(u64 a, u64 b, u64 c) {
    u64 d; asm("fma.rn.f32x2 %0, %1, %2, %3;" : "=l"(d) : "l"(a), "l"(b), "l"(c));
    return d;
}
__device__ __forceinline__ u32 smem_u32(const void* p) {
    u32 a; asm("{ .reg .u64 t; cvta.to.shared.u64 t, %1; cvt.u32.u64 %0, t; }"
               : "=r"(a) : "l"(p));
    return a;
}
__device__ __forceinline__ void ldm_x4(u32* r, u32 addr) {
    asm volatile("ldmatrix.sync.aligned.m8n8.x4.shared.b16 {%0,%1,%2,%3}, [%4];"
        : "=r"(r[0]), "=r"(r[1]), "=r"(r[2]), "=r"(r[3]) : "r"(addr));
}
__device__ __forceinline__ void ldm_x2(u32* r, u32 addr) {
    asm volatile("ldmatrix.sync.aligned.m8n8.x2.shared.b16 {%0,%1}, [%2];"
        : "=r"(r[0]), "=r"(r[1]) : "r"(addr));
}
__device__ __forceinline__ void mma_f16(float* d, const u32* a, const u32* b) {
    asm volatile("mma.sync.aligned.m16n8k16.row.col.f32.f16.f16.f32 "
        "{%0,%1,%2,%3}, {%4,%5,%6,%7}, {%8,%9}, {%0,%1,%2,%3};"
        : "+f"(d[0]), "+f"(d[1]), "+f"(d[2]), "+f"(d[3])
        : "r"(a[0]), "r"(a[1]), "r"(a[2]), "r"(a[3]), "r"(b[0]), "r"(b[1]));
}
__device__ __forceinline__ u32 h2u(__half2 h) {
    u32 r; asm("mov.b32 %0, %1;" : "=r"(r) : "r"(*(u32*)&h)); return r;
}

// smem layout for k_sem (bytes)
#define SM_AS   0                        // 512 f32
#define SM_HH   2048                     // 128 x 72 fp16 = 18432
#define SM_HL   (SM_HH + 18432)          // 20480
#define SM_B    (SM_HL + 18432)          // 38912, 144 x 72 fp16 = 20736
#define SM_TOT  (SM_B + 20736)           // 59648

// ---------------------------------------------------------------------------
// Split-K skinny GEMM: out[16,N] = in[16,K] @ W[K,N] (+bias)
// ---------------------------------------------------------------------------
__global__ void __launch_bounds__(512)
k_skinny(const float* __restrict__ in, const float* __restrict__ W,
         const float* __restrict__ bias, float* __restrict__ out,
         int K, int N, int do_sig)
{
    __shared__ float in_s[128 * 18];
    __shared__ float red[16 * 512];

    const int tid  = threadIdx.x;
    const int col  = tid & 31;
    const int slc  = tid >> 5;
    const int colg = blockIdx.x * 32 + col;
    const int colc = colg < N ? colg : N - 1;

    u64 acc2[8];
#pragma unroll
    for (int m = 0; m < 8; m++) acc2[m] = 0ull;

    for (int k0 = 0; k0 < K; k0 += 128) {
        __syncthreads();
#pragma unroll
        for (int i = 0; i < 4; i++) {
            int e = tid + 512 * i;
            int b = e >> 7, k = e & 127;
            in_s[k * 18 + b] = in[b * K + k0 + k];
        }
        __syncthreads();
#pragma unroll
        for (int kk = 0; kk < 8; kk++) {
            int k = slc * 8 + kk;
            float w = W[(size_t)(k0 + k) * N + colc];
            u64 w2 = pk2(w, w);
            const u64* ip = (const u64*)&in_s[k * 18];
#pragma unroll
            for (int m = 0; m < 8; m++)
                acc2[m] = ffma2(ip[m], w2, acc2[m]);
        }
    }
    float* rp = &red[slc * 512 + col * 16];
#pragma unroll
    for (int m = 0; m < 8; m++) {
        float lo, hi; upk2(acc2[m], lo, hi);
        rp[2 * m] = lo; rp[2 * m + 1] = hi;
    }
    __syncthreads();
    {
        int c = tid >> 4, b = tid & 15;
        float s = 0.f;
#pragma unroll
        for (int sl = 0; sl < 16; sl++) s += red[sl * 512 + c * 16 + b];
        int cg = blockIdx.x * 32 + c;
        if (cg < N) {
            float bb = bias ? bias[cg] : 0.f;
            float x = s + bb;
            if (do_sig) x = 1.f / (1.f + expf(-x));
            out[b * N + cg] = x;
        }
    }
}

// ---------------------------------------------------------------------------
// cont = sigmoid(att @ W_cls + b_cls); float2 col pairs.
// ---------------------------------------------------------------------------
__global__ void __launch_bounds__(256)
k_cont2(const float* __restrict__ att, const float* __restrict__ Wc,
        const float* __restrict__ bc, float* __restrict__ out)
{
    __shared__ float in_s[128 * 18];
    __shared__ float red[16 * 32 * 16];

    const int tid = threadIdx.x;
    const int cp  = tid & 15;
    const int slc = tid >> 4;
    const int col0 = blockIdx.x * 32 + 2 * cp;
    const int colc = col0 <= VV - 2 ? col0 : VV - 2;

    u64 acc[2][8];
#pragma unroll
    for (int j = 0; j < 2; j++)
#pragma unroll
        for (int m = 0; m < 8; m++) acc[j][m] = 0ull;

    for (int k0 = 0; k0 < DD; k0 += 128) {
        __syncthreads();
#pragma unroll
        for (int i = 0; i < 8; i++) {
            int e = tid + 256 * i;
            int b = e >> 7, k = e & 127;
            in_s[k * 18 + b] = att[b * DD + k0 + k];
        }
        __syncthreads();
#pragma unroll
        for (int kk = 0; kk < 8; kk++) {
            int k = slc * 8 + kk;
            float2 w = *(const float2*)&Wc[(size_t)(k0 + k) * VV + colc];
            u64 w0 = pk2(w.x, w.x), w1 = pk2(w.y, w.y);
            const u64* ip = (const u64*)&in_s[k * 18];
#pragma unroll
            for (int m = 0; m < 8; m++) {
                acc[0][m] = ffma2(ip[m], w0, acc[0][m]);
                acc[1][m] = ffma2(ip[m], w1, acc[1][m]);
            }
        }
    }
#pragma unroll
    for (int j = 0; j < 2; j++) {
        float* rp = &red[slc * 512 + (2 * cp + j) * 16];
#pragma unroll
        for (int m = 0; m < 8; m++) {
            float lo, hi; upk2(acc[j][m], lo, hi);
            rp[2 * m] = lo; rp[2 * m + 1] = hi;
        }
    }
    __syncthreads();
    for (int o = tid; o < 512; o += 256) {
        int c = o >> 4, b = o & 15;
        float s = 0.f;
#pragma unroll
        for (int sl = 0; sl < 16; sl++) s += red[sl * 512 + c * 16 + b];
        int cg = blockIdx.x * 32 + c;
        if (cg < VV)
            out[b * VV + cg] = 1.f / (1.f + expf(-(s + bc[cg])));
    }
}

// ---------------------------------------------------------------------------
// P[6890,512] = pos_emb[6890,256] @ W_ft1[1024:1280,:]  (fp32, FFMA2)
// ---------------------------------------------------------------------------
__global__ void __launch_bounds__(256)
k_P(const float* __restrict__ pos, const float* __restrict__ W1,
    float* __restrict__ Pout)
{
    const int vbase = blockIdx.x * 128;
    const int hbase = blockIdx.y * 64;
    const int tid = threadIdx.x;
    const int tx = tid & 15;
    const int ty = tid >> 4;

    __shared__ float As[32][130];
    __shared__ float Bs[32][64];

    u64 acc[8][2];
#pragma unroll
    for (int i = 0; i < 8; i++) { acc[i][0] = 0ull; acc[i][1] = 0ull; }

    for (int p0 = 0; p0 < PDIM; p0 += 32) {
#pragma unroll
        for (int i = 0; i < 16; i++) {
            int e = tid + 256 * i;
            int kk = e & 31, row = e >> 5;
            int v = vbase + row;
            As[kk][row] = (v < VV) ? pos[(size_t)v * PDIM + p0 + kk] : 0.f;
        }
#pragma unroll
        for (int i = 0; i < 8; i++) {
            int e = tid + 256 * i;
            int h = e & 63, kk = e >> 6;
            Bs[kk][h] = W1[(size_t)(DD + p0 + kk) * HID + hbase + h];
        }
        __syncthreads();
#pragma unroll
        for (int kk = 0; kk < 32; kk++) {
            u64 bw[2];
#pragma unroll
            for (int j = 0; j < 2; j++)
                bw[j] = *(const u64*)&Bs[kk][2 * (tx + 16 * j)];
#pragma unroll
            for (int i = 0; i < 8; i++) {
                float h = As[kk][ty * 8 + i];
                u64 h2 = pk2(h, h);
#pragma unroll
                for (int j = 0; j < 2; j++)
                    acc[i][j] = ffma2(h2, bw[j], acc[i][j]);
            }
        }
        __syncthreads();
    }
#pragma unroll
    for (int i = 0; i < 8; i++) {
        int v = vbase + ty * 8 + i;
        if (v >= VV) continue;
#pragma unroll
        for (int j = 0; j < 2; j++) {
            float lo, hi; upk2(acc[i][j], lo, hi);
            *(float2*)&Pout[(size_t)v * HID + hbase + 2 * (tx + 16 * j)]
                = make_float2(lo, hi);
        }
    }
}

// ---------------------------------------------------------------------------
// Build 8 fp16 B chunk images from W_ft2 [512,133]:
// img = k-chunk; layout [n=0..143][k=0..71], n>=133 / k>=64 zero.
// ---------------------------------------------------------------------------
__global__ void k_prepW(const float* __restrict__ W2,
                        __half* __restrict__ Bimg)
{
    const int img = blockIdx.x;
    for (int e = threadIdx.x; e < NC * LDH; e += 256) {
        int n = e / LDH, k = e % LDH;
        float w = (n < CC && k < 64) ? W2[(size_t)(img * 64 + k) * CC + n] : 0.f;
        Bimg[(size_t)img * (NC * LDH) + e] = __float2half_rn(w);
    }
}

// ---------------------------------------------------------------------------
// Main GEMM via mma.sync fp16 (2-term H split). CTA = (128-v tile, b),
// 256 thr = 4m x 2n warps. Per 64-k chunk: producer splits relu(a+P) into
// fp16 hi/lo smem; copy B image; 4 k16 steps x (2mt x 9nt x 2 terms) MMA.
// ---------------------------------------------------------------------------
__global__ void __launch_bounds__(256, 2)
k_sem_mma(const float* __restrict__ A,    // g_a [16,512]
          const float* __restrict__ P,    // g_P [6890,512]
          const __half* __restrict__ Bimg,
          const float* __restrict__ b2,   // [133]
          const float* __restrict__ cont, // out[0:16*6890]
          float* __restrict__ sem)        // out + 16*6890
{
    extern __shared__ char smem[];
    const u32 sb = smem_u32(smem);
    const int tid = threadIdx.x;
    const int wid = tid >> 5;
    const int l   = tid & 31;
    const int b = blockIdx.y;
    const int vbase = blockIdx.x * 128;

    const int wm = wid & 3;       // m-group: rows wm*32..+32 (2 m16 tiles)
    const int wn = wid >> 2;      // n-group: cols wn*72..+72 (9 n8 tiles)

    float* a_sm = (float*)(smem + SM_AS);
    for (int i = tid; i < HID; i += 256) a_sm[i] = A[b * HID + i];

    const int r = tid & 127;
    const int half = tid >> 7;
    const int v = vbase + r;
    const bool vok = v < VV;
    const size_t prow = (size_t)v * HID;

    // ldmatrix lane address components (byte offsets, row stride 144B)
    const u32 aln  = (u32)((l & 15) * 144 + (l >> 4) * 16);
    const u32 bln  = (u32)((l & 7) * 144 + ((l >> 3) & 1) * 16 + ((l >> 4) & 1) * (8 * 144));
    const u32 bln2 = (u32)((l & 7) * 144 + ((l >> 3) & 1) * 16);

    const u32 ahA = sb + SM_HH + (u32)(wm * 32 * 144) + aln;
    const u32 alA = sb + SM_HL + (u32)(wm * 32 * 144) + aln;
    const u32 bA  = sb + SM_B  + (u32)(wn * 72 * 144) + bln;
    const u32 b8A = sb + SM_B  + (u32)((wn * 72 + 64) * 144) + bln2;

    float acc[2][9][4];
#pragma unroll
    for (int i = 0; i < 2; i++)
#pragma unroll
        for (int j = 0; j < 9; j++)
#pragma unroll
            for (int q = 0; q < 4; q++) acc[i][j][q] = 0.f;

    __syncthreads();

    for (int ch = 0; ch < 8; ch++) {
        const int k0 = ch * 64;
        // --- producer: relu(a+P) -> fp16 hi + fp16 lo, 16B stores
#pragma unroll
        for (int kb = 0; kb < 2; kb++) {
            const int k = half * 32 + kb * 16;
            float x[16];
#pragma unroll
            for (int q = 0; q < 4; q++) {
                float4 p4 = vok ? *(const float4*)(P + prow + k0 + k + 4 * q)
                                : make_float4(0.f, 0.f, 0.f, 0.f);
                x[4*q+0] = fmaxf(p4.x + a_sm[k0 + k + 4*q + 0], 0.f);
                x[4*q+1] = fmaxf(p4.y + a_sm[k0 + k + 4*q + 1], 0.f);
                x[4*q+2] = fmaxf(p4.z + a_sm[k0 + k + 4*q + 2], 0.f);
                x[4*q+3] = fmaxf(p4.w + a_sm[k0 + k + 4*q + 3], 0.f);
            }
            u32 hw[8], lw[8];
#pragma unroll
            for (int i = 0; i < 8; i++) {
                __half2 hh = __floats2half2_rn(x[2*i], x[2*i+1]);
                float2 hf = __half22float2(hh);
                __half2 hl = __floats2half2_rn(x[2*i] - hf.x, x[2*i+1] - hf.y);
                hw[i] = h2u(hh);
                lw[i] = h2u(hl);
            }
            const u32 soff = (u32)(r * 144 + k * 2);
            asm volatile("st.shared.v4.b32 [%0], {%1,%2,%3,%4};"
                :: "r"(sb + SM_HH + soff), "r"(hw[0]), "r"(hw[1]), "r"(hw[2]), "r"(hw[3]) : "memory");
            asm volatile("st.shared.v4.b32 [%0], {%1,%2,%3,%4};"
                :: "r"(sb + SM_HH + soff + 16), "r"(hw[4]), "r"(hw[5]), "r"(hw[6]), "r"(hw[7]) : "memory");
            asm volatile("st.shared.v4.b32 [%0], {%1,%2,%3,%4};"
                :: "r"(sb + SM_HL + soff), "r"(lw[0]), "r"(lw[1]), "r"(lw[2]), "r"(lw[3]) : "memory");
            asm volatile("st.shared.v4.b32 [%0], {%1,%2,%3,%4};"
                :: "r"(sb + SM_HL + soff + 16), "r"(lw[4]), "r"(lw[5]), "r"(lw[6]), "r"(lw[7]) : "memory");
        }
        // --- B chunk copy (1296 uint4)
        {
            const uint4* sB = (const uint4*)(Bimg + (size_t)ch * (NC * LDH));
            uint4* dB = (uint4*)(smem + SM_B);
            for (int e = tid; e < 1296; e += 256) dB[e] = sB[e];
        }
        __syncthreads();
        // --- MMA: 4 k16 steps x (2mt x 9nt x 2 terms)
#pragma unroll
        for (int ks = 0; ks < 4; ks++) {
            const u32 ko = (u32)(ks * 32);
            u32 ah[2][4], al[2][4];
#pragma unroll
            for (int mt = 0; mt < 2; mt++) {
                ldm_x4(ah[mt], ahA + (u32)(mt * 16 * 144) + ko);
                ldm_x4(al[mt], alA + (u32)(mt * 16 * 144) + ko);
            }
#pragma unroll
            for (int p = 0; p < 4; p++) {
                u32 bb[4];
                ldm_x4(bb, bA + (u32)(p * 16 * 144) + ko);
#pragma unroll
                for (int mt = 0; mt < 2; mt++)
#pragma unroll
                    for (int t = 0; t < 2; t++) {
                        float* d = acc[mt][p * 2 + t];
                        mma_f16(d, ah[mt], &bb[2 * t]);
                        mma_f16(d, al[mt], &bb[2 * t]);
                    }
            }
            {   // n-tile 8 (cols 64..71 of this warp's 72)
                u32 s2[2];
                ldm_x2(s2, b8A + ko);
#pragma unroll
                for (int mt = 0; mt < 2; mt++) {
                    float* d = acc[mt][8];
                    mma_f16(d, ah[mt], s2);
                    mma_f16(d, al[mt], s2);
                }
            }
        }
        __syncthreads();
    }

    // --- epilogue: bias + mask + store sem[b, col, v]
    const int g = l >> 2, tg = l & 3;
#pragma unroll
    for (int mt = 0; mt < 2; mt++) {
        const int r0 = wm * 32 + mt * 16 + g;
        const int v0 = vbase + r0, v1 = v0 + 8;
        const bool ok0 = v0 < VV, ok1 = v1 < VV;
        const float m0 = (ok0 && cont[b * VV + v0] > 0.5f) ? 1.f : 0.f;
        const float m1 = (ok1 && cont[b * VV + v1] > 0.5f) ? 1.f : 0.f;
#pragma unroll
        for (int nt = 0; nt < 9; nt++) {
            const int cbase = wn * 72 + nt * 8 + tg * 2;
#pragma unroll
            for (int q = 0; q < 2; q++) {
                const int col = cbase + q;
                if (col >= CC) continue;
                const float bias = __ldg(&b2[col]);
                if (ok0) sem[((size_t)b * CC + col) * VV + v0] = m0 * (acc[mt][nt][q] + bias);
                if (ok1) sem[((size_t)b * CC + col) * VV + v1] = m1 * (acc[mt][nt][2 + q] + bias);
            }
        }
    }
}

// ---------------------------------------------------------------------------
extern "C" void kernel_launch(void* const* d_in, const int* in_sizes, int n_in,
                              void* d_out, int out_size)
{
    const float* features  = (const float*)d_in[0];
    const float* W_contact = (const float*)d_in[3];
    const float* b_contact = (const float*)d_in[4];
    const float* Wv        = (const float*)d_in[7];
    const float* Wo        = (const float*)d_in[8];
    const float* W_cls     = (const float*)d_in[9];
    const float* b_cls     = (const float*)d_in[10];
    const float* pos_emb   = (const float*)d_in[11];
    const float* W_ft1     = (const float*)d_in[12];
    const float* b_ft1     = (const float*)d_in[13];
    const float* W_ft2     = (const float*)d_in[14];
    const float* b_ft2     = (const float*)d_in[15];

    float* out  = (float*)d_out;
    float* cont = out;                  // [16, 6890]
    float* sem  = out + BB * VV;        // [16, 133, 6890]

    float *part, *tmp, *att, *a, *Pbuf;
    __half* Bimg;
    cudaGetSymbolAddress((void**)&part, g_part);
    cudaGetSymbolAddress((void**)&tmp,  g_tmp);
    cudaGetSymbolAddress((void**)&att,  g_att);
    cudaGetSymbolAddress((void**)&a,    g_a);
    cudaGetSymbolAddress((void**)&Pbuf, g_P);
    cudaGetSymbolAddress((void**)&Bimg, g_Bimg);

    cudaFuncSetAttribute(k_sem_mma, cudaFuncAttributeMaxDynamicSharedMemorySize, SM_TOT);

    // independent prep first
    k_prepW<<<8, 256>>>(W_ft2, Bimg);
    dim3 gP((VV + 127) / 128, HID / 64);
    k_P<<<gP, 256>>>(pos_emb, W_ft1, Pbuf);

    // att = (feat @ W_contact + b) @ Wv @ Wo
    k_skinny<<<DD / 32, 512>>>(features, W_contact, b_contact, part, DF, DD, 0);
    k_skinny<<<DD / 32, 512>>>(part, Wv, nullptr, tmp, DD, DD, 0);
    k_skinny<<<DD / 32, 512>>>(tmp,  Wo, nullptr, att, DD, DD, 0);

    // cont = sigmoid(att @ W_cls + b_cls)
    k_cont2<<<(VV + 31) / 32, 256>>>(att, W_cls, b_cls, cont);

    // a = att @ W_ft1[:1024] + b_ft1
    k_skinny<<<HID / 32, 512>>>(att, W_ft1, b_ft1, a, DD, HID, 0);

    // main masked GEMM on HMMA (fp16 2-term)
    dim3 gS((VV + 127) / 128, BB);
    k_sem_mma<<<gS, 256, SM_TOT>>>(a, Pbuf, Bimg, b_ft2, cont, sem);
}

// round 7
// speedup vs baseline: 6.2065x; 1.0479x over previous
#include <cuda_runtime.h>
#include <cuda_fp16.h>
#include <math.h>

// DECO decomposed (len-1 softmax == 1 → Wq/Wk/W_scene dead):
//   att  = (feat @ W_contact + b_c) @ Wv @ Wo            [16,1024]
//   cont = sigmoid(att @ W_cls + b_cls)                  [16,6890]
//   a    = att @ W_ft1[:1024] + b_ft1                    [16,512]
//   P    = pos_emb @ W_ft1[1024:]                        [6890,512]
//   sem[b,c,v] = mask * (relu(a[b]+P[v]) @ W_ft2 + b2)[c]
// Main GEMM: fp16 mma.sync 2-term H split on MASK-COMPACTED rows,
// XOR-swizzled smem, scatter kernel expands output.

#define BB   16
#define DF   1536
#define DD   1024
#define VV   6890
#define PDIM 256
#define HID  512
#define CC   133
#define NC   144
#define LDH  72

typedef unsigned long long u64;
typedef unsigned int u32;

__device__ float g_part[4 * BB * DD];
__device__ float g_tmp [4 * BB * DD];
__device__ float g_att [4 * BB * DD];
__device__ float g_a   [4 * BB * HID];
__device__ float g_P   [VV * HID];
__device__ int   g_idx [BB * VV];
__device__ int   g_inv [BB * VV];
__device__ int   g_cnt [BB];
__device__ float g_pred[(size_t)BB * NC * VV];   // [b][c][i] compact preds
__device__ __align__(16) __half g_Bimg[8 * NC * LDH];

__device__ __forceinline__ u64 pk2(float lo, float hi) {
    u64 r; asm("mov.b64 %0, {%1, %2};" : "=l"(r) : "f"(lo), "f"(hi)); return r;
}
__device__ __forceinline__ void upk2(u64 v, float& lo, float& hi) {
    asm("mov.b64 {%0, %1}, %2;" : "=f"(lo), "=f"(hi) : "l"(v));
}
__device__ __forceinline__ u64 ffma2(u64 a, u64 b, u64 c) {
    u64 d; asm("fma.rn.f32x2 %0, %1, %2, %3;" : "=l"(d) : "l"(a), "l"(b), "l"(c));
    return d;
}
__device__ __forceinline__ u32 smem_u32(const void* p) {
    u32 a; asm("{ .reg .u64 t; cvta.to.shared.u64 t, %1; cvt.u32.u64 %0, t; }"
               : "=r"(a) : "l"(p));
    return a;
}
__device__ __forceinline__ void ldm_x4(u32* r, u32 addr) {
    asm volatile("ldmatrix.sync.aligned.m8n8.x4.shared.b16 {%0,%1,%2,%3}, [%4];"
        : "=r"(r[0]), "=r"(r[1]), "=r"(r[2]), "=r"(r[3]) : "r"(addr));
}
__device__ __forceinline__ void ldm_x2(u32* r, u32 addr) {
    asm volatile("ldmatrix.sync.aligned.m8n8.x2.shared.b16 {%0,%1}, [%2];"
        : "=r"(r[0]), "=r"(r[1]) : "r"(addr));
}
__device__ __forceinline__ void mma_f16(float* d, const u32* a, const u32* b) {
    asm volatile("mma.sync.aligned.m16n8k16.row.col.f32.f16.f16.f32 "
        "{%0,%1,%2,%3}, {%4,%5,%6,%7}, {%8,%9}, {%0,%1,%2,%3};"
        : "+f"(d[0]), "+f"(d[1]), "+f"(d[2]), "+f"(d[3])
        : "r"(a[0]), "r"(a[1]), "r"(a[2]), "r"(a[3]), "r"(b[0]), "r"(b[1]));
}
__device__ __forceinline__ u32 h2u(__half2 h) {
    u32 r; asm("mov.b32 %0, %1;" : "=r"(r) : "r"(*(u32*)&h)); return r;
}

// smem layout for k_sem (bytes)
#define SM_AS   0                        // 512 f32
#define SM_HH   2048                     // 128 x 72 fp16 = 18432
#define SM_HL   (SM_HH + 18432)
#define SM_B    (SM_HL + 18432)          // 144 x 72 fp16 = 20736
#define SM_TOT  (SM_B + 20736)           // 59648

// ---------------------------------------------------------------------------
// Split-K skinny GEMM: out[gy][16][N] partial = in(sum of nsum copies) @ W
// over k range [gy*K/gridDim.y, ...). Bias added only in slice gy==0.
// ---------------------------------------------------------------------------
__global__ void __launch_bounds__(512)
k_skinny(const float* __restrict__ in, const float* __restrict__ W,
         const float* __restrict__ bias, float* __restrict__ out,
         int K, int N, int nsum)
{
    __shared__ float in_s[128 * 18];
    __shared__ float red[16 * 512];

    const int tid  = threadIdx.x;
    const int col  = tid & 31;
    const int slc  = tid >> 5;
    const int colg = blockIdx.x * 32 + col;
    const int colc = colg < N ? colg : N - 1;
    const int kspan = K / gridDim.y;
    const int kbase = blockIdx.y * kspan;

    u64 acc2[8];
#pragma unroll
    for (int m = 0; m < 8; m++) acc2[m] = 0ull;

    for (int k0 = kbase; k0 < kbase + kspan; k0 += 128) {
        __syncthreads();
#pragma unroll
        for (int i = 0; i < 4; i++) {
            int e = tid + 512 * i;
            int b = e >> 7, k = e & 127;
            float s = 0.f;
            for (int sc = 0; sc < nsum; sc++)
                s += in[(size_t)sc * BB * K + b * K + k0 + k];
            in_s[k * 18 + b] = s;
        }
        __syncthreads();
#pragma unroll
        for (int kk = 0; kk < 8; kk++) {
            int k = slc * 8 + kk;
            float w = W[(size_t)(k0 + k) * N + colc];
            u64 w2 = pk2(w, w);
            const u64* ip = (const u64*)&in_s[k * 18];
#pragma unroll
            for (int m = 0; m < 8; m++)
                acc2[m] = ffma2(ip[m], w2, acc2[m]);
        }
    }
    float* rp = &red[slc * 512 + col * 16];
#pragma unroll
    for (int m = 0; m < 8; m++) {
        float lo, hi; upk2(acc2[m], lo, hi);
        rp[2 * m] = lo; rp[2 * m + 1] = hi;
    }
    __syncthreads();
    {
        int c = tid >> 4, b = tid & 15;
        float s = 0.f;
#pragma unroll
        for (int sl = 0; sl < 16; sl++) s += red[sl * 512 + c * 16 + b];
        int cg = blockIdx.x * 32 + c;
        if (cg < N) {
            float bb = (bias && blockIdx.y == 0) ? bias[cg] : 0.f;
            out[(size_t)blockIdx.y * BB * N + b * N + cg] = s + bb;
        }
    }
}

// ---------------------------------------------------------------------------
// cont = sigmoid(sum4(att) @ W_cls + b_cls); float2 col pairs.
// ---------------------------------------------------------------------------
__global__ void __launch_bounds__(256)
k_cont2(const float* __restrict__ att, const float* __restrict__ Wc,
        const float* __restrict__ bc, float* __restrict__ out)
{
    __shared__ float in_s[128 * 18];
    __shared__ float red[16 * 32 * 16];

    const int tid = threadIdx.x;
    const int cp  = tid & 15;
    const int slc = tid >> 4;
    const int col0 = blockIdx.x * 32 + 2 * cp;
    const int colc = col0 <= VV - 2 ? col0 : VV - 2;

    u64 acc[2][8];
#pragma unroll
    for (int j = 0; j < 2; j++)
#pragma unroll
        for (int m = 0; m < 8; m++) acc[j][m] = 0ull;

    for (int k0 = 0; k0 < DD; k0 += 128) {
        __syncthreads();
#pragma unroll
        for (int i = 0; i < 8; i++) {
            int e = tid + 256 * i;
            int b = e >> 7, k = e & 127;
            float s = 0.f;
#pragma unroll
            for (int sc = 0; sc < 4; sc++)
                s += att[(size_t)sc * BB * DD + b * DD + k0 + k];
            in_s[k * 18 + b] = s;
        }
        __syncthreads();
#pragma unroll
        for (int kk = 0; kk < 8; kk++) {
            int k = slc * 8 + kk;
            float2 w = *(const float2*)&Wc[(size_t)(k0 + k) * VV + colc];
            u64 w0 = pk2(w.x, w.x), w1 = pk2(w.y, w.y);
            const u64* ip = (const u64*)&in_s[k * 18];
#pragma unroll
            for (int m = 0; m < 8; m++) {
                acc[0][m] = ffma2(ip[m], w0, acc[0][m]);
                acc[1][m] = ffma2(ip[m], w1, acc[1][m]);
            }
        }
    }
#pragma unroll
    for (int j = 0; j < 2; j++) {
        float* rp = &red[slc * 512 + (2 * cp + j) * 16];
#pragma unroll
        for (int m = 0; m < 8; m++) {
            float lo, hi; upk2(acc[j][m], lo, hi);
            rp[2 * m] = lo; rp[2 * m + 1] = hi;
        }
    }
    __syncthreads();
    for (int o = tid; o < 512; o += 256) {
        int c = o >> 4, b = o & 15;
        float s = 0.f;
#pragma unroll
        for (int sl = 0; sl < 16; sl++) s += red[sl * 512 + c * 16 + b];
        int cg = blockIdx.x * 32 + c;
        if (cg < VV)
            out[b * VV + cg] = 1.f / (1.f + expf(-(s + bc[cg])));
    }
}

// ---------------------------------------------------------------------------
// P[6890,512] = pos_emb @ W_ft1[1024:1280,:]  (fp32, FFMA2)
// ---------------------------------------------------------------------------
__global__ void __launch_bounds__(256)
k_P(const float* __restrict__ pos, const float* __restrict__ W1,
    float* __restrict__ Pout)
{
    const int vbase = blockIdx.x * 128;
    const int hbase = blockIdx.y * 64;
    const int tid = threadIdx.x;
    const int tx = tid & 15;
    const int ty = tid >> 4;

    __shared__ float As[32][130];
    __shared__ float Bs[32][64];

    u64 acc[8][2];
#pragma unroll
    for (int i = 0; i < 8; i++) { acc[i][0] = 0ull; acc[i][1] = 0ull; }

    for (int p0 = 0; p0 < PDIM; p0 += 32) {
#pragma unroll
        for (int i = 0; i < 16; i++) {
            int e = tid + 256 * i;
            int kk = e & 31, row = e >> 5;
            int v = vbase + row;
            As[kk][row] = (v < VV) ? pos[(size_t)v * PDIM + p0 + kk] : 0.f;
        }
#pragma unroll
        for (int i = 0; i < 8; i++) {
            int e = tid + 256 * i;
            int h = e & 63, kk = e >> 6;
            Bs[kk][h] = W1[(size_t)(DD + p0 + kk) * HID + hbase + h];
        }
        __syncthreads();
#pragma unroll
        for (int kk = 0; kk < 32; kk++) {
            u64 bw[2];
#pragma unroll
            for (int j = 0; j < 2; j++)
                bw[j] = *(const u64*)&Bs[kk][2 * (tx + 16 * j)];
#pragma unroll
            for (int i = 0; i < 8; i++) {
                float h = As[kk][ty * 8 + i];
                u64 h2 = pk2(h, h);
#pragma unroll
                for (int j = 0; j < 2; j++)
                    acc[i][j] = ffma2(h2, bw[j], acc[i][j]);
            }
        }
        __syncthreads();
    }
#pragma unroll
    for (int i = 0; i < 8; i++) {
        int v = vbase + ty * 8 + i;
        if (v >= VV) continue;
#pragma unroll
        for (int j = 0; j < 2; j++) {
            float lo, hi; upk2(acc[i][j], lo, hi);
            *(float2*)&Pout[(size_t)v * HID + hbase + 2 * (tx + 16 * j)]
                = make_float2(lo, hi);
        }
    }
}

// ---------------------------------------------------------------------------
// Build 8 fp16 B chunk images, XOR-swizzled: 16B chunk c of row n stored at
// chunk c ^ ((n>>3)&3) (chunks 0..7; chunk 8 pad untouched).
// ---------------------------------------------------------------------------
__global__ void k_prepW(const float* __restrict__ W2,
                        __half* __restrict__ Bimg)
{
    const int img = blockIdx.x;
    for (int e = threadIdx.x; e < NC * LDH; e += 256) {
        int n = e / LDH, k = e % LDH;
        float w = (n < CC && k < 64) ? W2[(size_t)(img * 64 + k) * CC + n] : 0.f;
        int ck = k >> 3;
        int cs = (ck < 8) ? (ck ^ ((n >> 3) & 3)) : 8;
        int off = n * LDH + cs * 8 + (k & 7);
        Bimg[(size_t)img * (NC * LDH) + off] = __float2half_rn(w);
    }
}

// ---------------------------------------------------------------------------
// Order-preserving mask compaction.
// ---------------------------------------------------------------------------
__global__ void __launch_bounds__(1024)
k_compact(const float* __restrict__ cont, int* __restrict__ idx,
          int* __restrict__ inv, int* __restrict__ cnt)
{
    const int b = blockIdx.x;
    const int tid = threadIdx.x;
    const int lane = tid & 31, wid = tid >> 5;
    __shared__ int wexc[32];
    __shared__ int s_base, s_tot;
    if (tid == 0) s_base = 0;
    __syncthreads();
    for (int v0 = 0; v0 < VV; v0 += 1024) {
        int v = v0 + tid;
        int m = (v < VV) && (cont[b * VV + v] > 0.5f);
        unsigned bal = __ballot_sync(0xffffffffu, m);
        int wsum = __popc(bal);
        int pw = __popc(bal & ((1u << lane) - 1u));
        if (lane == 0) wexc[wid] = wsum;
        __syncthreads();
        if (tid < 32) {
            int sv = wexc[tid];
            int e = sv;
#pragma unroll
            for (int d = 1; d < 32; d <<= 1) {
                int t = __shfl_up_sync(0xffffffffu, e, d);
                if (tid >= d) e += t;
            }
            wexc[tid] = e - sv;
            if (tid == 31) s_tot = e;
        }
        __syncthreads();
        int pos = s_base + wexc[wid] + pw;
        if (v < VV) {
            if (m) { idx[b * VV + pos] = v; inv[b * VV + v] = pos; }
            else inv[b * VV + v] = -1;
        }
        __syncthreads();
        if (tid == 0) s_base += s_tot;
        __syncthreads();
    }
    if (tid == 0) cnt[b] = s_base;
}

// ---------------------------------------------------------------------------
// Main GEMM (compacted rows) via mma.sync fp16 2-term, swizzled smem.
// B ldmatrix lane map (FIXED): row = (l&7) + ((l>>4)&1)*8, k-half = (l>>3)&1
// so fragments pair as {rows t*8.., k0} / {same rows, k1} = bb[2t], bb[2t+1].
// ---------------------------------------------------------------------------
__global__ void __launch_bounds__(256, 2)
k_sem_mma(const float* __restrict__ A4,   // g_a: 4 partials [4][16][512]
          const float* __restrict__ P,
          const __half* __restrict__ Bimg,
          const float* __restrict__ b2,
          const int* __restrict__ idx,
          const int* __restrict__ cnt,
          float* __restrict__ pred)
{
    const int b = blockIdx.y;
    const int cntb = cnt[b];
    const int ibase = blockIdx.x * 128;
    if (ibase >= cntb) return;

    extern __shared__ char smem[];
    const u32 sb = smem_u32(smem);
    const int tid = threadIdx.x;
    const int wid = tid >> 5;
    const int l   = tid & 31;
    const int wm = wid & 3;
    const int wn = wid >> 2;

    float* a_sm = (float*)(smem + SM_AS);
    for (int i = tid; i < HID; i += 256) {
        float s = 0.f;
#pragma unroll
        for (int sc = 0; sc < 4; sc++)
            s += A4[(size_t)sc * BB * HID + b * HID + i];
        a_sm[i] = s;
    }

    const int r = tid & 127;
    const int half = tid >> 7;
    const int ig = ibase + r;
    const int vrow = idx[b * VV + (ig < cntb ? ig : cntb - 1)];
    const size_t prow = (size_t)vrow * HID;
    const u32 qr = ((u32)r >> 3) & 3;

    float acc[2][9][4];
#pragma unroll
    for (int i = 0; i < 2; i++)
#pragma unroll
        for (int j = 0; j < 9; j++)
#pragma unroll
            for (int q = 0; q < 4; q++) acc[i][j][q] = 0.f;

    __syncthreads();

    for (int ch = 0; ch < 8; ch++) {
        const int k0 = ch * 64;
        // --- producer: relu(a+P) -> fp16 hi + lo, swizzled STS.128
#pragma unroll
        for (int kb = 0; kb < 2; kb++) {
            const int k = half * 32 + kb * 16;
            float x[16];
#pragma unroll
            for (int q = 0; q < 4; q++) {
                float4 p4 = *(const float4*)(P + prow + k0 + k + 4 * q);
                x[4*q+0] = fmaxf(p4.x + a_sm[k0 + k + 4*q + 0], 0.f);
                x[4*q+1] = fmaxf(p4.y + a_sm[k0 + k + 4*q + 1], 0.f);
                x[4*q+2] = fmaxf(p4.z + a_sm[k0 + k + 4*q + 2], 0.f);
                x[4*q+3] = fmaxf(p4.w + a_sm[k0 + k + 4*q + 3], 0.f);
            }
            u32 hw[8], lw[8];
#pragma unroll
            for (int i = 0; i < 8; i++) {
                __half2 hh = __floats2half2_rn(x[2*i], x[2*i+1]);
                float2 hf = __half22float2(hh);
                __half2 hl = __floats2half2_rn(x[2*i] - hf.x, x[2*i+1] - hf.y);
                hw[i] = h2u(hh);
                lw[i] = h2u(hl);
            }
            const u32 c0 = (u32)(half * 4 + kb * 2);
            const u32 off0 = (u32)(r * 144) + ((c0 ^ qr) << 4);
            const u32 off1 = (u32)(r * 144) + (((c0 + 1u) ^ qr) << 4);
            asm volatile("st.shared.v4.b32 [%0], {%1,%2,%3,%4};"
                :: "r"(sb + SM_HH + off0), "r"(hw[0]), "r"(hw[1]), "r"(hw[2]), "r"(hw[3]) : "memory");
            asm volatile("st.shared.v4.b32 [%0], {%1,%2,%3,%4};"
                :: "r"(sb + SM_HH + off1), "r"(hw[4]), "r"(hw[5]), "r"(hw[6]), "r"(hw[7]) : "memory");
            asm volatile("st.shared.v4.b32 [%0], {%1,%2,%3,%4};"
                :: "r"(sb + SM_HL + off0), "r"(lw[0]), "r"(lw[1]), "r"(lw[2]), "r"(lw[3]) : "memory");
            asm volatile("st.shared.v4.b32 [%0], {%1,%2,%3,%4};"
                :: "r"(sb + SM_HL + off1), "r"(lw[4]), "r"(lw[5]), "r"(lw[6]), "r"(lw[7]) : "memory");
        }
        // --- B chunk copy (pre-swizzled, raw)
        {
            const uint4* sB = (const uint4*)(Bimg + (size_t)ch * (NC * LDH));
            uint4* dB = (uint4*)(smem + SM_B);
            for (int e = tid; e < 1296; e += 256) dB[e] = sB[e];
        }
        __syncthreads();
        // --- MMA: 4 k16 steps x (2mt x 9nt x 2 terms), swizzled ldmatrix
#pragma unroll
        for (int ks = 0; ks < 4; ks++) {
            u32 ah[2][4], al[2][4];
#pragma unroll
            for (int mt = 0; mt < 2; mt++) {
                int ra = wm * 32 + mt * 16 + (l & 15);
                u32 qa = ((u32)ra >> 3) & 3;
                u32 chk = (((u32)(l >> 4) + 2u * ks) ^ qa) << 4;
                ldm_x4(ah[mt], sb + SM_HH + (u32)(ra * 144) + chk);
                ldm_x4(al[mt], sb + SM_HL + (u32)(ra * 144) + chk);
            }
#pragma unroll
            for (int p = 0; p < 4; p++) {
                // FIXED B lane map: row=(l&7)+((l>>4)&1)*8, k-half=(l>>3)&1
                int rb = wn * 72 + p * 16 + (l & 7) + ((l >> 4) & 1) * 8;
                u32 qb = ((u32)rb >> 3) & 3;
                u32 chk = ((((u32)(l >> 3) & 1u) + 2u * ks) ^ qb) << 4;
                u32 bb[4];
                ldm_x4(bb, sb + SM_B + (u32)(rb * 144) + chk);
#pragma unroll
                for (int mt = 0; mt < 2; mt++)
#pragma unroll
                    for (int t = 0; t < 2; t++) {
                        float* d = acc[mt][p * 2 + t];
                        mma_f16(d, ah[mt], &bb[2 * t]);
                        mma_f16(d, al[mt], &bb[2 * t]);
                    }
            }
            {   // n-tile 8 (cols 64..71 of this warp's span), lanes 0-15
                int rb2 = wn * 72 + 64 + (l & 7);
                u32 qb2 = ((u32)rb2 >> 3) & 3;
                u32 chk = ((((u32)(l >> 3) & 1u) + 2u * ks) ^ qb2) << 4;
                u32 s2[2];
                ldm_x2(s2, sb + SM_B + (u32)(rb2 * 144) + chk);
#pragma unroll
                for (int mt = 0; mt < 2; mt++) {
                    float* d = acc[mt][8];
                    mma_f16(d, ah[mt], s2);
                    mma_f16(d, al[mt], s2);
                }
            }
        }
        __syncthreads();
    }

    // --- epilogue: bias + coalesced store pred[b][col][i]
    const int g = l >> 2, tg = l & 3;
#pragma unroll
    for (int mt = 0; mt < 2; mt++) {
        const int i0 = ibase + wm * 32 + mt * 16 + g;
        const int i1 = i0 + 8;
        const bool ok0 = i0 < cntb, ok1 = i1 < cntb;
#pragma unroll
        for (int nt = 0; nt < 9; nt++) {
            const int cbase = wn * 72 + nt * 8 + tg * 2;
#pragma unroll
            for (int q = 0; q < 2; q++) {
                const int col = cbase + q;
                if (col >= CC) continue;
                const float bias = __ldg(&b2[col]);
                if (ok0) pred[((size_t)b * NC + col) * VV + i0] = acc[mt][nt][q] + bias;
                if (ok1) pred[((size_t)b * NC + col) * VV + i1] = acc[mt][nt][2 + q] + bias;
            }
        }
    }
}

// ---------------------------------------------------------------------------
// Scatter: sem[b,c,v] = inv[v]>=0 ? pred[b,c,inv[v]] : 0. Coalesced writes.
// ---------------------------------------------------------------------------
__global__ void __launch_bounds__(512)
k_scatter(const float* __restrict__ pred, const int* __restrict__ inv,
          float* __restrict__ sem)
{
    const int b = blockIdx.z, c = blockIdx.y;
    const int v = blockIdx.x * 512 + threadIdx.x;
    if (v >= VV) return;
    const int iv = inv[b * VV + v];
    float val = 0.f;
    if (iv >= 0) val = pred[((size_t)b * NC + c) * VV + iv];
    sem[((size_t)b * CC + c) * VV + v] = val;
}

// ---------------------------------------------------------------------------
extern "C" void kernel_launch(void* const* d_in, const int* in_sizes, int n_in,
                              void* d_out, int out_size)
{
    const float* features  = (const float*)d_in[0];
    const float* W_contact = (const float*)d_in[3];
    const float* b_contact = (const float*)d_in[4];
    const float* Wv        = (const float*)d_in[7];
    const float* Wo        = (const float*)d_in[8];
    const float* W_cls     = (const float*)d_in[9];
    const float* b_cls     = (const float*)d_in[10];
    const float* pos_emb   = (const float*)d_in[11];
    const float* W_ft1     = (const float*)d_in[12];
    const float* b_ft1     = (const float*)d_in[13];
    const float* W_ft2     = (const float*)d_in[14];
    const float* b_ft2     = (const float*)d_in[15];

    float* out  = (float*)d_out;
    float* cont = out;                  // [16, 6890]
    float* sem  = out + BB * VV;        // [16, 133, 6890]

    float *part, *tmp, *att, *a, *Pbuf, *pred;
    int *idx, *inv, *cnt;
    __half* Bimg;
    cudaGetSymbolAddress((void**)&part, g_part);
    cudaGetSymbolAddress((void**)&tmp,  g_tmp);
    cudaGetSymbolAddress((void**)&att,  g_att);
    cudaGetSymbolAddress((void**)&a,    g_a);
    cudaGetSymbolAddress((void**)&Pbuf, g_P);
    cudaGetSymbolAddress((void**)&pred, g_pred);
    cudaGetSymbolAddress((void**)&idx,  g_idx);
    cudaGetSymbolAddress((void**)&inv,  g_inv);
    cudaGetSymbolAddress((void**)&cnt,  g_cnt);
    cudaGetSymbolAddress((void**)&Bimg, g_Bimg);

    cudaFuncSetAttribute(k_sem_mma, cudaFuncAttributeMaxDynamicSharedMemorySize, SM_TOT);

    // independent prep
    k_prepW<<<8, 256>>>(W_ft2, Bimg);
    dim3 gP((VV + 127) / 128, HID / 64);
    k_P<<<gP, 256>>>(pos_emb, W_ft1, Pbuf);

    // att chain, 4-way K-split partials
    k_skinny<<<dim3(32, 4), 512>>>(features, W_contact, b_contact, part, DF, DD, 1);
    k_skinny<<<dim3(32, 4), 512>>>(part, Wv, nullptr, tmp, DD, DD, 4);
    k_skinny<<<dim3(32, 4), 512>>>(tmp,  Wo, nullptr, att, DD, DD, 4);

    // cont + a (consume 4 partials)
    k_cont2<<<(VV + 31) / 32, 256>>>(att, W_cls, b_cls, cont);
    k_skinny<<<dim3(16, 4), 512>>>(att, W_ft1, b_ft1, a, DD, HID, 4);

    // compaction
    k_compact<<<BB, 1024>>>(cont, idx, inv, cnt);

    // compacted main GEMM
    dim3 gS((VV + 127) / 128, BB);
    k_sem_mma<<<gS, 256, SM_TOT>>>(a, Pbuf, Bimg, b_ft2, idx, cnt, pred);

    // expand to sem
    dim3 gX((VV + 511) / 512, CC, BB);
    k_scatter<<<gX, 512>>>(pred, inv, sem);
}

// round 8
// speedup vs baseline: 6.2339x; 1.0044x over previous
#include <cuda_runtime.h>
#include <cuda_fp16.h>
#include <math.h>

// DECO decomposed (len-1 softmax == 1 → Wq/Wk/W_scene dead):
//   att  = (feat @ W_contact + b_c) @ Wv @ Wo            [16,1024]
//   cont = sigmoid(att @ W_cls + b_cls)                  [16,6890]
//   a    = att @ W_ft1[:1024] + b_ft1                    [16,512]
//   P    = pos_emb @ W_ft1[1024:]                        [6890,512]
//   sem[b,c,v] = mask * (relu(a[b]+P[v]) @ W_ft2 + b2)[c]
// Main GEMM: fp16 mma.sync 2-term H split, mask-compacted rows,
// SOFTWARE-PIPELINED: double-buffered H/B, register P prefetch, cp.async B.

#define BB   16
#define DF   1536
#define DD   1024
#define VV   6890
#define PDIM 256
#define HID  512
#define CC   133
#define NC   144
#define BROWS 136            // B smem rows (covers n-tiles up to row 135)

typedef unsigned long long u64;
typedef unsigned int u32;

__device__ float g_part[4 * BB * DD];
__device__ float g_tmp [4 * BB * DD];
__device__ float g_att [4 * BB * DD];
__device__ float g_a   [4 * BB * HID];
__device__ float g_P   [VV * HID];
__device__ int   g_idx [BB * VV];
__device__ int   g_inv [BB * VV];
__device__ int   g_cnt [BB];
__device__ float g_pred[(size_t)BB * NC * VV];
// 8 B-chunk images, SW128-swizzled, 136 rows x 64 halves (128 B) each
__device__ __align__(16) __half g_Bimg[8 * BROWS * 64];

__device__ __forceinline__ u64 pk2(float lo, float hi) {
    u64 r; asm("mov.b64 %0, {%1, %2};" : "=l"(r) : "f"(lo), "f"(hi)); return r;
}
__device__ __forceinline__ void upk2(u64 v, float& lo, float& hi) {
    asm("mov.b64 {%0, %1}, %2;" : "=f"(lo), "=f"(hi) : "l"(v));
}
__device__ __forceinline__ u64 ffma2(u64 a, u64 b, u64 c) {
    u64 d; asm("fma.rn.f32x2 %0, %1, %2, %3;" : "=l"(d) : "l"(a), "l"(b), "l"(c));
    return d;
}
__device__ __forceinline__ u32 smem_u32(const void* p) {
    u32 a; asm("{ .reg .u64 t; cvta.to.shared.u64 t, %1; cvt.u32.u64 %0, t; }"
               : "=r"(a) : "l"(p));
    return a;
}
__device__ __forceinline__ void ldm_x4(u32* r, u32 addr) {
    asm volatile("ldmatrix.sync.aligned.m8n8.x4.shared.b16 {%0,%1,%2,%3}, [%4];"
        : "=r"(r[0]), "=r"(r[1]), "=r"(r[2]), "=r"(r[3]) : "r"(addr));
}
__device__ __forceinline__ void ldm_x2(u32* r, u32 addr) {
    asm volatile("ldmatrix.sync.aligned.m8n8.x2.shared.b16 {%0,%1}, [%2];"
        : "=r"(r[0]), "=r"(r[1]) : "r"(addr));
}
__device__ __forceinline__ void mma_f16(float* d, const u32* a, const u32* b) {
    asm volatile("mma.sync.aligned.m16n8k16.row.col.f32.f16.f16.f32 "
        "{%0,%1,%2,%3}, {%4,%5,%6,%7}, {%8,%9}, {%0,%1,%2,%3};"
        : "+f"(d[0]), "+f"(d[1]), "+f"(d[2]), "+f"(d[3])
        : "r"(a[0]), "r"(a[1]), "r"(a[2]), "r"(a[3]), "r"(b[0]), "r"(b[1]));
}
__device__ __forceinline__ u32 h2u(__half2 h) {
    u32 r; asm("mov.b32 %0, %1;" : "=r"(r) : "r"(*(u32*)&h)); return r;
}
__device__ __forceinline__ void cpasync16(u32 dst, const void* src) {
    asm volatile("cp.async.cg.shared.global [%0], [%1], 16;"
                 :: "r"(dst), "l"(src) : "memory");
}
__device__ __forceinline__ void cpasync_commit() {
    asm volatile("cp.async.commit_group;" ::: "memory");
}
__device__ __forceinline__ void cpasync_wait0() {
    asm volatile("cp.async.wait_group 0;" ::: "memory");
}

// smem layout for k_sem (bytes)
#define SM_AS     0                        // 512 f32 = 2048
#define SM_H(bf)  (2048 + (bf) * 36864)    // hi plane; lo plane +18432
#define SM_B(bf)  (75776 + (bf) * 17408)   // 136 x 128 B
#define SM_TOT    110592

// ---------------------------------------------------------------------------
// Split-K skinny GEMM: out[gy][16][N] partial = in(sum nsum copies) @ W
// ---------------------------------------------------------------------------
__global__ void __launch_bounds__(512)
k_skinny(const float* __restrict__ in, const float* __restrict__ W,
         const float* __restrict__ bias, float* __restrict__ out,
         int K, int N, int nsum)
{
    __shared__ float in_s[128 * 18];
    __shared__ float red[16 * 512];

    const int tid  = threadIdx.x;
    const int col  = tid & 31;
    const int slc  = tid >> 5;
    const int colg = blockIdx.x * 32 + col;
    const int colc = colg < N ? colg : N - 1;
    const int kspan = K / gridDim.y;
    const int kbase = blockIdx.y * kspan;

    u64 acc2[8];
#pragma unroll
    for (int m = 0; m < 8; m++) acc2[m] = 0ull;

    for (int k0 = kbase; k0 < kbase + kspan; k0 += 128) {
        __syncthreads();
#pragma unroll
        for (int i = 0; i < 4; i++) {
            int e = tid + 512 * i;
            int b = e >> 7, k = e & 127;
            float s = 0.f;
            for (int sc = 0; sc < nsum; sc++)
                s += in[(size_t)sc * BB * K + b * K + k0 + k];
            in_s[k * 18 + b] = s;
        }
        __syncthreads();
#pragma unroll
        for (int kk = 0; kk < 8; kk++) {
            int k = slc * 8 + kk;
            float w = W[(size_t)(k0 + k) * N + colc];
            u64 w2 = pk2(w, w);
            const u64* ip = (const u64*)&in_s[k * 18];
#pragma unroll
            for (int m = 0; m < 8; m++)
                acc2[m] = ffma2(ip[m], w2, acc2[m]);
        }
    }
    float* rp = &red[slc * 512 + col * 16];
#pragma unroll
    for (int m = 0; m < 8; m++) {
        float lo, hi; upk2(acc2[m], lo, hi);
        rp[2 * m] = lo; rp[2 * m + 1] = hi;
    }
    __syncthreads();
    {
        int c = tid >> 4, b = tid & 15;
        float s = 0.f;
#pragma unroll
        for (int sl = 0; sl < 16; sl++) s += red[sl * 512 + c * 16 + b];
        int cg = blockIdx.x * 32 + c;
        if (cg < N) {
            float bb = (bias && blockIdx.y == 0) ? bias[cg] : 0.f;
            out[(size_t)blockIdx.y * BB * N + b * N + cg] = s + bb;
        }
    }
}

// ---------------------------------------------------------------------------
// cont = sigmoid(sum4(att) @ W_cls + b_cls); float2 col pairs.
// ---------------------------------------------------------------------------
__global__ void __launch_bounds__(256)
k_cont2(const float* __restrict__ att, const float* __restrict__ Wc,
        const float* __restrict__ bc, float* __restrict__ out)
{
    __shared__ float in_s[128 * 18];
    __shared__ float red[16 * 32 * 16];

    const int tid = threadIdx.x;
    const int cp  = tid & 15;
    const int slc = tid >> 4;
    const int col0 = blockIdx.x * 32 + 2 * cp;
    const int colc = col0 <= VV - 2 ? col0 : VV - 2;

    u64 acc[2][8];
#pragma unroll
    for (int j = 0; j < 2; j++)
#pragma unroll
        for (int m = 0; m < 8; m++) acc[j][m] = 0ull;

    for (int k0 = 0; k0 < DD; k0 += 128) {
        __syncthreads();
#pragma unroll
        for (int i = 0; i < 8; i++) {
            int e = tid + 256 * i;
            int b = e >> 7, k = e & 127;
            float s = 0.f;
#pragma unroll
            for (int sc = 0; sc < 4; sc++)
                s += att[(size_t)sc * BB * DD + b * DD + k0 + k];
            in_s[k * 18 + b] = s;
        }
        __syncthreads();
#pragma unroll
        for (int kk = 0; kk < 8; kk++) {
            int k = slc * 8 + kk;
            float2 w = *(const float2*)&Wc[(size_t)(k0 + k) * VV + colc];
            u64 w0 = pk2(w.x, w.x), w1 = pk2(w.y, w.y);
            const u64* ip = (const u64*)&in_s[k * 18];
#pragma unroll
            for (int m = 0; m < 8; m++) {
                acc[0][m] = ffma2(ip[m], w0, acc[0][m]);
                acc[1][m] = ffma2(ip[m], w1, acc[1][m]);
            }
        }
    }
#pragma unroll
    for (int j = 0; j < 2; j++) {
        float* rp = &red[slc * 512 + (2 * cp + j) * 16];
#pragma unroll
        for (int m = 0; m < 8; m++) {
            float lo, hi; upk2(acc[j][m], lo, hi);
            rp[2 * m] = lo; rp[2 * m + 1] = hi;
        }
    }
    __syncthreads();
    for (int o = tid; o < 512; o += 256) {
        int c = o >> 4, b = o & 15;
        float s = 0.f;
#pragma unroll
        for (int sl = 0; sl < 16; sl++) s += red[sl * 512 + c * 16 + b];
        int cg = blockIdx.x * 32 + c;
        if (cg < VV)
            out[b * VV + cg] = 1.f / (1.f + expf(-(s + bc[cg])));
    }
}

// ---------------------------------------------------------------------------
// P[6890,512] = pos_emb @ W_ft1[1024:1280,:]  (fp32, FFMA2)
// ---------------------------------------------------------------------------
__global__ void __launch_bounds__(256)
k_P(const float* __restrict__ pos, const float* __restrict__ W1,
    float* __restrict__ Pout)
{
    const int vbase = blockIdx.x * 128;
    const int hbase = blockIdx.y * 64;
    const int tid = threadIdx.x;
    const int tx = tid & 15;
    const int ty = tid >> 4;

    __shared__ float As[32][130];
    __shared__ float Bs[32][64];

    u64 acc[8][2];
#pragma unroll
    for (int i = 0; i < 8; i++) { acc[i][0] = 0ull; acc[i][1] = 0ull; }

    for (int p0 = 0; p0 < PDIM; p0 += 32) {
#pragma unroll
        for (int i = 0; i < 16; i++) {
            int e = tid + 256 * i;
            int kk = e & 31, row = e >> 5;
            int v = vbase + row;
            As[kk][row] = (v < VV) ? pos[(size_t)v * PDIM + p0 + kk] : 0.f;
        }
#pragma unroll
        for (int i = 0; i < 8; i++) {
            int e = tid + 256 * i;
            int h = e & 63, kk = e >> 6;
            Bs[kk][h] = W1[(size_t)(DD + p0 + kk) * HID + hbase + h];
        }
        __syncthreads();
#pragma unroll
        for (int kk = 0; kk < 32; kk++) {
            u64 bw[2];
#pragma unroll
            for (int j = 0; j < 2; j++)
                bw[j] = *(const u64*)&Bs[kk][2 * (tx + 16 * j)];
#pragma unroll
            for (int i = 0; i < 8; i++) {
                float h = As[kk][ty * 8 + i];
                u64 h2 = pk2(h, h);
#pragma unroll
                for (int j = 0; j < 2; j++)
                    acc[i][j] = ffma2(h2, bw[j], acc[i][j]);
            }
        }
        __syncthreads();
    }
#pragma unroll
    for (int i = 0; i < 8; i++) {
        int v = vbase + ty * 8 + i;
        if (v >= VV) continue;
#pragma unroll
        for (int j = 0; j < 2; j++) {
            float lo, hi; upk2(acc[i][j], lo, hi);
            *(float2*)&Pout[(size_t)v * HID + hbase + 2 * (tx + 16 * j)]
                = make_float2(lo, hi);
        }
    }
}

// ---------------------------------------------------------------------------
// Build 8 fp16 B images, 136 rows x 64 halves, SW128 xor: chunk ^= (n&7).
// ---------------------------------------------------------------------------
__global__ void k_prepW(const float* __restrict__ W2,
                        __half* __restrict__ Bimg)
{
    const int img = blockIdx.x;
    for (int e = threadIdx.x; e < BROWS * 64; e += 256) {
        int n = e >> 6, k = e & 63;
        float w = (n < CC) ? W2[(size_t)(img * 64 + k) * CC + n] : 0.f;
        int off = (n << 6) + (((k >> 3) ^ (n & 7)) << 3) + (k & 7);
        Bimg[(size_t)img * (BROWS * 64) + off] = __float2half_rn(w);
    }
}

// ---------------------------------------------------------------------------
// Order-preserving mask compaction.
// ---------------------------------------------------------------------------
__global__ void __launch_bounds__(1024)
k_compact(const float* __restrict__ cont, int* __restrict__ idx,
          int* __restrict__ inv, int* __restrict__ cnt)
{
    const int b = blockIdx.x;
    const int tid = threadIdx.x;
    const int lane = tid & 31, wid = tid >> 5;
    __shared__ int wexc[32];
    __shared__ int s_base, s_tot;
    if (tid == 0) s_base = 0;
    __syncthreads();
    for (int v0 = 0; v0 < VV; v0 += 1024) {
        int v = v0 + tid;
        int m = (v < VV) && (cont[b * VV + v] > 0.5f);
        unsigned bal = __ballot_sync(0xffffffffu, m);
        int wsum = __popc(bal);
        int pw = __popc(bal & ((1u << lane) - 1u));
        if (lane == 0) wexc[wid] = wsum;
        __syncthreads();
        if (tid < 32) {
            int sv = wexc[tid];
            int e = sv;
#pragma unroll
            for (int d = 1; d < 32; d <<= 1) {
                int t = __shfl_up_sync(0xffffffffu, e, d);
                if (tid >= d) e += t;
            }
            wexc[tid] = e - sv;
            if (tid == 31) s_tot = e;
        }
        __syncthreads();
        int pos = s_base + wexc[wid] + pw;
        if (v < VV) {
            if (m) { idx[b * VV + pos] = v; inv[b * VV + v] = pos; }
            else inv[b * VV + v] = -1;
        }
        __syncthreads();
        if (tid == 0) s_base += s_tot;
        __syncthreads();
    }
    if (tid == 0) cnt[b] = s_base;
}

// ---------------------------------------------------------------------------
// Pipelined main GEMM (compacted rows), fp16 mma.sync 2-term.
// Double-buffered H (stride 144, 2-bit xor) and B (stride 128, SW128 xor).
// Per chunk: one sync; P(ch+1) LDG + B(ch+1) cp.async hidden behind MMA(ch).
// ---------------------------------------------------------------------------
__global__ void __launch_bounds__(256, 2)
k_sem_mma(const float* __restrict__ A4,
          const float* __restrict__ P,
          const __half* __restrict__ Bimg,
          const float* __restrict__ b2,
          const int* __restrict__ idx,
          const int* __restrict__ cnt,
          float* __restrict__ pred)
{
    const int b = blockIdx.y;
    const int cntb = cnt[b];
    const int ibase = blockIdx.x * 128;
    if (ibase >= cntb) return;

    extern __shared__ char smem[];
    const u32 sb = smem_u32(smem);
    const int tid = threadIdx.x;
    const int wid = tid >> 5;
    const int l   = tid & 31;
    const int wm = wid & 3;
    const int wn = wid >> 2;

    float* a_sm = (float*)(smem + SM_AS);
    for (int i = tid; i < HID; i += 256) {
        float s = 0.f;
#pragma unroll
        for (int sc = 0; sc < 4; sc++)
            s += A4[(size_t)sc * BB * HID + b * HID + i];
        a_sm[i] = s;
    }

    const int r = tid & 127;
    const int half = tid >> 7;
    const int ig = ibase + r;
    const int vrow = idx[b * VV + (ig < cntb ? ig : cntb - 1)];
    const float* __restrict__ prow = P + (size_t)vrow * HID + half * 32;
    const u32 qr = ((u32)r >> 3) & 3;
    const u32 hbase_off = (u32)(r * 144);

    float acc[2][9][4];
#pragma unroll
    for (int i = 0; i < 2; i++)
#pragma unroll
        for (int j = 0; j < 9; j++)
#pragma unroll
            for (int q = 0; q < 4; q++) acc[i][j][q] = 0.f;

    float4 pf[8];

    // ---- prologue: B(0) cp.async, P(0) load, H(0) produce
    {
        const char* srcB = (const char*)(Bimg);
        u32 dstB = sb + SM_B(0);
        for (int e = tid; e < 1088; e += 256)
            cpasync16(dstB + e * 16, srcB + e * 16);
        cpasync_commit();
    }
#pragma unroll
    for (int q = 0; q < 8; q++) pf[q] = *(const float4*)(prow + 4 * q);
    __syncthreads();   // a_sm ready
#pragma unroll
    for (int kb = 0; kb < 2; kb++) {
        float x[16];
#pragma unroll
        for (int q = 0; q < 4; q++) {
            float4 p4 = pf[kb * 4 + q];
            const float* ap = a_sm + half * 32 + kb * 16 + 4 * q;
            x[4*q+0] = fmaxf(p4.x + ap[0], 0.f);
            x[4*q+1] = fmaxf(p4.y + ap[1], 0.f);
            x[4*q+2] = fmaxf(p4.z + ap[2], 0.f);
            x[4*q+3] = fmaxf(p4.w + ap[3], 0.f);
        }
        u32 hw[8], lw[8];
#pragma unroll
        for (int i = 0; i < 8; i++) {
            __half2 hh = __floats2half2_rn(x[2*i], x[2*i+1]);
            float2 hf = __half22float2(hh);
            __half2 hl = __floats2half2_rn(x[2*i] - hf.x, x[2*i+1] - hf.y);
            hw[i] = h2u(hh); lw[i] = h2u(hl);
        }
        const u32 c0 = (u32)(half * 4 + kb * 2);
        const u32 off0 = hbase_off + ((c0 ^ qr) << 4);
        const u32 off1 = hbase_off + (((c0 + 1u) ^ qr) << 4);
        asm volatile("st.shared.v4.b32 [%0], {%1,%2,%3,%4};"
            :: "r"(sb + SM_H(0) + off0), "r"(hw[0]), "r"(hw[1]), "r"(hw[2]), "r"(hw[3]) : "memory");
        asm volatile("st.shared.v4.b32 [%0], {%1,%2,%3,%4};"
            :: "r"(sb + SM_H(0) + off1), "r"(hw[4]), "r"(hw[5]), "r"(hw[6]), "r"(hw[7]) : "memory");
        asm volatile("st.shared.v4.b32 [%0], {%1,%2,%3,%4};"
            :: "r"(sb + SM_H(0) + 18432 + off0), "r"(lw[0]), "r"(lw[1]), "r"(lw[2]), "r"(lw[3]) : "memory");
        asm volatile("st.shared.v4.b32 [%0], {%1,%2,%3,%4};"
            :: "r"(sb + SM_H(0) + 18432 + off1), "r"(lw[4]), "r"(lw[5]), "r"(lw[6]), "r"(lw[7]) : "memory");
    }
    cpasync_wait0();

    // ---- main pipelined loop
    int buf = 0;
    for (int ch = 0; ch < 8; ch++) {
        __syncthreads();   // H(ch), B(ch) visible to all
        const int nb = buf ^ 1;
        if (ch < 7) {
            // B(ch+1) via cp.async into other buffer
            const char* srcB = (const char*)(Bimg + (size_t)(ch + 1) * (BROWS * 64));
            u32 dstB = sb + SM_B(nb);
            for (int e = tid; e < 1088; e += 256)
                cpasync16(dstB + e * 16, srcB + e * 16);
            cpasync_commit();
            // P(ch+1) prefetch into registers (drains behind MMA below)
            const float* ps = prow + (ch + 1) * 64;
#pragma unroll
            for (int q = 0; q < 8; q++) pf[q] = *(const float4*)(ps + 4 * q);
        }

        // ---- MMA on buffers `buf`
        const u32 hH = sb + SM_H(buf);
        const u32 hL = hH + 18432;
        const u32 bB = sb + SM_B(buf);
#pragma unroll
        for (int ks = 0; ks < 4; ks++) {
            u32 ah[2][4], al[2][4];
#pragma unroll
            for (int mt = 0; mt < 2; mt++) {
                int ra = wm * 32 + mt * 16 + (l & 15);
                u32 qa = ((u32)ra >> 3) & 3;
                u32 chk = (((u32)(l >> 4) + 2u * ks) ^ qa) << 4;
                ldm_x4(ah[mt], hH + (u32)(ra * 144) + chk);
                ldm_x4(al[mt], hL + (u32)(ra * 144) + chk);
            }
#pragma unroll
            for (int p = 0; p < 4; p++) {
                int rb = wn * 72 + p * 16 + (l & 7) + ((l >> 4) & 1) * 8;
                u32 chunkf = 2u * ks + ((u32)(l >> 3) & 1u);
                u32 bb[4];
                ldm_x4(bb, bB + (u32)(rb << 7) + ((chunkf ^ ((u32)rb & 7u)) << 4));
#pragma unroll
                for (int mt = 0; mt < 2; mt++)
#pragma unroll
                    for (int t = 0; t < 2; t++) {
                        float* d = acc[mt][p * 2 + t];
                        mma_f16(d, ah[mt], &bb[2 * t]);
                        mma_f16(d, al[mt], &bb[2 * t]);
                    }
            }
            {   // n-tile 8: wn=0 real (cols 64-71); wn=1 discarded (reads wn=0 rows)
                int rb2 = 64 + (l & 7);
                u32 chunkf = 2u * ks + ((u32)(l >> 3) & 1u);
                u32 s2[2];
                ldm_x2(s2, bB + (u32)(rb2 << 7) + ((chunkf ^ ((u32)rb2 & 7u)) << 4));
#pragma unroll
                for (int mt = 0; mt < 2; mt++) {
                    float* d = acc[mt][8];
                    mma_f16(d, ah[mt], s2);
                    mma_f16(d, al[mt], s2);
                }
            }
        }

        // ---- produce H(ch+1) into other buffer (uses prefetched pf)
        if (ch < 7) {
#pragma unroll
            for (int kb = 0; kb < 2; kb++) {
                float x[16];
#pragma unroll
                for (int q = 0; q < 4; q++) {
                    float4 p4 = pf[kb * 4 + q];
                    const float* ap = a_sm + (ch + 1) * 64 + half * 32 + kb * 16 + 4 * q;
                    x[4*q+0] = fmaxf(p4.x + ap[0], 0.f);
                    x[4*q+1] = fmaxf(p4.y + ap[1], 0.f);
                    x[4*q+2] = fmaxf(p4.z + ap[2], 0.f);
                    x[4*q+3] = fmaxf(p4.w + ap[3], 0.f);
                }
                u32 hw[8], lw[8];
#pragma unroll
                for (int i = 0; i < 8; i++) {
                    __half2 hh = __floats2half2_rn(x[2*i], x[2*i+1]);
                    float2 hf = __half22float2(hh);
                    __half2 hl = __floats2half2_rn(x[2*i] - hf.x, x[2*i+1] - hf.y);
                    hw[i] = h2u(hh); lw[i] = h2u(hl);
                }
                const u32 c0 = (u32)(half * 4 + kb * 2);
                const u32 off0 = hbase_off + ((c0 ^ qr) << 4);
                const u32 off1 = hbase_off + (((c0 + 1u) ^ qr) << 4);
                asm volatile("st.shared.v4.b32 [%0], {%1,%2,%3,%4};"
                    :: "r"(sb + SM_H(nb) + off0), "r"(hw[0]), "r"(hw[1]), "r"(hw[2]), "r"(hw[3]) : "memory");
                asm volatile("st.shared.v4.b32 [%0], {%1,%2,%3,%4};"
                    :: "r"(sb + SM_H(nb) + off1), "r"(hw[4]), "r"(hw[5]), "r"(hw[6]), "r"(hw[7]) : "memory");
                asm volatile("st.shared.v4.b32 [%0], {%1,%2,%3,%4};"
                    :: "r"(sb + SM_H(nb) + 18432 + off0), "r"(lw[0]), "r"(lw[1]), "r"(lw[2]), "r"(lw[3]) : "memory");
                asm volatile("st.shared.v4.b32 [%0], {%1,%2,%3,%4};"
                    :: "r"(sb + SM_H(nb) + 18432 + off1), "r"(lw[4]), "r"(lw[5]), "r"(lw[6]), "r"(lw[7]) : "memory");
            }
            cpasync_wait0();
        }
        buf = nb;
    }

    // --- epilogue: bias + coalesced store pred[b][col][i]
    const int g = l >> 2, tg = l & 3;
#pragma unroll
    for (int mt = 0; mt < 2; mt++) {
        const int i0 = ibase + wm * 32 + mt * 16 + g;
        const int i1 = i0 + 8;
        const bool ok0 = i0 < cntb, ok1 = i1 < cntb;
#pragma unroll
        for (int nt = 0; nt < 9; nt++) {
            const int cbase = wn * 72 + nt * 8 + tg * 2;
#pragma unroll
            for (int q = 0; q < 2; q++) {
                const int col = cbase + q;
                if (col >= CC) continue;
                const float bias = __ldg(&b2[col]);
                if (ok0) pred[((size_t)b * NC + col) * VV + i0] = acc[mt][nt][q] + bias;
                if (ok1) pred[((size_t)b * NC + col) * VV + i1] = acc[mt][nt][2 + q] + bias;
            }
        }
    }
}

// ---------------------------------------------------------------------------
// Scatter: sem[b,c,v] = inv[v]>=0 ? pred[b,c,inv[v]] : 0.
// ---------------------------------------------------------------------------
__global__ void __launch_bounds__(512)
k_scatter(const float* __restrict__ pred, const int* __restrict__ inv,
          float* __restrict__ sem)
{
    const int b = blockIdx.z, c = blockIdx.y;
    const int v = blockIdx.x * 512 + threadIdx.x;
    if (v >= VV) return;
    const int iv = inv[b * VV + v];
    float val = 0.f;
    if (iv >= 0) val = pred[((size_t)b * NC + c) * VV + iv];
    sem[((size_t)b * CC + c) * VV + v] = val;
}

// ---------------------------------------------------------------------------
extern "C" void kernel_launch(void* const* d_in, const int* in_sizes, int n_in,
                              void* d_out, int out_size)
{
    const float* features  = (const float*)d_in[0];
    const float* W_contact = (const float*)d_in[3];
    const float* b_contact = (const float*)d_in[4];
    const float* Wv        = (const float*)d_in[7];
    const float* Wo        = (const float*)d_in[8];
    const float* W_cls     = (const float*)d_in[9];
    const float* b_cls     = (const float*)d_in[10];
    const float* pos_emb   = (const float*)d_in[11];
    const float* W_ft1     = (const float*)d_in[12];
    const float* b_ft1     = (const float*)d_in[13];
    const float* W_ft2     = (const float*)d_in[14];
    const float* b_ft2     = (const float*)d_in[15];

    float* out  = (float*)d_out;
    float* cont = out;                  // [16, 6890]
    float* sem  = out + BB * VV;        // [16, 133, 6890]

    float *part, *tmp, *att, *a, *Pbuf, *pred;
    int *idx, *inv, *cnt;
    __half* Bimg;
    cudaGetSymbolAddress((void**)&part, g_part);
    cudaGetSymbolAddress((void**)&tmp,  g_tmp);
    cudaGetSymbolAddress((void**)&att,  g_att);
    cudaGetSymbolAddress((void**)&a,    g_a);
    cudaGetSymbolAddress((void**)&Pbuf, g_P);
    cudaGetSymbolAddress((void**)&pred, g_pred);
    cudaGetSymbolAddress((void**)&idx,  g_idx);
    cudaGetSymbolAddress((void**)&inv,  g_inv);
    cudaGetSymbolAddress((void**)&cnt,  g_cnt);
    cudaGetSymbolAddress((void**)&Bimg, g_Bimg);

    cudaFuncSetAttribute(k_sem_mma, cudaFuncAttributeMaxDynamicSharedMemorySize, SM_TOT);

    // independent prep
    k_prepW<<<8, 256>>>(W_ft2, Bimg);
    dim3 gP((VV + 127) / 128, HID / 64);
    k_P<<<gP, 256>>>(pos_emb, W_ft1, Pbuf);

    // att chain, 4-way K-split partials
    k_skinny<<<dim3(32, 4), 512>>>(features, W_contact, b_contact, part, DF, DD, 1);
    k_skinny<<<dim3(32, 4), 512>>>(part, Wv, nullptr, tmp, DD, DD, 4);
    k_skinny<<<dim3(32, 4), 512>>>(tmp,  Wo, nullptr, att, DD, DD, 4);

    // cont + a (consume 4 partials)
    k_cont2<<<(VV + 31) / 32, 256>>>(att, W_cls, b_cls, cont);
    k_skinny<<<dim3(16, 4), 512>>>(att, W_ft1, b_ft1, a, DD, HID, 4);

    // compaction
    k_compact<<<BB, 1024>>>(cont, idx, inv, cnt);

    // pipelined compacted main GEMM
    dim3 gS((VV + 127) / 128, BB);
    k_sem_mma<<<gS, 256, SM_TOT>>>(a, Pbuf, Bimg, b_ft2, idx, cnt, pred);

    // expand to sem
    dim3 gX((VV + 511) / 512, CC, BB);
    k_scatter<<<gX, 512>>>(pred, inv, sem);
}

// round 9
// speedup vs baseline: 6.5077x; 1.0439x over previous
#include <cuda_runtime.h>
#include <cuda_fp16.h>
#include <cuda_bf16.h>
#include <math.h>

// DECO decomposed (len-1 softmax == 1 → Wq/Wk/W_scene dead):
//   att  = (feat @ W_contact + b_c) @ Wv @ Wo            [16,1024]
//   cont = sigmoid(att @ W_cls + b_cls)                  [16,6890]
//   a    = att @ W_ft1[:1024] + b_ft1                    [16,512]
//   P    = pos_emb @ W_ft1[1024:]     — NOW on HMMA bf16 3-term
//   sem[b,c,v] = mask * (relu(a[b]+P[v]) @ W_ft2 + b2)[c]
// Main GEMM: fp16 mma.sync 2-term H split, mask-compacted rows, fused
// scattered epilogue (sem pre-zeroed); pipelined H/B staging.

#define BB   16
#define DF   1536
#define DD   1024
#define VV   6890
#define PDIM 256
#define HID  512
#define CC   133
#define NC   144
#define BROWS 136

typedef unsigned long long u64;
typedef unsigned int u32;

__device__ float g_part[4 * BB * DD];
__device__ float g_tmp [4 * BB * DD];
__device__ float g_att [4 * BB * DD];
__device__ float g_a   [4 * BB * HID];
__device__ float g_P   [VV * HID];
__device__ int   g_idx [BB * VV];
__device__ int   g_cnt [BB];
__device__ __align__(16) __half g_Bimg[8 * BROWS * 64];
// W_ft1[1024:] bf16 hi/lo images: [plane2][chunk4][h512][64 halves], SW128 xor
__device__ __align__(16) __nv_bfloat16 g_B1img[2 * 4 * 512 * 64];

__device__ __forceinline__ u64 pk2(float lo, float hi) {
    u64 r; asm("mov.b64 %0, {%1, %2};" : "=l"(r) : "f"(lo), "f"(hi)); return r;
}
__device__ __forceinline__ void upk2(u64 v, float& lo, float& hi) {
    asm("mov.b64 {%0, %1}, %2;" : "=f"(lo), "=f"(hi) : "l"(v));
}
__device__ __forceinline__ u64 ffma2(u64 a, u64 b, u64 c) {
    u64 d; asm("fma.rn.f32x2 %0, %1, %2, %3;" : "=l"(d) : "l"(a), "l"(b), "l"(c));
    return d;
}
__device__ __forceinline__ u32 smem_u32(const void* p) {
    u32 a; asm("{ .reg .u64 t; cvta.to.shared.u64 t, %1; cvt.u32.u64 %0, t; }"
               : "=r"(a) : "l"(p));
    return a;
}
__device__ __forceinline__ void ldm_x4(u32* r, u32 addr) {
    asm volatile("ldmatrix.sync.aligned.m8n8.x4.shared.b16 {%0,%1,%2,%3}, [%4];"
        : "=r"(r[0]), "=r"(r[1]), "=r"(r[2]), "=r"(r[3]) : "r"(addr));
}
__device__ __forceinline__ void ldm_x2(u32* r, u32 addr) {
    asm volatile("ldmatrix.sync.aligned.m8n8.x2.shared.b16 {%0,%1}, [%2];"
        : "=r"(r[0]), "=r"(r[1]) : "r"(addr));
}
__device__ __forceinline__ void mma_f16(float* d, const u32* a, const u32* b) {
    asm volatile("mma.sync.aligned.m16n8k16.row.col.f32.f16.f16.f32 "
        "{%0,%1,%2,%3}, {%4,%5,%6,%7}, {%8,%9}, {%0,%1,%2,%3};"
        : "+f"(d[0]), "+f"(d[1]), "+f"(d[2]), "+f"(d[3])
        : "r"(a[0]), "r"(a[1]), "r"(a[2]), "r"(a[3]), "r"(b[0]), "r"(b[1]));
}
__device__ __forceinline__ void mma_bf16(float* d, const u32* a, const u32* b) {
    asm volatile("mma.sync.aligned.m16n8k16.row.col.f32.bf16.bf16.f32 "
        "{%0,%1,%2,%3}, {%4,%5,%6,%7}, {%8,%9}, {%0,%1,%2,%3};"
        : "+f"(d[0]), "+f"(d[1]), "+f"(d[2]), "+f"(d[3])
        : "r"(a[0]), "r"(a[1]), "r"(a[2]), "r"(a[3]), "r"(b[0]), "r"(b[1]));
}
__device__ __forceinline__ u32 h2u(__half2 h) {
    u32 r; asm("mov.b32 %0, %1;" : "=r"(r) : "r"(*(u32*)&h)); return r;
}
__device__ __forceinline__ void cpasync16(u32 dst, const void* src) {
    asm volatile("cp.async.cg.shared.global [%0], [%1], 16;"
                 :: "r"(dst), "l"(src) : "memory");
}
__device__ __forceinline__ void cpasync_commit() {
    asm volatile("cp.async.commit_group;" ::: "memory");
}
__device__ __forceinline__ void cpasync_wait0() {
    asm volatile("cp.async.wait_group 0;" ::: "memory");
}

// k_sem smem layout (bytes)
#define SM_AS     0
#define SM_H(bf)  (2048 + (bf) * 36864)
#define SM_B(bf)  (75776 + (bf) * 17408)
#define SM_TOT    110592
// k_P_mma smem layout (bytes)
#define SMP_HH 0
#define SMP_HL 16384
#define SMP_BH 32768
#define SMP_BL 49152
#define SMP_TOT 65536

// ---------------------------------------------------------------------------
// Zero the sem region of the output.
// ---------------------------------------------------------------------------
__global__ void __launch_bounds__(256)
k_zero(float4* __restrict__ p, int n4)
{
    for (int i = blockIdx.x * 256 + threadIdx.x; i < n4; i += gridDim.x * 256)
        p[i] = make_float4(0.f, 0.f, 0.f, 0.f);
}

// ---------------------------------------------------------------------------
// Split-K skinny GEMM: out[gy][16][N] partial = in(sum nsum copies) @ W
// ---------------------------------------------------------------------------
__global__ void __launch_bounds__(512)
k_skinny(const float* __restrict__ in, const float* __restrict__ W,
         const float* __restrict__ bias, float* __restrict__ out,
         int K, int N, int nsum)
{
    __shared__ float in_s[128 * 18];
    __shared__ float red[16 * 512];

    const int tid  = threadIdx.x;
    const int col  = tid & 31;
    const int slc  = tid >> 5;
    const int colg = blockIdx.x * 32 + col;
    const int colc = colg < N ? colg : N - 1;
    const int kspan = K / gridDim.y;
    const int kbase = blockIdx.y * kspan;

    u64 acc2[8];
#pragma unroll
    for (int m = 0; m < 8; m++) acc2[m] = 0ull;

    for (int k0 = kbase; k0 < kbase + kspan; k0 += 128) {
        __syncthreads();
#pragma unroll
        for (int i = 0; i < 4; i++) {
            int e = tid + 512 * i;
            int b = e >> 7, k = e & 127;
            float s = 0.f;
            for (int sc = 0; sc < nsum; sc++)
                s += in[(size_t)sc * BB * K + b * K + k0 + k];
            in_s[k * 18 + b] = s;
        }
        __syncthreads();
#pragma unroll
        for (int kk = 0; kk < 8; kk++) {
            int k = slc * 8 + kk;
            float w = W[(size_t)(k0 + k) * N + colc];
            u64 w2 = pk2(w, w);
            const u64* ip = (const u64*)&in_s[k * 18];
#pragma unroll
            for (int m = 0; m < 8; m++)
                acc2[m] = ffma2(ip[m], w2, acc2[m]);
        }
    }
    float* rp = &red[slc * 512 + col * 16];
#pragma unroll
    for (int m = 0; m < 8; m++) {
        float lo, hi; upk2(acc2[m], lo, hi);
        rp[2 * m] = lo; rp[2 * m + 1] = hi;
    }
    __syncthreads();
    {
        int c = tid >> 4, b = tid & 15;
        float s = 0.f;
#pragma unroll
        for (int sl = 0; sl < 16; sl++) s += red[sl * 512 + c * 16 + b];
        int cg = blockIdx.x * 32 + c;
        if (cg < N) {
            float bb = (bias && blockIdx.y == 0) ? bias[cg] : 0.f;
            out[(size_t)blockIdx.y * BB * N + b * N + cg] = s + bb;
        }
    }
}

// ---------------------------------------------------------------------------
// cont = sigmoid(sum4(att) @ W_cls + b_cls); float2 col pairs.
// ---------------------------------------------------------------------------
__global__ void __launch_bounds__(256)
k_cont2(const float* __restrict__ att, const float* __restrict__ Wc,
        const float* __restrict__ bc, float* __restrict__ out)
{
    __shared__ float in_s[128 * 18];
    __shared__ float red[16 * 32 * 16];

    const int tid = threadIdx.x;
    const int cp  = tid & 15;
    const int slc = tid >> 4;
    const int col0 = blockIdx.x * 32 + 2 * cp;
    const int colc = col0 <= VV - 2 ? col0 : VV - 2;

    u64 acc[2][8];
#pragma unroll
    for (int j = 0; j < 2; j++)
#pragma unroll
        for (int m = 0; m < 8; m++) acc[j][m] = 0ull;

    for (int k0 = 0; k0 < DD; k0 += 128) {
        __syncthreads();
#pragma unroll
        for (int i = 0; i < 8; i++) {
            int e = tid + 256 * i;
            int b = e >> 7, k = e & 127;
            float s = 0.f;
#pragma unroll
            for (int sc = 0; sc < 4; sc++)
                s += att[(size_t)sc * BB * DD + b * DD + k0 + k];
            in_s[k * 18 + b] = s;
        }
        __syncthreads();
#pragma unroll
        for (int kk = 0; kk < 8; kk++) {
            int k = slc * 8 + kk;
            float2 w = *(const float2*)&Wc[(size_t)(k0 + k) * VV + colc];
            u64 w0 = pk2(w.x, w.x), w1 = pk2(w.y, w.y);
            const u64* ip = (const u64*)&in_s[k * 18];
#pragma unroll
            for (int m = 0; m < 8; m++) {
                acc[0][m] = ffma2(ip[m], w0, acc[0][m]);
                acc[1][m] = ffma2(ip[m], w1, acc[1][m]);
            }
        }
    }
#pragma unroll
    for (int j = 0; j < 2; j++) {
        float* rp = &red[slc * 512 + (2 * cp + j) * 16];
#pragma unroll
        for (int m = 0; m < 8; m++) {
            float lo, hi; upk2(acc[j][m], lo, hi);
            rp[2 * m] = lo; rp[2 * m + 1] = hi;
        }
    }
    __syncthreads();
    for (int o = tid; o < 512; o += 256) {
        int c = o >> 4, b = o & 15;
        float s = 0.f;
#pragma unroll
        for (int sl = 0; sl < 16; sl++) s += red[sl * 512 + c * 16 + b];
        int cg = blockIdx.x * 32 + c;
        if (cg < VV)
            out[b * VV + cg] = 1.f / (1.f + expf(-(s + bc[cg])));
    }
}

// ---------------------------------------------------------------------------
// Build W_ft1[1024:] bf16 hi/lo chunk images. blk = plane*4 + chunk.
// Layout [h 512][64 halves], SW128 xor (chunk16B ^ (h&7)).
// ---------------------------------------------------------------------------
__global__ void k_prepW1(const float* __restrict__ W1,
                         __nv_bfloat16* __restrict__ B1)
{
    const int blk = blockIdx.x;
    const int plane = blk >> 2, ch = blk & 3;
    for (int e = threadIdx.x; e < 512 * 64; e += 256) {
        int n = e >> 6, k = e & 63;
        float w = W1[(size_t)(DD + ch * 64 + k) * HID + n];
        __nv_bfloat16 h = __float2bfloat16(w);
        __nv_bfloat16 val = plane ? __float2bfloat16(w - __bfloat162float(h)) : h;
        int off = (n << 6) + (((k >> 3) ^ (n & 7)) << 3) + (k & 7);
        B1[(size_t)blk * (512 * 64) + off] = val;
    }
}

// ---------------------------------------------------------------------------
// P = pos_emb @ W_ft1[1024:] via bf16 HMMA, 3-term split (Ah*Bh+Ah*Bl+Al*Bh).
// CTA = 128 v-rows x 128 h-cols; grid (54, 4). 256 thr = 4m x 2n warps.
// K=256: 4 chunks of 64. H smem stride 128B, SW128 xor (chunk ^ row&7).
// ---------------------------------------------------------------------------
__global__ void __launch_bounds__(256, 1)
k_P_mma(const float* __restrict__ pos, const __nv_bfloat16* __restrict__ B1,
        float* __restrict__ Pout)
{
    extern __shared__ char smem[];
    const u32 sb = smem_u32(smem);
    const int tid = threadIdx.x;
    const int wid = tid >> 5;
    const int l   = tid & 31;
    const int wm = wid & 3;
    const int wn = wid >> 2;
    const int vbase = blockIdx.x * 128;
    const int hbase = blockIdx.y * 128;

    const int r = tid & 127;
    const int half = tid >> 7;
    const int v = vbase + r;
    const int vc = v < VV ? v : VV - 1;
    const float* __restrict__ prow = pos + (size_t)vc * PDIM + half * 32;

    float acc[2][8][4];
#pragma unroll
    for (int i = 0; i < 2; i++)
#pragma unroll
        for (int j = 0; j < 8; j++)
#pragma unroll
            for (int q = 0; q < 4; q++) acc[i][j][q] = 0.f;

    for (int ch = 0; ch < 4; ch++) {
        // --- producer: pos -> bf16 hi/lo, swizzled STS.128
        float4 pf[8];
#pragma unroll
        for (int q = 0; q < 8; q++)
            pf[q] = *(const float4*)(prow + ch * 64 + 4 * q);
#pragma unroll
        for (int kb = 0; kb < 2; kb++) {
            float x[16];
#pragma unroll
            for (int q = 0; q < 4; q++) {
                float4 p4 = pf[kb * 4 + q];
                x[4*q+0] = p4.x; x[4*q+1] = p4.y; x[4*q+2] = p4.z; x[4*q+3] = p4.w;
            }
            u32 hw[8], lw[8];
#pragma unroll
            for (int i = 0; i < 8; i++) {
                __nv_bfloat16 h0 = __float2bfloat16(x[2*i]);
                __nv_bfloat16 h1 = __float2bfloat16(x[2*i+1]);
                __nv_bfloat16 l0 = __float2bfloat16(x[2*i]   - __bfloat162float(h0));
                __nv_bfloat16 l1 = __float2bfloat16(x[2*i+1] - __bfloat162float(h1));
                hw[i] = (u32)__bfloat16_as_ushort(h0) | ((u32)__bfloat16_as_ushort(h1) << 16);
                lw[i] = (u32)__bfloat16_as_ushort(l0) | ((u32)__bfloat16_as_ushort(l1) << 16);
            }
            const u32 c0 = (u32)(half * 4 + kb * 2);
            const u32 q7 = (u32)r & 7u;
            const u32 off0 = (u32)(r << 7) + ((c0 ^ q7) << 4);
            const u32 off1 = (u32)(r << 7) + (((c0 + 1u) ^ q7) << 4);
            asm volatile("st.shared.v4.b32 [%0], {%1,%2,%3,%4};"
                :: "r"(sb + SMP_HH + off0), "r"(hw[0]), "r"(hw[1]), "r"(hw[2]), "r"(hw[3]) : "memory");
            asm volatile("st.shared.v4.b32 [%0], {%1,%2,%3,%4};"
                :: "r"(sb + SMP_HH + off1), "r"(hw[4]), "r"(hw[5]), "r"(hw[6]), "r"(hw[7]) : "memory");
            asm volatile("st.shared.v4.b32 [%0], {%1,%2,%3,%4};"
                :: "r"(sb + SMP_HL + off0), "r"(lw[0]), "r"(lw[1]), "r"(lw[2]), "r"(lw[3]) : "memory");
            asm volatile("st.shared.v4.b32 [%0], {%1,%2,%3,%4};"
                :: "r"(sb + SMP_HL + off1), "r"(lw[4]), "r"(lw[5]), "r"(lw[6]), "r"(lw[7]) : "memory");
        }
        // --- B slice copy (pre-swizzled): hi/lo 1024 uint4 each
        {
            const uint4* sH = (const uint4*)(B1 + (size_t)ch * 32768 + (size_t)hbase * 64);
            const uint4* sL = (const uint4*)(B1 + (size_t)(4 + ch) * 32768 + (size_t)hbase * 64);
            uint4* dH = (uint4*)(smem + SMP_BH);
            uint4* dL = (uint4*)(smem + SMP_BL);
#pragma unroll
            for (int i = 0; i < 4; i++) {
                int e = tid + 256 * i;
                dH[e] = sH[e]; dL[e] = sL[e];
            }
        }
        __syncthreads();
        // --- MMA: 4 k16 steps x (2mt x 8nt x 3 terms)
#pragma unroll
        for (int ks = 0; ks < 4; ks++) {
            u32 ah[2][4], al[2][4];
#pragma unroll
            for (int mt = 0; mt < 2; mt++) {
                int ra = wm * 32 + mt * 16 + (l & 15);
                u32 c = (u32)(l >> 4) + 2u * ks;
                u32 sw = ((c ^ ((u32)ra & 7u)) << 4);
                ldm_x4(ah[mt], sb + SMP_HH + (u32)(ra << 7) + sw);
                ldm_x4(al[mt], sb + SMP_HL + (u32)(ra << 7) + sw);
            }
#pragma unroll
            for (int p = 0; p < 4; p++) {
                int rb = wn * 64 + p * 16 + (l & 7) + ((l >> 4) & 1) * 8;
                u32 cf = 2u * ks + ((u32)(l >> 3) & 1u);
                u32 swb = ((cf ^ ((u32)rb & 7u)) << 4);
                u32 bh[4], bl[4];
                ldm_x4(bh, sb + SMP_BH + (u32)(rb << 7) + swb);
                ldm_x4(bl, sb + SMP_BL + (u32)(rb << 7) + swb);
#pragma unroll
                for (int mt = 0; mt < 2; mt++)
#pragma unroll
                    for (int t = 0; t < 2; t++) {
                        float* d = acc[mt][p * 2 + t];
                        mma_bf16(d, ah[mt], &bh[2 * t]);
                        mma_bf16(d, ah[mt], &bl[2 * t]);
                        mma_bf16(d, al[mt], &bh[2 * t]);
                    }
            }
        }
        __syncthreads();
    }

    // --- epilogue: store P
    const int g = l >> 2, tg = l & 3;
#pragma unroll
    for (int mt = 0; mt < 2; mt++) {
        const int i0 = vbase + wm * 32 + mt * 16 + g;
        const int i1 = i0 + 8;
#pragma unroll
        for (int nt = 0; nt < 8; nt++) {
            const int col = hbase + wn * 64 + nt * 8 + tg * 2;
            if (i0 < VV)
                *(float2*)&Pout[(size_t)i0 * HID + col]
                    = make_float2(acc[mt][nt][0], acc[mt][nt][1]);
            if (i1 < VV)
                *(float2*)&Pout[(size_t)i1 * HID + col]
                    = make_float2(acc[mt][nt][2], acc[mt][nt][3]);
        }
    }
}

// ---------------------------------------------------------------------------
// Build 8 fp16 W_ft2 images, 136 rows x 64 halves, SW128 xor chunk^=(n&7).
// ---------------------------------------------------------------------------
__global__ void k_prepW(const float* __restrict__ W2,
                        __half* __restrict__ Bimg)
{
    const int img = blockIdx.x;
    for (int e = threadIdx.x; e < BROWS * 64; e += 256) {
        int n = e >> 6, k = e & 63;
        float w = (n < CC) ? W2[(size_t)(img * 64 + k) * CC + n] : 0.f;
        int off = (n << 6) + (((k >> 3) ^ (n & 7)) << 3) + (k & 7);
        Bimg[(size_t)img * (BROWS * 64) + off] = __float2half_rn(w);
    }
}

// ---------------------------------------------------------------------------
// Order-preserving mask compaction (idx + cnt only).
// ---------------------------------------------------------------------------
__global__ void __launch_bounds__(1024)
k_compact(const float* __restrict__ cont, int* __restrict__ idx,
          int* __restrict__ cnt)
{
    const int b = blockIdx.x;
    const int tid = threadIdx.x;
    const int lane = tid & 31, wid = tid >> 5;
    __shared__ int wexc[32];
    __shared__ int s_base, s_tot;
    if (tid == 0) s_base = 0;
    __syncthreads();
    for (int v0 = 0; v0 < VV; v0 += 1024) {
        int v = v0 + tid;
        int m = (v < VV) && (cont[b * VV + v] > 0.5f);
        unsigned bal = __ballot_sync(0xffffffffu, m);
        int wsum = __popc(bal);
        int pw = __popc(bal & ((1u << lane) - 1u));
        if (lane == 0) wexc[wid] = wsum;
        __syncthreads();
        if (tid < 32) {
            int sv = wexc[tid];
            int e = sv;
#pragma unroll
            for (int d = 1; d < 32; d <<= 1) {
                int t = __shfl_up_sync(0xffffffffu, e, d);
                if (tid >= d) e += t;
            }
            wexc[tid] = e - sv;
            if (tid == 31) s_tot = e;
        }
        __syncthreads();
        int pos = s_base + wexc[wid] + pw;
        if (v < VV && m) idx[b * VV + pos] = v;
        __syncthreads();
        if (tid == 0) s_base += s_tot;
        __syncthreads();
    }
    if (tid == 0) cnt[b] = s_base;
}

// ---------------------------------------------------------------------------
// Pipelined main GEMM (compacted rows), fp16 mma.sync 2-term; fused
// scattered epilogue writes sem[b, c, idx[i]] (sem pre-zeroed).
// ---------------------------------------------------------------------------
__global__ void __launch_bounds__(256, 2)
k_sem_mma(const float* __restrict__ A4,
          const float* __restrict__ P,
          const __half* __restrict__ Bimg,
          const float* __restrict__ b2,
          const int* __restrict__ idx,
          const int* __restrict__ cnt,
          float* __restrict__ sem)
{
    const int b = blockIdx.y;
    const int cntb = cnt[b];
    const int ibase = blockIdx.x * 128;
    if (ibase >= cntb) return;

    extern __shared__ char smem[];
    const u32 sb = smem_u32(smem);
    const int tid = threadIdx.x;
    const int wid = tid >> 5;
    const int l   = tid & 31;
    const int wm = wid & 3;
    const int wn = wid >> 2;

    float* a_sm = (float*)(smem + SM_AS);
    for (int i = tid; i < HID; i += 256) {
        float s = 0.f;
#pragma unroll
        for (int sc = 0; sc < 4; sc++)
            s += A4[(size_t)sc * BB * HID + b * HID + i];
        a_sm[i] = s;
    }

    const int r = tid & 127;
    const int half = tid >> 7;
    const int ig = ibase + r;
    const int vrow = idx[b * VV + (ig < cntb ? ig : cntb - 1)];
    const float* __restrict__ prow = P + (size_t)vrow * HID + half * 32;
    const u32 qr = ((u32)r >> 3) & 3;
    const u32 hbase_off = (u32)(r * 144);

    float acc[2][9][4];
#pragma unroll
    for (int i = 0; i < 2; i++)
#pragma unroll
        for (int j = 0; j < 9; j++)
#pragma unroll
            for (int q = 0; q < 4; q++) acc[i][j][q] = 0.f;

    float4 pf[8];

    // ---- prologue
    {
        const char* srcB = (const char*)(Bimg);
        u32 dstB = sb + SM_B(0);
        for (int e = tid; e < 1088; e += 256)
            cpasync16(dstB + e * 16, srcB + e * 16);
        cpasync_commit();
    }
#pragma unroll
    for (int q = 0; q < 8; q++) pf[q] = *(const float4*)(prow + 4 * q);
    __syncthreads();
#pragma unroll
    for (int kb = 0; kb < 2; kb++) {
        float x[16];
#pragma unroll
        for (int q = 0; q < 4; q++) {
            float4 p4 = pf[kb * 4 + q];
            const float* ap = a_sm + half * 32 + kb * 16 + 4 * q;
            x[4*q+0] = fmaxf(p4.x + ap[0], 0.f);
            x[4*q+1] = fmaxf(p4.y + ap[1], 0.f);
            x[4*q+2] = fmaxf(p4.z + ap[2], 0.f);
            x[4*q+3] = fmaxf(p4.w + ap[3], 0.f);
        }
        u32 hw[8], lw[8];
#pragma unroll
        for (int i = 0; i < 8; i++) {
            __half2 hh = __floats2half2_rn(x[2*i], x[2*i+1]);
            float2 hf = __half22float2(hh);
            __half2 hl = __floats2half2_rn(x[2*i] - hf.x, x[2*i+1] - hf.y);
            hw[i] = h2u(hh); lw[i] = h2u(hl);
        }
        const u32 c0 = (u32)(half * 4 + kb * 2);
        const u32 off0 = hbase_off + ((c0 ^ qr) << 4);
        const u32 off1 = hbase_off + (((c0 + 1u) ^ qr) << 4);
        asm volatile("st.shared.v4.b32 [%0], {%1,%2,%3,%4};"
            :: "r"(sb + SM_H(0) + off0), "r"(hw[0]), "r"(hw[1]), "r"(hw[2]), "r"(hw[3]) : "memory");
        asm volatile("st.shared.v4.b32 [%0], {%1,%2,%3,%4};"
            :: "r"(sb + SM_H(0) + off1), "r"(hw[4]), "r"(hw[5]), "r"(hw[6]), "r"(hw[7]) : "memory");
        asm volatile("st.shared.v4.b32 [%0], {%1,%2,%3,%4};"
            :: "r"(sb + SM_H(0) + 18432 + off0), "r"(lw[0]), "r"(lw[1]), "r"(lw[2]), "r"(lw[3]) : "memory");
        asm volatile("st.shared.v4.b32 [%0], {%1,%2,%3,%4};"
            :: "r"(sb + SM_H(0) + 18432 + off1), "r"(lw[4]), "r"(lw[5]), "r"(lw[6]), "r"(lw[7]) : "memory");
    }
    cpasync_wait0();

    // ---- main pipelined loop
    int buf = 0;
    for (int ch = 0; ch < 8; ch++) {
        __syncthreads();
        const int nb = buf ^ 1;
        if (ch < 7) {
            const char* srcB = (const char*)(Bimg + (size_t)(ch + 1) * (BROWS * 64));
            u32 dstB = sb + SM_B(nb);
            for (int e = tid; e < 1088; e += 256)
                cpasync16(dstB + e * 16, srcB + e * 16);
            cpasync_commit();
            const float* ps = prow + (ch + 1) * 64;
#pragma unroll
            for (int q = 0; q < 8; q++) pf[q] = *(const float4*)(ps + 4 * q);
        }

        const u32 hH = sb + SM_H(buf);
        const u32 hL = hH + 18432;
        const u32 bB = sb + SM_B(buf);
#pragma unroll
        for (int ks = 0; ks < 4; ks++) {
            u32 ah[2][4], al[2][4];
#pragma unroll
            for (int mt = 0; mt < 2; mt++) {
                int ra = wm * 32 + mt * 16 + (l & 15);
                u32 qa = ((u32)ra >> 3) & 3;
                u32 chk = (((u32)(l >> 4) + 2u * ks) ^ qa) << 4;
                ldm_x4(ah[mt], hH + (u32)(ra * 144) + chk);
                ldm_x4(al[mt], hL + (u32)(ra * 144) + chk);
            }
#pragma unroll
            for (int p = 0; p < 4; p++) {
                int rb = wn * 72 + p * 16 + (l & 7) + ((l >> 4) & 1) * 8;
                u32 chunkf = 2u * ks + ((u32)(l >> 3) & 1u);
                u32 bb[4];
                ldm_x4(bb, bB + (u32)(rb << 7) + ((chunkf ^ ((u32)rb & 7u)) << 4));
#pragma unroll
                for (int mt = 0; mt < 2; mt++)
#pragma unroll
                    for (int t = 0; t < 2; t++) {
                        float* d = acc[mt][p * 2 + t];
                        mma_f16(d, ah[mt], &bb[2 * t]);
                        mma_f16(d, al[mt], &bb[2 * t]);
                    }
            }
            {
                int rb2 = 64 + (l & 7);
                u32 chunkf = 2u * ks + ((u32)(l >> 3) & 1u);
                u32 s2[2];
                ldm_x2(s2, bB + (u32)(rb2 << 7) + ((chunkf ^ ((u32)rb2 & 7u)) << 4));
#pragma unroll
                for (int mt = 0; mt < 2; mt++) {
                    float* d = acc[mt][8];
                    mma_f16(d, ah[mt], s2);
                    mma_f16(d, al[mt], s2);
                }
            }
        }

        if (ch < 7) {
#pragma unroll
            for (int kb = 0; kb < 2; kb++) {
                float x[16];
#pragma unroll
                for (int q = 0; q < 4; q++) {
                    float4 p4 = pf[kb * 4 + q];
                    const float* ap = a_sm + (ch + 1) * 64 + half * 32 + kb * 16 + 4 * q;
                    x[4*q+0] = fmaxf(p4.x + ap[0], 0.f);
                    x[4*q+1] = fmaxf(p4.y + ap[1], 0.f);
                    x[4*q+2] = fmaxf(p4.z + ap[2], 0.f);
                    x[4*q+3] = fmaxf(p4.w + ap[3], 0.f);
                }
                u32 hw[8], lw[8];
#pragma unroll
                for (int i = 0; i < 8; i++) {
                    __half2 hh = __floats2half2_rn(x[2*i], x[2*i+1]);
                    float2 hf = __half22float2(hh);
                    __half2 hl = __floats2half2_rn(x[2*i] - hf.x, x[2*i+1] - hf.y);
                    hw[i] = h2u(hh); lw[i] = h2u(hl);
                }
                const u32 c0 = (u32)(half * 4 + kb * 2);
                const u32 off0 = hbase_off + ((c0 ^ qr) << 4);
                const u32 off1 = hbase_off + (((c0 + 1u) ^ qr) << 4);
                asm volatile("st.shared.v4.b32 [%0], {%1,%2,%3,%4};"
                    :: "r"(sb + SM_H(nb) + off0), "r"(hw[0]), "r"(hw[1]), "r"(hw[2]), "r"(hw[3]) : "memory");
                asm volatile("st.shared.v4.b32 [%0], {%1,%2,%3,%4};"
                    :: "r"(sb + SM_H(nb) + off1), "r"(hw[4]), "r"(hw[5]), "r"(hw[6]), "r"(hw[7]) : "memory");
                asm volatile("st.shared.v4.b32 [%0], {%1,%2,%3,%4};"
                    :: "r"(sb + SM_H(nb) + 18432 + off0), "r"(lw[0]), "r"(lw[1]), "r"(lw[2]), "r"(lw[3]) : "memory");
                asm volatile("st.shared.v4.b32 [%0], {%1,%2,%3,%4};"
                    :: "r"(sb + SM_H(nb) + 18432 + off1), "r"(lw[4]), "r"(lw[5]), "r"(lw[6]), "r"(lw[7]) : "memory");
            }
            cpasync_wait0();
        }
        buf = nb;
    }

    // --- fused epilogue: bias + scattered store sem[b, col, idx[i]]
    const int g = l >> 2, tg = l & 3;
#pragma unroll
    for (int mt = 0; mt < 2; mt++) {
        const int i0 = ibase + wm * 32 + mt * 16 + g;
        const int i1 = i0 + 8;
        const bool ok0 = i0 < cntb, ok1 = i1 < cntb;
        const int v0 = ok0 ? idx[b * VV + i0] : 0;
        const int v1 = ok1 ? idx[b * VV + i1] : 0;
#pragma unroll
        for (int nt = 0; nt < 9; nt++) {
            const int cbase = wn * 72 + nt * 8 + tg * 2;
#pragma unroll
            for (int q = 0; q < 2; q++) {
                const int col = cbase + q;
                if (col >= CC) continue;
                const float bias = __ldg(&b2[col]);
                if (ok0) sem[((size_t)b * CC + col) * VV + v0] = acc[mt][nt][q] + bias;
                if (ok1) sem[((size_t)b * CC + col) * VV + v1] = acc[mt][nt][2 + q] + bias;
            }
        }
    }
}

// ---------------------------------------------------------------------------
extern "C" void kernel_launch(void* const* d_in, const int* in_sizes, int n_in,
                              void* d_out, int out_size)
{
    const float* features  = (const float*)d_in[0];
    const float* W_contact = (const float*)d_in[3];
    const float* b_contact = (const float*)d_in[4];
    const float* Wv        = (const float*)d_in[7];
    const float* Wo        = (const float*)d_in[8];
    const float* W_cls     = (const float*)d_in[9];
    const float* b_cls     = (const float*)d_in[10];
    const float* pos_emb   = (const float*)d_in[11];
    const float* W_ft1     = (const float*)d_in[12];
    const float* b_ft1     = (const float*)d_in[13];
    const float* W_ft2     = (const float*)d_in[14];
    const float* b_ft2     = (const float*)d_in[15];

    float* out  = (float*)d_out;
    float* cont = out;                  // [16, 6890]
    float* sem  = out + BB * VV;        // [16, 133, 6890]

    float *part, *tmp, *att, *a, *Pbuf;
    int *idx, *cnt;
    __half* Bimg;
    __nv_bfloat16* B1img;
    cudaGetSymbolAddress((void**)&part,  g_part);
    cudaGetSymbolAddress((void**)&tmp,   g_tmp);
    cudaGetSymbolAddress((void**)&att,   g_att);
    cudaGetSymbolAddress((void**)&a,     g_a);
    cudaGetSymbolAddress((void**)&Pbuf,  g_P);
    cudaGetSymbolAddress((void**)&idx,   g_idx);
    cudaGetSymbolAddress((void**)&cnt,   g_cnt);
    cudaGetSymbolAddress((void**)&Bimg,  g_Bimg);
    cudaGetSymbolAddress((void**)&B1img, g_B1img);

    cudaFuncSetAttribute(k_sem_mma, cudaFuncAttributeMaxDynamicSharedMemorySize, SM_TOT);
    cudaFuncSetAttribute(k_P_mma,  cudaFuncAttributeMaxDynamicSharedMemorySize, SMP_TOT);

    // pre-zero sem region (scattered epilogue only writes masked-in entries)
    k_zero<<<2048, 256>>>((float4*)sem, (BB * CC * VV) / 4);

    // weight image prep (independent)
    k_prepW<<<8, 256>>>(W_ft2, Bimg);
    k_prepW1<<<8, 256>>>(W_ft1, B1img);

    // P = pos_emb @ W_ft1[1024:] on HMMA bf16 3-term
    dim3 gP((VV + 127) / 128, 4);
    k_P_mma<<<gP, 256, SMP_TOT>>>(pos_emb, B1img, Pbuf);

    // att chain, 4-way K-split partials
    k_skinny<<<dim3(32, 4), 512>>>(features, W_contact, b_contact, part, DF, DD, 1);
    k_skinny<<<dim3(32, 4), 512>>>(part, Wv, nullptr, tmp, DD, DD, 4);
    k_skinny<<<dim3(32, 4), 512>>>(tmp,  Wo, nullptr, att, DD, DD, 4);

    // cont + a (consume 4 partials)
    k_cont2<<<(VV + 31) / 32, 256>>>(att, W_cls, b_cls, cont);
    k_skinny<<<dim3(16, 4), 512>>>(att, W_ft1, b_ft1, a, DD, HID, 4);

    // compaction
    k_compact<<<BB, 1024>>>(cont, idx, cnt);

    // pipelined compacted main GEMM with fused scattered epilogue
    dim3 gS((VV + 127) / 128, BB);
    k_sem_mma<<<gS, 256, SM_TOT>>>(a, Pbuf, Bimg, b_ft2, idx, cnt, sem);
}

// round 10
// speedup vs baseline: 7.0047x; 1.0764x over previous
#include <cuda_runtime.h>
#include <cuda_fp16.h>
#include <cuda_bf16.h>
#include <math.h>

// DECO decomposed (len-1 softmax == 1 → Wq/Wk/W_scene dead):
//   att  = (feat @ W_contact + b_c) @ Wv @ Wo            [16,1024]
//   cont = sigmoid(att @ W_cls + b_cls)                  [16,6890]
//   a    = att @ W_ft1[:1024] + b_ft1                    [16,512]
//   P    = pos_emb @ W_ft1[1024:]   (HMMA bf16 3-term, N=64/CTA)
//   sem[b,c,v] = mask * (relu(a[b]+P[v]) @ W_ft2 + b2)[c]
// Main GEMM: fp16 mma.sync 2-term H split, mask-compacted rows, PERSISTENT
// CTAs (grid=296 looping over tiles), fused scattered epilogue.

#define BB   16
#define DF   1536
#define DD   1024
#define VV   6890
#define PDIM 256
#define HID  512
#define CC   133
#define NC   144
#define BROWS 136
#define NPERS 296

typedef unsigned long long u64;
typedef unsigned int u32;

__device__ float g_part[4 * BB * DD];
__device__ float g_tmp [4 * BB * DD];
__device__ float g_att [4 * BB * DD];
__device__ float g_a   [4 * BB * HID];
__device__ float g_P   [VV * HID];
__device__ int   g_idx [BB * VV];
__device__ int   g_cnt [BB];
__device__ __align__(16) __half g_Bimg[8 * BROWS * 64];
__device__ __align__(16) __nv_bfloat16 g_B1img[2 * 4 * 512 * 64];

__device__ __forceinline__ u64 pk2(float lo, float hi) {
    u64 r; asm("mov.b64 %0, {%1, %2};" : "=l"(r) : "f"(lo), "f"(hi)); return r;
}
__device__ __forceinline__ void upk2(u64 v, float& lo, float& hi) {
    asm("mov.b64 {%0, %1}, %2;" : "=f"(lo), "=f"(hi) : "l"(v));
}
__device__ __forceinline__ u64 ffma2(u64 a, u64 b, u64 c) {
    u64 d; asm("fma.rn.f32x2 %0, %1, %2, %3;" : "=l"(d) : "l"(a), "l"(b), "l"(c));
    return d;
}
__device__ __forceinline__ u32 smem_u32(const void* p) {
    u32 a; asm("{ .reg .u64 t; cvta.to.shared.u64 t, %1; cvt.u32.u64 %0, t; }"
               : "=r"(a) : "l"(p));
    return a;
}
__device__ __forceinline__ void ldm_x4(u32* r, u32 addr) {
    asm volatile("ldmatrix.sync.aligned.m8n8.x4.shared.b16 {%0,%1,%2,%3}, [%4];"
        : "=r"(r[0]), "=r"(r[1]), "=r"(r[2]), "=r"(r[3]) : "r"(addr));
}
__device__ __forceinline__ void ldm_x2(u32* r, u32 addr) {
    asm volatile("ldmatrix.sync.aligned.m8n8.x2.shared.b16 {%0,%1}, [%2];"
        : "=r"(r[0]), "=r"(r[1]) : "r"(addr));
}
__device__ __forceinline__ void mma_f16(float* d, const u32* a, const u32* b) {
    asm volatile("mma.sync.aligned.m16n8k16.row.col.f32.f16.f16.f32 "
        "{%0,%1,%2,%3}, {%4,%5,%6,%7}, {%8,%9}, {%0,%1,%2,%3};"
        : "+f"(d[0]), "+f"(d[1]), "+f"(d[2]), "+f"(d[3])
        : "r"(a[0]), "r"(a[1]), "r"(a[2]), "r"(a[3]), "r"(b[0]), "r"(b[1]));
}
__device__ __forceinline__ void mma_bf16(float* d, const u32* a, const u32* b) {
    asm volatile("mma.sync.aligned.m16n8k16.row.col.f32.bf16.bf16.f32 "
        "{%0,%1,%2,%3}, {%4,%5,%6,%7}, {%8,%9}, {%0,%1,%2,%3};"
        : "+f"(d[0]), "+f"(d[1]), "+f"(d[2]), "+f"(d[3])
        : "r"(a[0]), "r"(a[1]), "r"(a[2]), "r"(a[3]), "r"(b[0]), "r"(b[1]));
}
__device__ __forceinline__ u32 h2u(__half2 h) {
    u32 r; asm("mov.b32 %0, %1;" : "=r"(r) : "r"(*(u32*)&h)); return r;
}
__device__ __forceinline__ void cpasync16(u32 dst, const void* src) {
    asm volatile("cp.async.cg.shared.global [%0], [%1], 16;"
                 :: "r"(dst), "l"(src) : "memory");
}
__device__ __forceinline__ void cpasync_commit() {
    asm volatile("cp.async.commit_group;" ::: "memory");
}
__device__ __forceinline__ void cpasync_wait0() {
    asm volatile("cp.async.wait_group 0;" ::: "memory");
}

// k_sem smem layout (bytes)
#define SM_AS     0
#define SM_H(bf)  (2048 + (bf) * 36864)
#define SM_B(bf)  (75776 + (bf) * 17408)
#define SM_TOT    110592
// k_P_mma smem layout (bytes) — N=64 per CTA
#define SMP_HH 0
#define SMP_HL 16384
#define SMP_BH 32768
#define SMP_BL 40960
#define SMP_TOT 49152

// ---------------------------------------------------------------------------
// Fused misc: blocks [0,8) prepW (W_ft2 fp16 images), [8,16) prepW1
// (W_ft1[1024:] bf16 hi/lo images), [16,528) zero sem.
// ---------------------------------------------------------------------------
__global__ void __launch_bounds__(256)
k_misc(const float* __restrict__ W2, __half* __restrict__ Bimg,
       const float* __restrict__ W1, __nv_bfloat16* __restrict__ B1,
       float4* __restrict__ zp, int n4)
{
    const int bx = blockIdx.x;
    const int tid = threadIdx.x;
    if (bx < 8) {
        const int img = bx;
        for (int e = tid; e < BROWS * 64; e += 256) {
            int n = e >> 6, k = e & 63;
            float w = (n < CC) ? W2[(size_t)(img * 64 + k) * CC + n] : 0.f;
            int off = (n << 6) + (((k >> 3) ^ (n & 7)) << 3) + (k & 7);
            Bimg[(size_t)img * (BROWS * 64) + off] = __float2half_rn(w);
        }
    } else if (bx < 16) {
        const int blk = bx - 8;
        const int plane = blk >> 2, ch = blk & 3;
        for (int e = tid; e < 512 * 64; e += 256) {
            int n = e >> 6, k = e & 63;
            float w = W1[(size_t)(DD + ch * 64 + k) * HID + n];
            __nv_bfloat16 h = __float2bfloat16(w);
            __nv_bfloat16 val = plane ? __float2bfloat16(w - __bfloat162float(h)) : h;
            int off = (n << 6) + (((k >> 3) ^ (n & 7)) << 3) + (k & 7);
            B1[(size_t)blk * (512 * 64) + off] = val;
        }
    } else {
        const int zb = bx - 16;
        for (int i = zb * 256 + tid; i < n4; i += 512 * 256)
            zp[i] = make_float4(0.f, 0.f, 0.f, 0.f);
    }
}

// ---------------------------------------------------------------------------
// Split-K skinny GEMM: out[gy][16][N] partial = in(sum nsum copies) @ W
// ---------------------------------------------------------------------------
__global__ void __launch_bounds__(512)
k_skinny(const float* __restrict__ in, const float* __restrict__ W,
         const float* __restrict__ bias, float* __restrict__ out,
         int K, int N, int nsum)
{
    __shared__ float in_s[128 * 18];
    __shared__ float red[16 * 512];

    const int tid  = threadIdx.x;
    const int col  = tid & 31;
    const int slc  = tid >> 5;
    const int colg = blockIdx.x * 32 + col;
    const int colc = colg < N ? colg : N - 1;
    const int kspan = K / gridDim.y;
    const int kbase = blockIdx.y * kspan;

    u64 acc2[8];
#pragma unroll
    for (int m = 0; m < 8; m++) acc2[m] = 0ull;

    for (int k0 = kbase; k0 < kbase + kspan; k0 += 128) {
        __syncthreads();
#pragma unroll
        for (int i = 0; i < 4; i++) {
            int e = tid + 512 * i;
            int b = e >> 7, k = e & 127;
            float s = 0.f;
            for (int sc = 0; sc < nsum; sc++)
                s += in[(size_t)sc * BB * K + b * K + k0 + k];
            in_s[k * 18 + b] = s;
        }
        __syncthreads();
#pragma unroll
        for (int kk = 0; kk < 8; kk++) {
            int k = slc * 8 + kk;
            float w = W[(size_t)(k0 + k) * N + colc];
            u64 w2 = pk2(w, w);
            const u64* ip = (const u64*)&in_s[k * 18];
#pragma unroll
            for (int m = 0; m < 8; m++)
                acc2[m] = ffma2(ip[m], w2, acc2[m]);
        }
    }
    float* rp = &red[slc * 512 + col * 16];
#pragma unroll
    for (int m = 0; m < 8; m++) {
        float lo, hi; upk2(acc2[m], lo, hi);
        rp[2 * m] = lo; rp[2 * m + 1] = hi;
    }
    __syncthreads();
    {
        int c = tid >> 4, b = tid & 15;
        float s = 0.f;
#pragma unroll
        for (int sl = 0; sl < 16; sl++) s += red[sl * 512 + c * 16 + b];
        int cg = blockIdx.x * 32 + c;
        if (cg < N) {
            float bb = (bias && blockIdx.y == 0) ? bias[cg] : 0.f;
            out[(size_t)blockIdx.y * BB * N + b * N + cg] = s + bb;
        }
    }
}

// ---------------------------------------------------------------------------
// cont = sigmoid(sum4(att) @ W_cls + b_cls); float2 col pairs.
// ---------------------------------------------------------------------------
__global__ void __launch_bounds__(256)
k_cont2(const float* __restrict__ att, const float* __restrict__ Wc,
        const float* __restrict__ bc, float* __restrict__ out)
{
    __shared__ float in_s[128 * 18];
    __shared__ float red[16 * 32 * 16];

    const int tid = threadIdx.x;
    const int cp  = tid & 15;
    const int slc = tid >> 4;
    const int col0 = blockIdx.x * 32 + 2 * cp;
    const int colc = col0 <= VV - 2 ? col0 : VV - 2;

    u64 acc[2][8];
#pragma unroll
    for (int j = 0; j < 2; j++)
#pragma unroll
        for (int m = 0; m < 8; m++) acc[j][m] = 0ull;

    for (int k0 = 0; k0 < DD; k0 += 128) {
        __syncthreads();
#pragma unroll
        for (int i = 0; i < 8; i++) {
            int e = tid + 256 * i;
            int b = e >> 7, k = e & 127;
            float s = 0.f;
#pragma unroll
            for (int sc = 0; sc < 4; sc++)
                s += att[(size_t)sc * BB * DD + b * DD + k0 + k];
            in_s[k * 18 + b] = s;
        }
        __syncthreads();
#pragma unroll
        for (int kk = 0; kk < 8; kk++) {
            int k = slc * 8 + kk;
            float2 w = *(const float2*)&Wc[(size_t)(k0 + k) * VV + colc];
            u64 w0 = pk2(w.x, w.x), w1 = pk2(w.y, w.y);
            const u64* ip = (const u64*)&in_s[k * 18];
#pragma unroll
            for (int m = 0; m < 8; m++) {
                acc[0][m] = ffma2(ip[m], w0, acc[0][m]);
                acc[1][m] = ffma2(ip[m], w1, acc[1][m]);
            }
        }
    }
#pragma unroll
    for (int j = 0; j < 2; j++) {
        float* rp = &red[slc * 512 + (2 * cp + j) * 16];
#pragma unroll
        for (int m = 0; m < 8; m++) {
            float lo, hi; upk2(acc[j][m], lo, hi);
            rp[2 * m] = lo; rp[2 * m + 1] = hi;
        }
    }
    __syncthreads();
    for (int o = tid; o < 512; o += 256) {
        int c = o >> 4, b = o & 15;
        float s = 0.f;
#pragma unroll
        for (int sl = 0; sl < 16; sl++) s += red[sl * 512 + c * 16 + b];
        int cg = blockIdx.x * 32 + c;
        if (cg < VV)
            out[b * VV + cg] = 1.f / (1.f + expf(-(s + bc[cg])));
    }
}

// ---------------------------------------------------------------------------
// P = pos_emb @ W_ft1[1024:] via bf16 HMMA 3-term. N=64 per CTA,
// grid (54, 8); 256 thr = 4m x 2n warps (32 cols each). 2 CTAs/SM.
// ---------------------------------------------------------------------------
__global__ void __launch_bounds__(256, 2)
k_P_mma(const float* __restrict__ pos, const __nv_bfloat16* __restrict__ B1,
        float* __restrict__ Pout)
{
    extern __shared__ char smem[];
    const u32 sb = smem_u32(smem);
    const int tid = threadIdx.x;
    const int wid = tid >> 5;
    const int l   = tid & 31;
    const int wm = wid & 3;
    const int wn = wid >> 2;
    const int vbase = blockIdx.x * 128;
    const int hbase = blockIdx.y * 64;

    const int r = tid & 127;
    const int half = tid >> 7;
    const int v = vbase + r;
    const int vc = v < VV ? v : VV - 1;
    const float* __restrict__ prow = pos + (size_t)vc * PDIM + half * 32;

    float acc[2][4][4];
#pragma unroll
    for (int i = 0; i < 2; i++)
#pragma unroll
        for (int j = 0; j < 4; j++)
#pragma unroll
            for (int q = 0; q < 4; q++) acc[i][j][q] = 0.f;

    for (int ch = 0; ch < 4; ch++) {
        float4 pf[8];
#pragma unroll
        for (int q = 0; q < 8; q++)
            pf[q] = *(const float4*)(prow + ch * 64 + 4 * q);
#pragma unroll
        for (int kb = 0; kb < 2; kb++) {
            float x[16];
#pragma unroll
            for (int q = 0; q < 4; q++) {
                float4 p4 = pf[kb * 4 + q];
                x[4*q+0] = p4.x; x[4*q+1] = p4.y; x[4*q+2] = p4.z; x[4*q+3] = p4.w;
            }
            u32 hw[8], lw[8];
#pragma unroll
            for (int i = 0; i < 8; i++) {
                __nv_bfloat16 h0 = __float2bfloat16(x[2*i]);
                __nv_bfloat16 h1 = __float2bfloat16(x[2*i+1]);
                __nv_bfloat16 l0 = __float2bfloat16(x[2*i]   - __bfloat162float(h0));
                __nv_bfloat16 l1 = __float2bfloat16(x[2*i+1] - __bfloat162float(h1));
                hw[i] = (u32)__bfloat16_as_ushort(h0) | ((u32)__bfloat16_as_ushort(h1) << 16);
                lw[i] = (u32)__bfloat16_as_ushort(l0) | ((u32)__bfloat16_as_ushort(l1) << 16);
            }
            const u32 c0 = (u32)(half * 4 + kb * 2);
            const u32 q7 = (u32)r & 7u;
            const u32 off0 = (u32)(r << 7) + ((c0 ^ q7) << 4);
            const u32 off1 = (u32)(r << 7) + (((c0 + 1u) ^ q7) << 4);
            asm volatile("st.shared.v4.b32 [%0], {%1,%2,%3,%4};"
                :: "r"(sb + SMP_HH + off0), "r"(hw[0]), "r"(hw[1]), "r"(hw[2]), "r"(hw[3]) : "memory");
            asm volatile("st.shared.v4.b32 [%0], {%1,%2,%3,%4};"
                :: "r"(sb + SMP_HH + off1), "r"(hw[4]), "r"(hw[5]), "r"(hw[6]), "r"(hw[7]) : "memory");
            asm volatile("st.shared.v4.b32 [%0], {%1,%2,%3,%4};"
                :: "r"(sb + SMP_HL + off0), "r"(lw[0]), "r"(lw[1]), "r"(lw[2]), "r"(lw[3]) : "memory");
            asm volatile("st.shared.v4.b32 [%0], {%1,%2,%3,%4};"
                :: "r"(sb + SMP_HL + off1), "r"(lw[4]), "r"(lw[5]), "r"(lw[6]), "r"(lw[7]) : "memory");
        }
        // B slice copy: 64 rows x 128B hi + lo = 512 uint4 each
        {
            const uint4* sH = (const uint4*)(B1 + (size_t)ch * 32768 + (size_t)hbase * 64);
            const uint4* sL = (const uint4*)(B1 + (size_t)(4 + ch) * 32768 + (size_t)hbase * 64);
            uint4* dH = (uint4*)(smem + SMP_BH);
            uint4* dL = (uint4*)(smem + SMP_BL);
#pragma unroll
            for (int i = 0; i < 2; i++) {
                int e = tid + 256 * i;
                dH[e] = sH[e]; dL[e] = sL[e];
            }
        }
        __syncthreads();
#pragma unroll
        for (int ks = 0; ks < 4; ks++) {
            u32 ah[2][4], al[2][4];
#pragma unroll
            for (int mt = 0; mt < 2; mt++) {
                int ra = wm * 32 + mt * 16 + (l & 15);
                u32 c = (u32)(l >> 4) + 2u * ks;
                u32 sw = ((c ^ ((u32)ra & 7u)) << 4);
                ldm_x4(ah[mt], sb + SMP_HH + (u32)(ra << 7) + sw);
                ldm_x4(al[mt], sb + SMP_HL + (u32)(ra << 7) + sw);
            }
#pragma unroll
            for (int p = 0; p < 2; p++) {
                int rb = wn * 32 + p * 16 + (l & 7) + ((l >> 4) & 1) * 8;
                u32 cf = 2u * ks + ((u32)(l >> 3) & 1u);
                u32 swb = ((cf ^ ((u32)rb & 7u)) << 4);
                u32 bh[4], bl[4];
                ldm_x4(bh, sb + SMP_BH + (u32)(rb << 7) + swb);
                ldm_x4(bl, sb + SMP_BL + (u32)(rb << 7) + swb);
#pragma unroll
                for (int mt = 0; mt < 2; mt++)
#pragma unroll
                    for (int t = 0; t < 2; t++) {
                        float* d = acc[mt][p * 2 + t];
                        mma_bf16(d, ah[mt], &bh[2 * t]);
                        mma_bf16(d, ah[mt], &bl[2 * t]);
                        mma_bf16(d, al[mt], &bh[2 * t]);
                    }
            }
        }
        __syncthreads();
    }

    const int g = l >> 2, tg = l & 3;
#pragma unroll
    for (int mt = 0; mt < 2; mt++) {
        const int i0 = vbase + wm * 32 + mt * 16 + g;
        const int i1 = i0 + 8;
#pragma unroll
        for (int nt = 0; nt < 4; nt++) {
            const int col = hbase + wn * 32 + nt * 8 + tg * 2;
            if (i0 < VV)
                *(float2*)&Pout[(size_t)i0 * HID + col]
                    = make_float2(acc[mt][nt][0], acc[mt][nt][1]);
            if (i1 < VV)
                *(float2*)&Pout[(size_t)i1 * HID + col]
                    = make_float2(acc[mt][nt][2], acc[mt][nt][3]);
        }
    }
}

// ---------------------------------------------------------------------------
// Order-preserving mask compaction (idx + cnt).
// ---------------------------------------------------------------------------
__global__ void __launch_bounds__(1024)
k_compact(const float* __restrict__ cont, int* __restrict__ idx,
          int* __restrict__ cnt)
{
    const int b = blockIdx.x;
    const int tid = threadIdx.x;
    const int lane = tid & 31, wid = tid >> 5;
    __shared__ int wexc[32];
    __shared__ int s_base, s_tot;
    if (tid == 0) s_base = 0;
    __syncthreads();
    for (int v0 = 0; v0 < VV; v0 += 1024) {
        int v = v0 + tid;
        int m = (v < VV) && (cont[b * VV + v] > 0.5f);
        unsigned bal = __ballot_sync(0xffffffffu, m);
        int wsum = __popc(bal);
        int pw = __popc(bal & ((1u << lane) - 1u));
        if (lane == 0) wexc[wid] = wsum;
        __syncthreads();
        if (tid < 32) {
            int sv = wexc[tid];
            int e = sv;
#pragma unroll
            for (int d = 1; d < 32; d <<= 1) {
                int t = __shfl_up_sync(0xffffffffu, e, d);
                if (tid >= d) e += t;
            }
            wexc[tid] = e - sv;
            if (tid == 31) s_tot = e;
        }
        __syncthreads();
        int pos = s_base + wexc[wid] + pw;
        if (v < VV && m) idx[b * VV + pos] = v;
        __syncthreads();
        if (tid == 0) s_base += s_tot;
        __syncthreads();
    }
    if (tid == 0) cnt[b] = s_base;
}

// ---------------------------------------------------------------------------
// PERSISTENT pipelined main GEMM (compacted rows), fp16 mma.sync 2-term,
// fused scattered epilogue (sem pre-zeroed). grid = NPERS; each CTA loops
// over global tile list derived from cnt[].
// ---------------------------------------------------------------------------
__global__ void __launch_bounds__(256, 2)
k_sem_mma(const float* __restrict__ A4,
          const float* __restrict__ P,
          const __half* __restrict__ Bimg,
          const float* __restrict__ b2,
          const int* __restrict__ idx,
          const int* __restrict__ cnt,
          float* __restrict__ sem)
{
    extern __shared__ char smem[];
    const u32 sb = smem_u32(smem);
    const int tid = threadIdx.x;
    const int wid = tid >> 5;
    const int l   = tid & 31;
    const int wm = wid & 3;
    const int wn = wid >> 2;
    const int r = tid & 127;
    const int half = tid >> 7;
    const u32 qr = ((u32)r >> 3) & 3;
    const u32 hbase_off = (u32)(r * 144);

    // tile offsets from cnt (cheap per-thread scalar compute)
    int offv[17];
    offv[0] = 0;
#pragma unroll
    for (int b = 0; b < 16; b++)
        offv[b + 1] = offv[b] + ((cnt[b] + 127) >> 7);
    const int total = offv[16];

    float* a_sm = (float*)(smem + SM_AS);

    for (int w = blockIdx.x; w < total; w += NPERS) {
        int b = 0;
#pragma unroll
        for (int t = 0; t < 15; t++) if (w >= offv[b + 1]) b++;
        const int cntb = cnt[b];
        const int ibase = (w - offv[b]) << 7;

        // stage a[b]
        for (int i = tid; i < HID; i += 256) {
            float s = 0.f;
#pragma unroll
            for (int sc = 0; sc < 4; sc++)
                s += A4[(size_t)sc * BB * HID + b * HID + i];
            a_sm[i] = s;
        }

        const int ig = ibase + r;
        const int vrow = idx[b * VV + (ig < cntb ? ig : cntb - 1)];
        const float* __restrict__ prow = P + (size_t)vrow * HID + half * 32;

        float acc[2][9][4];
#pragma unroll
        for (int i = 0; i < 2; i++)
#pragma unroll
            for (int j = 0; j < 9; j++)
#pragma unroll
                for (int q = 0; q < 4; q++) acc[i][j][q] = 0.f;

        float4 pf[8];

        // prologue: B(0) cp.async + H(0) produce
        {
            const char* srcB = (const char*)(Bimg);
            u32 dstB = sb + SM_B(0);
            for (int e = tid; e < 1088; e += 256)
                cpasync16(dstB + e * 16, srcB + e * 16);
            cpasync_commit();
        }
#pragma unroll
        for (int q = 0; q < 8; q++) pf[q] = *(const float4*)(prow + 4 * q);
        __syncthreads();   // a_sm ready
#pragma unroll
        for (int kb = 0; kb < 2; kb++) {
            float x[16];
#pragma unroll
            for (int q = 0; q < 4; q++) {
                float4 p4 = pf[kb * 4 + q];
                const float* ap = a_sm + half * 32 + kb * 16 + 4 * q;
                x[4*q+0] = fmaxf(p4.x + ap[0], 0.f);
                x[4*q+1] = fmaxf(p4.y + ap[1], 0.f);
                x[4*q+2] = fmaxf(p4.z + ap[2], 0.f);
                x[4*q+3] = fmaxf(p4.w + ap[3], 0.f);
            }
            u32 hw[8], lw[8];
#pragma unroll
            for (int i = 0; i < 8; i++) {
                __half2 hh = __floats2half2_rn(x[2*i], x[2*i+1]);
                float2 hf = __half22float2(hh);
                __half2 hl = __floats2half2_rn(x[2*i] - hf.x, x[2*i+1] - hf.y);
                hw[i] = h2u(hh); lw[i] = h2u(hl);
            }
            const u32 c0 = (u32)(half * 4 + kb * 2);
            const u32 off0 = hbase_off + ((c0 ^ qr) << 4);
            const u32 off1 = hbase_off + (((c0 + 1u) ^ qr) << 4);
            asm volatile("st.shared.v4.b32 [%0], {%1,%2,%3,%4};"
                :: "r"(sb + SM_H(0) + off0), "r"(hw[0]), "r"(hw[1]), "r"(hw[2]), "r"(hw[3]) : "memory");
            asm volatile("st.shared.v4.b32 [%0], {%1,%2,%3,%4};"
                :: "r"(sb + SM_H(0) + off1), "r"(hw[4]), "r"(hw[5]), "r"(hw[6]), "r"(hw[7]) : "memory");
            asm volatile("st.shared.v4.b32 [%0], {%1,%2,%3,%4};"
                :: "r"(sb + SM_H(0) + 18432 + off0), "r"(lw[0]), "r"(lw[1]), "r"(lw[2]), "r"(lw[3]) : "memory");
            asm volatile("st.shared.v4.b32 [%0], {%1,%2,%3,%4};"
                :: "r"(sb + SM_H(0) + 18432 + off1), "r"(lw[4]), "r"(lw[5]), "r"(lw[6]), "r"(lw[7]) : "memory");
        }
        cpasync_wait0();

        int buf = 0;
        for (int ch = 0; ch < 8; ch++) {
            __syncthreads();
            const int nb = buf ^ 1;
            if (ch < 7) {
                const char* srcB = (const char*)(Bimg + (size_t)(ch + 1) * (BROWS * 64));
                u32 dstB = sb + SM_B(nb);
                for (int e = tid; e < 1088; e += 256)
                    cpasync16(dstB + e * 16, srcB + e * 16);
                cpasync_commit();
                const float* ps = prow + (ch + 1) * 64;
#pragma unroll
                for (int q = 0; q < 8; q++) pf[q] = *(const float4*)(ps + 4 * q);
            }

            const u32 hH = sb + SM_H(buf);
            const u32 hL = hH + 18432;
            const u32 bB = sb + SM_B(buf);
#pragma unroll
            for (int ks = 0; ks < 4; ks++) {
                u32 ah[2][4], al[2][4];
#pragma unroll
                for (int mt = 0; mt < 2; mt++) {
                    int ra = wm * 32 + mt * 16 + (l & 15);
                    u32 qa = ((u32)ra >> 3) & 3;
                    u32 chk = (((u32)(l >> 4) + 2u * ks) ^ qa) << 4;
                    ldm_x4(ah[mt], hH + (u32)(ra * 144) + chk);
                    ldm_x4(al[mt], hL + (u32)(ra * 144) + chk);
                }
#pragma unroll
                for (int p = 0; p < 4; p++) {
                    int rb = wn * 72 + p * 16 + (l & 7) + ((l >> 4) & 1) * 8;
                    u32 chunkf = 2u * ks + ((u32)(l >> 3) & 1u);
                    u32 bb[4];
                    ldm_x4(bb, bB + (u32)(rb << 7) + ((chunkf ^ ((u32)rb & 7u)) << 4));
#pragma unroll
                    for (int mt = 0; mt < 2; mt++)
#pragma unroll
                        for (int t = 0; t < 2; t++) {
                            float* d = acc[mt][p * 2 + t];
                            mma_f16(d, ah[mt], &bb[2 * t]);
                            mma_f16(d, al[mt], &bb[2 * t]);
                        }
                }
                {
                    int rb2 = 64 + (l & 7);
                    u32 chunkf = 2u * ks + ((u32)(l >> 3) & 1u);
                    u32 s2[2];
                    ldm_x2(s2, bB + (u32)(rb2 << 7) + ((chunkf ^ ((u32)rb2 & 7u)) << 4));
#pragma unroll
                    for (int mt = 0; mt < 2; mt++) {
                        float* d = acc[mt][8];
                        mma_f16(d, ah[mt], s2);
                        mma_f16(d, al[mt], s2);
                    }
                }
            }

            if (ch < 7) {
#pragma unroll
                for (int kb = 0; kb < 2; kb++) {
                    float x[16];
#pragma unroll
                    for (int q = 0; q < 4; q++) {
                        float4 p4 = pf[kb * 4 + q];
                        const float* ap = a_sm + (ch + 1) * 64 + half * 32 + kb * 16 + 4 * q;
                        x[4*q+0] = fmaxf(p4.x + ap[0], 0.f);
                        x[4*q+1] = fmaxf(p4.y + ap[1], 0.f);
                        x[4*q+2] = fmaxf(p4.z + ap[2], 0.f);
                        x[4*q+3] = fmaxf(p4.w + ap[3], 0.f);
                    }
                    u32 hw[8], lw[8];
#pragma unroll
                    for (int i = 0; i < 8; i++) {
                        __half2 hh = __floats2half2_rn(x[2*i], x[2*i+1]);
                        float2 hf = __half22float2(hh);
                        __half2 hl = __floats2half2_rn(x[2*i] - hf.x, x[2*i+1] - hf.y);
                        hw[i] = h2u(hh); lw[i] = h2u(hl);
                    }
                    const u32 c0 = (u32)(half * 4 + kb * 2);
                    const u32 off0 = hbase_off + ((c0 ^ qr) << 4);
                    const u32 off1 = hbase_off + (((c0 + 1u) ^ qr) << 4);
                    asm volatile("st.shared.v4.b32 [%0], {%1,%2,%3,%4};"
                        :: "r"(sb + SM_H(nb) + off0), "r"(hw[0]), "r"(hw[1]), "r"(hw[2]), "r"(hw[3]) : "memory");
                    asm volatile("st.shared.v4.b32 [%0], {%1,%2,%3,%4};"
                        :: "r"(sb + SM_H(nb) + off1), "r"(hw[4]), "r"(hw[5]), "r"(hw[6]), "r"(hw[7]) : "memory");
                    asm volatile("st.shared.v4.b32 [%0], {%1,%2,%3,%4};"
                        :: "r"(sb + SM_H(nb) + 18432 + off0), "r"(lw[0]), "r"(lw[1]), "r"(lw[2]), "r"(lw[3]) : "memory");
                    asm volatile("st.shared.v4.b32 [%0], {%1,%2,%3,%4};"
                        :: "r"(sb + SM_H(nb) + 18432 + off1), "r"(lw[4]), "r"(lw[5]), "r"(lw[6]), "r"(lw[7]) : "memory");
                }
                cpasync_wait0();
            }
            buf = nb;
        }

        // fused epilogue: bias + scattered store sem[b, col, idx[i]]
        const int g = l >> 2, tg = l & 3;
#pragma unroll
        for (int mt = 0; mt < 2; mt++) {
            const int i0 = ibase + wm * 32 + mt * 16 + g;
            const int i1 = i0 + 8;
            const bool ok0 = i0 < cntb, ok1 = i1 < cntb;
            const int v0 = ok0 ? idx[b * VV + i0] : 0;
            const int v1 = ok1 ? idx[b * VV + i1] : 0;
#pragma unroll
            for (int nt = 0; nt < 9; nt++) {
                const int cbase = wn * 72 + nt * 8 + tg * 2;
#pragma unroll
                for (int q = 0; q < 2; q++) {
                    const int col = cbase + q;
                    if (col >= CC) continue;
                    const float bias = __ldg(&b2[col]);
                    if (ok0) sem[((size_t)b * CC + col) * VV + v0] = acc[mt][nt][q] + bias;
                    if (ok1) sem[((size_t)b * CC + col) * VV + v1] = acc[mt][nt][2 + q] + bias;
                }
            }
        }
    }
}

// ---------------------------------------------------------------------------
extern "C" void kernel_launch(void* const* d_in, const int* in_sizes, int n_in,
                              void* d_out, int out_size)
{
    const float* features  = (const float*)d_in[0];
    const float* W_contact = (const float*)d_in[3];
    const float* b_contact = (const float*)d_in[4];
    const float* Wv        = (const float*)d_in[7];
    const float* Wo        = (const float*)d_in[8];
    const float* W_cls     = (const float*)d_in[9];
    const float* b_cls     = (const float*)d_in[10];
    const float* pos_emb   = (const float*)d_in[11];
    const float* W_ft1     = (const float*)d_in[12];
    const float* b_ft1     = (const float*)d_in[13];
    const float* W_ft2     = (const float*)d_in[14];
    const float* b_ft2     = (const float*)d_in[15];

    float* out  = (float*)d_out;
    float* cont = out;                  // [16, 6890]
    float* sem  = out + BB * VV;        // [16, 133, 6890]

    float *part, *tmp, *att, *a, *Pbuf;
    int *idx, *cnt;
    __half* Bimg;
    __nv_bfloat16* B1img;
    cudaGetSymbolAddress((void**)&part,  g_part);
    cudaGetSymbolAddress((void**)&tmp,   g_tmp);
    cudaGetSymbolAddress((void**)&att,   g_att);
    cudaGetSymbolAddress((void**)&a,     g_a);
    cudaGetSymbolAddress((void**)&Pbuf,  g_P);
    cudaGetSymbolAddress((void**)&idx,   g_idx);
    cudaGetSymbolAddress((void**)&cnt,   g_cnt);
    cudaGetSymbolAddress((void**)&Bimg,  g_Bimg);
    cudaGetSymbolAddress((void**)&B1img, g_B1img);

    cudaFuncSetAttribute(k_sem_mma, cudaFuncAttributeMaxDynamicSharedMemorySize, SM_TOT);
    cudaFuncSetAttribute(k_P_mma,  cudaFuncAttributeMaxDynamicSharedMemorySize, SMP_TOT);

    // fused zero + weight-image prep
    k_misc<<<528, 256>>>(W_ft2, Bimg, W_ft1, B1img,
                         (float4*)sem, (BB * CC * VV) / 4);

    // P = pos_emb @ W_ft1[1024:] on HMMA bf16 3-term (N=64/CTA)
    dim3 gP((VV + 127) / 128, 8);
    k_P_mma<<<gP, 256, SMP_TOT>>>(pos_emb, B1img, Pbuf);

    // att chain, 4-way K-split partials
    k_skinny<<<dim3(32, 4), 512>>>(features, W_contact, b_contact, part, DF, DD, 1);
    k_skinny<<<dim3(32, 4), 512>>>(part, Wv, nullptr, tmp, DD, DD, 4);
    k_skinny<<<dim3(32, 4), 512>>>(tmp,  Wo, nullptr, att, DD, DD, 4);

    // cont + a (consume 4 partials)
    k_cont2<<<(VV + 31) / 32, 256>>>(att, W_cls, b_cls, cont);
    k_skinny<<<dim3(16, 4), 512>>>(att, W_ft1, b_ft1, a, DD, HID, 4);

    // compaction
    k_compact<<<BB, 1024>>>(cont, idx, cnt);

    // persistent pipelined main GEMM with fused scattered epilogue
    k_sem_mma<<<NPERS, 256, SM_TOT>>>(a, Pbuf, Bimg, b_ft2, idx, cnt, sem);
}

// round 11
// speedup vs baseline: 7.6905x; 1.0979x over previous
#include <cuda_runtime.h>
#include <cuda_fp16.h>
#include <cuda_bf16.h>
#include <math.h>

// DECO decomposed (len-1 softmax == 1 → Wq/Wk/W_scene dead):
//   att  = (feat @ W_contact + b_c) @ Wv @ Wo            [16,1024]
//   cont = sigmoid(att @ W_cls + b_cls)                  [16,6890]
//   a    = att @ W_ft1[:1024] + b_ft1                    [16,512]
//   P    = pos_emb @ W_ft1[1024:]   (HMMA bf16 3-term)
//   sem[b,c,v] = mask * (relu(a[b]+P[v]) @ W_ft2 + b2)[c]
// Main GEMM: fp16 mma.sync 1-TERM (H and W both fp16), mask-compacted rows,
// persistent 1-CTA/SM with ALL B chunk images smem-resident, fused scattered
// epilogue.

#define BB   16
#define DF   1536
#define DD   1024
#define VV   6890
#define PDIM 256
#define HID  512
#define CC   133
#define NC   144
#define BROWS 136
#define NPERS 148

typedef unsigned long long u64;
typedef unsigned int u32;

__device__ float g_part[4 * BB * DD];
__device__ float g_tmp [4 * BB * DD];
__device__ float g_att [4 * BB * DD];
__device__ float g_a   [4 * BB * HID];
__device__ float g_P   [VV * HID];
__device__ int   g_idx [BB * VV];
__device__ int   g_cnt [BB];
__device__ __align__(16) __half g_Bimg[8 * BROWS * 64];
__device__ __align__(16) __nv_bfloat16 g_B1img[2 * 4 * 512 * 64];

__device__ __forceinline__ u64 pk2(float lo, float hi) {
    u64 r; asm("mov.b64 %0, {%1, %2};" : "=l"(r) : "f"(lo), "f"(hi)); return r;
}
__device__ __forceinline__ void upk2(u64 v, float& lo, float& hi) {
    asm("mov.b64 {%0, %1}, %2;" : "=f"(lo), "=f"(hi) : "l"(v));
}
__device__ __forceinline__ u64 ffma2(u64 a, u64 b, u64 c) {
    u64 d; asm("fma.rn.f32x2 %0, %1, %2, %3;" : "=l"(d) : "l"(a), "l"(b), "l"(c));
    return d;
}
__device__ __forceinline__ u32 smem_u32(const void* p) {
    u32 a; asm("{ .reg .u64 t; cvta.to.shared.u64 t, %1; cvt.u32.u64 %0, t; }"
               : "=r"(a) : "l"(p));
    return a;
}
__device__ __forceinline__ void ldm_x4(u32* r, u32 addr) {
    asm volatile("ldmatrix.sync.aligned.m8n8.x4.shared.b16 {%0,%1,%2,%3}, [%4];"
        : "=r"(r[0]), "=r"(r[1]), "=r"(r[2]), "=r"(r[3]) : "r"(addr));
}
__device__ __forceinline__ void ldm_x2(u32* r, u32 addr) {
    asm volatile("ldmatrix.sync.aligned.m8n8.x2.shared.b16 {%0,%1}, [%2];"
        : "=r"(r[0]), "=r"(r[1]) : "r"(addr));
}
__device__ __forceinline__ void mma_f16(float* d, const u32* a, const u32* b) {
    asm volatile("mma.sync.aligned.m16n8k16.row.col.f32.f16.f16.f32 "
        "{%0,%1,%2,%3}, {%4,%5,%6,%7}, {%8,%9}, {%0,%1,%2,%3};"
        : "+f"(d[0]), "+f"(d[1]), "+f"(d[2]), "+f"(d[3])
        : "r"(a[0]), "r"(a[1]), "r"(a[2]), "r"(a[3]), "r"(b[0]), "r"(b[1]));
}
__device__ __forceinline__ void mma_bf16(float* d, const u32* a, const u32* b) {
    asm volatile("mma.sync.aligned.m16n8k16.row.col.f32.bf16.bf16.f32 "
        "{%0,%1,%2,%3}, {%4,%5,%6,%7}, {%8,%9}, {%0,%1,%2,%3};"
        : "+f"(d[0]), "+f"(d[1]), "+f"(d[2]), "+f"(d[3])
        : "r"(a[0]), "r"(a[1]), "r"(a[2]), "r"(a[3]), "r"(b[0]), "r"(b[1]));
}
__device__ __forceinline__ u32 h2u(__half2 h) {
    u32 r; asm("mov.b32 %0, %1;" : "=r"(r) : "r"(*(u32*)&h)); return r;
}
__device__ __forceinline__ void cpasync16(u32 dst, const void* src) {
    asm volatile("cp.async.cg.shared.global [%0], [%1], 16;"
                 :: "r"(dst), "l"(src) : "memory");
}
__device__ __forceinline__ void cpasync_commit() {
    asm volatile("cp.async.commit_group;" ::: "memory");
}
__device__ __forceinline__ void cpasync_wait0() {
    asm volatile("cp.async.wait_group 0;" ::: "memory");
}

// k_sem smem layout (bytes): a_sm | H double-buffer (hi only) | 8 B chunks
#define SM_AS     0
#define SM_H(bf)  (2048 + (bf) * 18432)
#define SM_BALL   38912
#define SM_BC(ch) (SM_BALL + (ch) * 17408)
#define SM_TOT    178176
// k_P_mma smem layout (bytes)
#define SMP_HH 0
#define SMP_HL 16384
#define SMP_BH 32768
#define SMP_BL 40960
#define SMP_TOT 49152

// ---------------------------------------------------------------------------
// Fused misc: [0,8) prepW fp16 W_ft2 images; [8,16) prepW1 bf16 W_ft1 hi/lo;
// [16,528) zero sem.
// ---------------------------------------------------------------------------
__global__ void __launch_bounds__(256)
k_misc(const float* __restrict__ W2, __half* __restrict__ Bimg,
       const float* __restrict__ W1, __nv_bfloat16* __restrict__ B1,
       float4* __restrict__ zp, int n4)
{
    const int bx = blockIdx.x;
    const int tid = threadIdx.x;
    if (bx < 8) {
        const int img = bx;
        for (int e = tid; e < BROWS * 64; e += 256) {
            int n = e >> 6, k = e & 63;
            float w = (n < CC) ? W2[(size_t)(img * 64 + k) * CC + n] : 0.f;
            int off = (n << 6) + (((k >> 3) ^ (n & 7)) << 3) + (k & 7);
            Bimg[(size_t)img * (BROWS * 64) + off] = __float2half_rn(w);
        }
    } else if (bx < 16) {
        const int blk = bx - 8;
        const int plane = blk >> 2, ch = blk & 3;
        for (int e = tid; e < 512 * 64; e += 256) {
            int n = e >> 6, k = e & 63;
            float w = W1[(size_t)(DD + ch * 64 + k) * HID + n];
            __nv_bfloat16 h = __float2bfloat16(w);
            __nv_bfloat16 val = plane ? __float2bfloat16(w - __bfloat162float(h)) : h;
            int off = (n << 6) + (((k >> 3) ^ (n & 7)) << 3) + (k & 7);
            B1[(size_t)blk * (512 * 64) + off] = val;
        }
    } else {
        const int zb = bx - 16;
        for (int i = zb * 256 + tid; i < n4; i += 512 * 256)
            zp[i] = make_float4(0.f, 0.f, 0.f, 0.f);
    }
}

// ---------------------------------------------------------------------------
// Split-K skinny GEMM: out[gy][16][N] partial = in(sum nsum copies) @ W
// ---------------------------------------------------------------------------
__global__ void __launch_bounds__(512)
k_skinny(const float* __restrict__ in, const float* __restrict__ W,
         const float* __restrict__ bias, float* __restrict__ out,
         int K, int N, int nsum)
{
    __shared__ float in_s[128 * 18];
    __shared__ float red[16 * 512];

    const int tid  = threadIdx.x;
    const int col  = tid & 31;
    const int slc  = tid >> 5;
    const int colg = blockIdx.x * 32 + col;
    const int colc = colg < N ? colg : N - 1;
    const int kspan = K / gridDim.y;
    const int kbase = blockIdx.y * kspan;

    u64 acc2[8];
#pragma unroll
    for (int m = 0; m < 8; m++) acc2[m] = 0ull;

    for (int k0 = kbase; k0 < kbase + kspan; k0 += 128) {
        __syncthreads();
#pragma unroll
        for (int i = 0; i < 4; i++) {
            int e = tid + 512 * i;
            int b = e >> 7, k = e & 127;
            float s = 0.f;
            for (int sc = 0; sc < nsum; sc++)
                s += in[(size_t)sc * BB * K + b * K + k0 + k];
            in_s[k * 18 + b] = s;
        }
        __syncthreads();
#pragma unroll
        for (int kk = 0; kk < 8; kk++) {
            int k = slc * 8 + kk;
            float w = W[(size_t)(k0 + k) * N + colc];
            u64 w2 = pk2(w, w);
            const u64* ip = (const u64*)&in_s[k * 18];
#pragma unroll
            for (int m = 0; m < 8; m++)
                acc2[m] = ffma2(ip[m], w2, acc2[m]);
        }
    }
    float* rp = &red[slc * 512 + col * 16];
#pragma unroll
    for (int m = 0; m < 8; m++) {
        float lo, hi; upk2(acc2[m], lo, hi);
        rp[2 * m] = lo; rp[2 * m + 1] = hi;
    }
    __syncthreads();
    {
        int c = tid >> 4, b = tid & 15;
        float s = 0.f;
#pragma unroll
        for (int sl = 0; sl < 16; sl++) s += red[sl * 512 + c * 16 + b];
        int cg = blockIdx.x * 32 + c;
        if (cg < N) {
            float bb = (bias && blockIdx.y == 0) ? bias[cg] : 0.f;
            out[(size_t)blockIdx.y * BB * N + b * N + cg] = s + bb;
        }
    }
}

// ---------------------------------------------------------------------------
// cont = sigmoid(sum4(att) @ W_cls + b_cls); float2 col pairs.
// ---------------------------------------------------------------------------
__global__ void __launch_bounds__(256)
k_cont2(const float* __restrict__ att, const float* __restrict__ Wc,
        const float* __restrict__ bc, float* __restrict__ out)
{
    __shared__ float in_s[128 * 18];
    __shared__ float red[16 * 32 * 16];

    const int tid = threadIdx.x;
    const int cp  = tid & 15;
    const int slc = tid >> 4;
    const int col0 = blockIdx.x * 32 + 2 * cp;
    const int colc = col0 <= VV - 2 ? col0 : VV - 2;

    u64 acc[2][8];
#pragma unroll
    for (int j = 0; j < 2; j++)
#pragma unroll
        for (int m = 0; m < 8; m++) acc[j][m] = 0ull;

    for (int k0 = 0; k0 < DD; k0 += 128) {
        __syncthreads();
#pragma unroll
        for (int i = 0; i < 8; i++) {
            int e = tid + 256 * i;
            int b = e >> 7, k = e & 127;
            float s = 0.f;
#pragma unroll
            for (int sc = 0; sc < 4; sc++)
                s += att[(size_t)sc * BB * DD + b * DD + k0 + k];
            in_s[k * 18 + b] = s;
        }
        __syncthreads();
#pragma unroll
        for (int kk = 0; kk < 8; kk++) {
            int k = slc * 8 + kk;
            float2 w = *(const float2*)&Wc[(size_t)(k0 + k) * VV + colc];
            u64 w0 = pk2(w.x, w.x), w1 = pk2(w.y, w.y);
            const u64* ip = (const u64*)&in_s[k * 18];
#pragma unroll
            for (int m = 0; m < 8; m++) {
                acc[0][m] = ffma2(ip[m], w0, acc[0][m]);
                acc[1][m] = ffma2(ip[m], w1, acc[1][m]);
            }
        }
    }
#pragma unroll
    for (int j = 0; j < 2; j++) {
        float* rp = &red[slc * 512 + (2 * cp + j) * 16];
#pragma unroll
        for (int m = 0; m < 8; m++) {
            float lo, hi; upk2(acc[j][m], lo, hi);
            rp[2 * m] = lo; rp[2 * m + 1] = hi;
        }
    }
    __syncthreads();
    for (int o = tid; o < 512; o += 256) {
        int c = o >> 4, b = o & 15;
        float s = 0.f;
#pragma unroll
        for (int sl = 0; sl < 16; sl++) s += red[sl * 512 + c * 16 + b];
        int cg = blockIdx.x * 32 + c;
        if (cg < VV)
            out[b * VV + cg] = 1.f / (1.f + expf(-(s + bc[cg])));
    }
}

// ---------------------------------------------------------------------------
// P = pos_emb @ W_ft1[1024:] via bf16 HMMA 3-term. N=64/CTA, grid (54, 8).
// ---------------------------------------------------------------------------
__global__ void __launch_bounds__(256, 2)
k_P_mma(const float* __restrict__ pos, const __nv_bfloat16* __restrict__ B1,
        float* __restrict__ Pout)
{
    extern __shared__ char smem[];
    const u32 sb = smem_u32(smem);
    const int tid = threadIdx.x;
    const int wid = tid >> 5;
    const int l   = tid & 31;
    const int wm = wid & 3;
    const int wn = wid >> 2;
    const int vbase = blockIdx.x * 128;
    const int hbase = blockIdx.y * 64;

    const int r = tid & 127;
    const int half = tid >> 7;
    const int v = vbase + r;
    const int vc = v < VV ? v : VV - 1;
    const float* __restrict__ prow = pos + (size_t)vc * PDIM + half * 32;

    float acc[2][4][4];
#pragma unroll
    for (int i = 0; i < 2; i++)
#pragma unroll
        for (int j = 0; j < 4; j++)
#pragma unroll
            for (int q = 0; q < 4; q++) acc[i][j][q] = 0.f;

    for (int ch = 0; ch < 4; ch++) {
        float4 pf[8];
#pragma unroll
        for (int q = 0; q < 8; q++)
            pf[q] = *(const float4*)(prow + ch * 64 + 4 * q);
#pragma unroll
        for (int kb = 0; kb < 2; kb++) {
            float x[16];
#pragma unroll
            for (int q = 0; q < 4; q++) {
                float4 p4 = pf[kb * 4 + q];
                x[4*q+0] = p4.x; x[4*q+1] = p4.y; x[4*q+2] = p4.z; x[4*q+3] = p4.w;
            }
            u32 hw[8], lw[8];
#pragma unroll
            for (int i = 0; i < 8; i++) {
                __nv_bfloat16 h0 = __float2bfloat16(x[2*i]);
                __nv_bfloat16 h1 = __float2bfloat16(x[2*i+1]);
                __nv_bfloat16 l0 = __float2bfloat16(x[2*i]   - __bfloat162float(h0));
                __nv_bfloat16 l1 = __float2bfloat16(x[2*i+1] - __bfloat162float(h1));
                hw[i] = (u32)__bfloat16_as_ushort(h0) | ((u32)__bfloat16_as_ushort(h1) << 16);
                lw[i] = (u32)__bfloat16_as_ushort(l0) | ((u32)__bfloat16_as_ushort(l1) << 16);
            }
            const u32 c0 = (u32)(half * 4 + kb * 2);
            const u32 q7 = (u32)r & 7u;
            const u32 off0 = (u32)(r << 7) + ((c0 ^ q7) << 4);
            const u32 off1 = (u32)(r << 7) + (((c0 + 1u) ^ q7) << 4);
            asm volatile("st.shared.v4.b32 [%0], {%1,%2,%3,%4};"
                :: "r"(sb + SMP_HH + off0), "r"(hw[0]), "r"(hw[1]), "r"(hw[2]), "r"(hw[3]) : "memory");
            asm volatile("st.shared.v4.b32 [%0], {%1,%2,%3,%4};"
                :: "r"(sb + SMP_HH + off1), "r"(hw[4]), "r"(hw[5]), "r"(hw[6]), "r"(hw[7]) : "memory");
            asm volatile("st.shared.v4.b32 [%0], {%1,%2,%3,%4};"
                :: "r"(sb + SMP_HL + off0), "r"(lw[0]), "r"(lw[1]), "r"(lw[2]), "r"(lw[3]) : "memory");
            asm volatile("st.shared.v4.b32 [%0], {%1,%2,%3,%4};"
                :: "r"(sb + SMP_HL + off1), "r"(lw[4]), "r"(lw[5]), "r"(lw[6]), "r"(lw[7]) : "memory");
        }
        {
            const uint4* sH = (const uint4*)(B1 + (size_t)ch * 32768 + (size_t)hbase * 64);
            const uint4* sL = (const uint4*)(B1 + (size_t)(4 + ch) * 32768 + (size_t)hbase * 64);
            uint4* dH = (uint4*)(smem + SMP_BH);
            uint4* dL = (uint4*)(smem + SMP_BL);
#pragma unroll
            for (int i = 0; i < 2; i++) {
                int e = tid + 256 * i;
                dH[e] = sH[e]; dL[e] = sL[e];
            }
        }
        __syncthreads();
#pragma unroll
        for (int ks = 0; ks < 4; ks++) {
            u32 ah[2][4], al[2][4];
#pragma unroll
            for (int mt = 0; mt < 2; mt++) {
                int ra = wm * 32 + mt * 16 + (l & 15);
                u32 c = (u32)(l >> 4) + 2u * ks;
                u32 sw = ((c ^ ((u32)ra & 7u)) << 4);
                ldm_x4(ah[mt], sb + SMP_HH + (u32)(ra << 7) + sw);
                ldm_x4(al[mt], sb + SMP_HL + (u32)(ra << 7) + sw);
            }
#pragma unroll
            for (int p = 0; p < 2; p++) {
                int rb = wn * 32 + p * 16 + (l & 7) + ((l >> 4) & 1) * 8;
                u32 cf = 2u * ks + ((u32)(l >> 3) & 1u);
                u32 swb = ((cf ^ ((u32)rb & 7u)) << 4);
                u32 bh[4], bl[4];
                ldm_x4(bh, sb + SMP_BH + (u32)(rb << 7) + swb);
                ldm_x4(bl, sb + SMP_BL + (u32)(rb << 7) + swb);
#pragma unroll
                for (int mt = 0; mt < 2; mt++)
#pragma unroll
                    for (int t = 0; t < 2; t++) {
                        float* d = acc[mt][p * 2 + t];
                        mma_bf16(d, ah[mt], &bh[2 * t]);
                        mma_bf16(d, ah[mt], &bl[2 * t]);
                        mma_bf16(d, al[mt], &bh[2 * t]);
                    }
            }
        }
        __syncthreads();
    }

    const int g = l >> 2, tg = l & 3;
#pragma unroll
    for (int mt = 0; mt < 2; mt++) {
        const int i0 = vbase + wm * 32 + mt * 16 + g;
        const int i1 = i0 + 8;
#pragma unroll
        for (int nt = 0; nt < 4; nt++) {
            const int col = hbase + wn * 32 + nt * 8 + tg * 2;
            if (i0 < VV)
                *(float2*)&Pout[(size_t)i0 * HID + col]
                    = make_float2(acc[mt][nt][0], acc[mt][nt][1]);
            if (i1 < VV)
                *(float2*)&Pout[(size_t)i1 * HID + col]
                    = make_float2(acc[mt][nt][2], acc[mt][nt][3]);
        }
    }
}

// ---------------------------------------------------------------------------
// Order-preserving mask compaction.
// ---------------------------------------------------------------------------
__global__ void __launch_bounds__(1024)
k_compact(const float* __restrict__ cont, int* __restrict__ idx,
          int* __restrict__ cnt)
{
    const int b = blockIdx.x;
    const int tid = threadIdx.x;
    const int lane = tid & 31, wid = tid >> 5;
    __shared__ int wexc[32];
    __shared__ int s_base, s_tot;
    if (tid == 0) s_base = 0;
    __syncthreads();
    for (int v0 = 0; v0 < VV; v0 += 1024) {
        int v = v0 + tid;
        int m = (v < VV) && (cont[b * VV + v] > 0.5f);
        unsigned bal = __ballot_sync(0xffffffffu, m);
        int wsum = __popc(bal);
        int pw = __popc(bal & ((1u << lane) - 1u));
        if (lane == 0) wexc[wid] = wsum;
        __syncthreads();
        if (tid < 32) {
            int sv = wexc[tid];
            int e = sv;
#pragma unroll
            for (int d = 1; d < 32; d <<= 1) {
                int t = __shfl_up_sync(0xffffffffu, e, d);
                if (tid >= d) e += t;
            }
            wexc[tid] = e - sv;
            if (tid == 31) s_tot = e;
        }
        __syncthreads();
        int pos = s_base + wexc[wid] + pw;
        if (v < VV && m) idx[b * VV + pos] = v;
        __syncthreads();
        if (tid == 0) s_base += s_tot;
        __syncthreads();
    }
    if (tid == 0) cnt[b] = s_base;
}

// ---------------------------------------------------------------------------
// PERSISTENT main GEMM, 1-term fp16. 1 CTA/SM, grid=148. All 8 B chunk
// images loaded once into smem; H (hi only) double-buffered per chunk.
// Fused scattered epilogue (sem pre-zeroed).
// ---------------------------------------------------------------------------
__global__ void __launch_bounds__(256, 1)
k_sem_mma(const float* __restrict__ A4,
          const float* __restrict__ P,
          const __half* __restrict__ Bimg,
          const float* __restrict__ b2,
          const int* __restrict__ idx,
          const int* __restrict__ cnt,
          float* __restrict__ sem)
{
    extern __shared__ char smem[];
    const u32 sb = smem_u32(smem);
    const int tid = threadIdx.x;
    const int wid = tid >> 5;
    const int l   = tid & 31;
    const int wm = wid & 3;
    const int wn = wid >> 2;
    const int r = tid & 127;
    const int half = tid >> 7;
    const u32 qr = ((u32)r >> 3) & 3;
    const u32 hbase_off = (u32)(r * 144);

    // one-time: load ALL 8 B chunk images (8 x 1088 uint4)
    {
        const char* srcB = (const char*)(Bimg);
        u32 dstB = sb + SM_BALL;
        for (int e = tid; e < 8 * 1088; e += 256)
            cpasync16(dstB + e * 16, srcB + e * 16);
        cpasync_commit();
    }

    // tile offsets from cnt
    int offv[17];
    offv[0] = 0;
#pragma unroll
    for (int b = 0; b < 16; b++)
        offv[b + 1] = offv[b] + ((cnt[b] + 127) >> 7);
    const int total = offv[16];

    float* a_sm = (float*)(smem + SM_AS);
    cpasync_wait0();

    for (int w = blockIdx.x; w < total; w += NPERS) {
        int b = 0;
#pragma unroll
        for (int t = 0; t < 15; t++) if (w >= offv[b + 1]) b++;
        const int cntb = cnt[b];
        const int ibase = (w - offv[b]) << 7;

        // stage a[b] (sum of 4 partials)
        for (int i = tid; i < HID; i += 256) {
            float s = 0.f;
#pragma unroll
            for (int sc = 0; sc < 4; sc++)
                s += A4[(size_t)sc * BB * HID + b * HID + i];
            a_sm[i] = s;
        }

        const int ig = ibase + r;
        const int vrow = idx[b * VV + (ig < cntb ? ig : cntb - 1)];
        const float* __restrict__ prow = P + (size_t)vrow * HID + half * 32;

        float acc[2][9][4];
#pragma unroll
        for (int i = 0; i < 2; i++)
#pragma unroll
            for (int j = 0; j < 9; j++)
#pragma unroll
                for (int q = 0; q < 4; q++) acc[i][j][q] = 0.f;

        float4 pf[8];
#pragma unroll
        for (int q = 0; q < 8; q++) pf[q] = *(const float4*)(prow + 4 * q);
        __syncthreads();   // a_sm ready (also isolates from previous tile)

        // produce H(0) (hi plane only)
#pragma unroll
        for (int kb = 0; kb < 2; kb++) {
            float x[16];
#pragma unroll
            for (int q = 0; q < 4; q++) {
                float4 p4 = pf[kb * 4 + q];
                const float* ap = a_sm + half * 32 + kb * 16 + 4 * q;
                x[4*q+0] = fmaxf(p4.x + ap[0], 0.f);
                x[4*q+1] = fmaxf(p4.y + ap[1], 0.f);
                x[4*q+2] = fmaxf(p4.z + ap[2], 0.f);
                x[4*q+3] = fmaxf(p4.w + ap[3], 0.f);
            }
            u32 hw[8];
#pragma unroll
            for (int i = 0; i < 8; i++)
                hw[i] = h2u(__floats2half2_rn(x[2*i], x[2*i+1]));
            const u32 c0 = (u32)(half * 4 + kb * 2);
            const u32 off0 = hbase_off + ((c0 ^ qr) << 4);
            const u32 off1 = hbase_off + (((c0 + 1u) ^ qr) << 4);
            asm volatile("st.shared.v4.b32 [%0], {%1,%2,%3,%4};"
                :: "r"(sb + SM_H(0) + off0), "r"(hw[0]), "r"(hw[1]), "r"(hw[2]), "r"(hw[3]) : "memory");
            asm volatile("st.shared.v4.b32 [%0], {%1,%2,%3,%4};"
                :: "r"(sb + SM_H(0) + off1), "r"(hw[4]), "r"(hw[5]), "r"(hw[6]), "r"(hw[7]) : "memory");
        }

        int buf = 0;
        for (int ch = 0; ch < 8; ch++) {
            __syncthreads();   // H(ch) visible
            const int nb = buf ^ 1;
            if (ch < 7) {
                const float* ps = prow + (ch + 1) * 64;
#pragma unroll
                for (int q = 0; q < 8; q++) pf[q] = *(const float4*)(ps + 4 * q);
            }

            const u32 hH = sb + SM_H(buf);
            const u32 bB = sb + SM_BC(ch);
#pragma unroll
            for (int ks = 0; ks < 4; ks++) {
                u32 ah[2][4];
#pragma unroll
                for (int mt = 0; mt < 2; mt++) {
                    int ra = wm * 32 + mt * 16 + (l & 15);
                    u32 qa = ((u32)ra >> 3) & 3;
                    u32 chk = (((u32)(l >> 4) + 2u * ks) ^ qa) << 4;
                    ldm_x4(ah[mt], hH + (u32)(ra * 144) + chk);
                }
#pragma unroll
                for (int p = 0; p < 4; p++) {
                    int rb = wn * 72 + p * 16 + (l & 7) + ((l >> 4) & 1) * 8;
                    u32 chunkf = 2u * ks + ((u32)(l >> 3) & 1u);
                    u32 bb[4];
                    ldm_x4(bb, bB + (u32)(rb << 7) + ((chunkf ^ ((u32)rb & 7u)) << 4));
#pragma unroll
                    for (int mt = 0; mt < 2; mt++)
#pragma unroll
                        for (int t = 0; t < 2; t++)
                            mma_f16(acc[mt][p * 2 + t], ah[mt], &bb[2 * t]);
                }
                {
                    int rb2 = 64 + (l & 7);
                    u32 chunkf = 2u * ks + ((u32)(l >> 3) & 1u);
                    u32 s2[2];
                    ldm_x2(s2, bB + (u32)(rb2 << 7) + ((chunkf ^ ((u32)rb2 & 7u)) << 4));
#pragma unroll
                    for (int mt = 0; mt < 2; mt++)
                        mma_f16(acc[mt][8], ah[mt], s2);
                }
            }

            if (ch < 7) {
                // produce H(ch+1) into other buffer
#pragma unroll
                for (int kb = 0; kb < 2; kb++) {
                    float x[16];
#pragma unroll
                    for (int q = 0; q < 4; q++) {
                        float4 p4 = pf[kb * 4 + q];
                        const float* ap = a_sm + (ch + 1) * 64 + half * 32 + kb * 16 + 4 * q;
                        x[4*q+0] = fmaxf(p4.x + ap[0], 0.f);
                        x[4*q+1] = fmaxf(p4.y + ap[1], 0.f);
                        x[4*q+2] = fmaxf(p4.z + ap[2], 0.f);
                        x[4*q+3] = fmaxf(p4.w + ap[3], 0.f);
                    }
                    u32 hw[8];
#pragma unroll
                    for (int i = 0; i < 8; i++)
                        hw[i] = h2u(__floats2half2_rn(x[2*i], x[2*i+1]));
                    const u32 c0 = (u32)(half * 4 + kb * 2);
                    const u32 off0 = hbase_off + ((c0 ^ qr) << 4);
                    const u32 off1 = hbase_off + (((c0 + 1u) ^ qr) << 4);
                    asm volatile("st.shared.v4.b32 [%0], {%1,%2,%3,%4};"
                        :: "r"(sb + SM_H(nb) + off0), "r"(hw[0]), "r"(hw[1]), "r"(hw[2]), "r"(hw[3]) : "memory");
                    asm volatile("st.shared.v4.b32 [%0], {%1,%2,%3,%4};"
                        :: "r"(sb + SM_H(nb) + off1), "r"(hw[4]), "r"(hw[5]), "r"(hw[6]), "r"(hw[7]) : "memory");
                }
            }
            buf = nb;
        }

        // fused epilogue: bias + scattered store sem[b, col, idx[i]]
        const int g = l >> 2, tg = l & 3;
#pragma unroll
        for (int mt = 0; mt < 2; mt++) {
            const int i0 = ibase + wm * 32 + mt * 16 + g;
            const int i1 = i0 + 8;
            const bool ok0 = i0 < cntb, ok1 = i1 < cntb;
            const int v0 = ok0 ? idx[b * VV + i0] : 0;
            const int v1 = ok1 ? idx[b * VV + i1] : 0;
#pragma unroll
            for (int nt = 0; nt < 9; nt++) {
                const int cbase = wn * 72 + nt * 8 + tg * 2;
#pragma unroll
                for (int q = 0; q < 2; q++) {
                    const int col = cbase + q;
                    if (col >= CC) continue;
                    const float bias = __ldg(&b2[col]);
                    if (ok0) sem[((size_t)b * CC + col) * VV + v0] = acc[mt][nt][q] + bias;
                    if (ok1) sem[((size_t)b * CC + col) * VV + v1] = acc[mt][nt][2 + q] + bias;
                }
            }
        }
    }
}

// ---------------------------------------------------------------------------
extern "C" void kernel_launch(void* const* d_in, const int* in_sizes, int n_in,
                              void* d_out, int out_size)
{
    const float* features  = (const float*)d_in[0];
    const float* W_contact = (const float*)d_in[3];
    const float* b_contact = (const float*)d_in[4];
    const float* Wv        = (const float*)d_in[7];
    const float* Wo        = (const float*)d_in[8];
    const float* W_cls     = (const float*)d_in[9];
    const float* b_cls     = (const float*)d_in[10];
    const float* pos_emb   = (const float*)d_in[11];
    const float* W_ft1     = (const float*)d_in[12];
    const float* b_ft1     = (const float*)d_in[13];
    const float* W_ft2     = (const float*)d_in[14];
    const float* b_ft2     = (const float*)d_in[15];

    float* out  = (float*)d_out;
    float* cont = out;                  // [16, 6890]
    float* sem  = out + BB * VV;        // [16, 133, 6890]

    float *part, *tmp, *att, *a, *Pbuf;
    int *idx, *cnt;
    __half* Bimg;
    __nv_bfloat16* B1img;
    cudaGetSymbolAddress((void**)&part,  g_part);
    cudaGetSymbolAddress((void**)&tmp,   g_tmp);
    cudaGetSymbolAddress((void**)&att,   g_att);
    cudaGetSymbolAddress((void**)&a,     g_a);
    cudaGetSymbolAddress((void**)&Pbuf,  g_P);
    cudaGetSymbolAddress((void**)&idx,   g_idx);
    cudaGetSymbolAddress((void**)&cnt,   g_cnt);
    cudaGetSymbolAddress((void**)&Bimg,  g_Bimg);
    cudaGetSymbolAddress((void**)&B1img, g_B1img);

    cudaFuncSetAttribute(k_sem_mma, cudaFuncAttributeMaxDynamicSharedMemorySize, SM_TOT);
    cudaFuncSetAttribute(k_P_mma,  cudaFuncAttributeMaxDynamicSharedMemorySize, SMP_TOT);

    // fused zero + weight-image prep
    k_misc<<<528, 256>>>(W_ft2, Bimg, W_ft1, B1img,
                         (float4*)sem, (BB * CC * VV) / 4);

    // P = pos_emb @ W_ft1[1024:] on HMMA bf16 3-term (N=64/CTA)
    dim3 gP((VV + 127) / 128, 8);
    k_P_mma<<<gP, 256, SMP_TOT>>>(pos_emb, B1img, Pbuf);

    // att chain, 4-way K-split partials
    k_skinny<<<dim3(32, 4), 512>>>(features, W_contact, b_contact, part, DF, DD, 1);
    k_skinny<<<dim3(32, 4), 512>>>(part, Wv, nullptr, tmp, DD, DD, 4);
    k_skinny<<<dim3(32, 4), 512>>>(tmp,  Wo, nullptr, att, DD, DD, 4);

    // cont + a (consume 4 partials)
    k_cont2<<<(VV + 31) / 32, 256>>>(att, W_cls, b_cls, cont);
    k_skinny<<<dim3(16, 4), 512>>>(att, W_ft1, b_ft1, a, DD, HID, 4);

    // compaction
    k_compact<<<BB, 1024>>>(cont, idx, cnt);

    // persistent 1-term main GEMM, all-B-resident, fused scattered epilogue
    k_sem_mma<<<NPERS, 256, SM_TOT>>>(a, Pbuf, Bimg, b_ft2, idx, cnt, sem);
}

// round 12
// speedup vs baseline: 8.1834x; 1.0641x over previous
#include <cuda_runtime.h>
#include <cuda_fp16.h>
#include <cuda_bf16.h>
#include <math.h>

// DECO decomposed (len-1 softmax == 1 → Wq/Wk/W_scene dead):
//   att  = (feat @ W_contact + b_c) @ Wv @ Wo            [16,1024]
//   cont = sigmoid(att @ W_cls + b_cls)                  [16,6890]
//   a    = att @ W_ft1[:1024] + b_ft1                    [16,512]
//   P    = pos_emb @ W_ft1[1024:]   (HMMA bf16 3-term)
//   sem[b,c,v] = mask * (relu(a[b]+P[v]) @ W_ft2 + b2)[c]
// R12: entire front-end chain fused into ONE persistent kernel (grid=148)
// with device-wide spin barriers. Main GEMM: fp16 1-term, persistent,
// all-B-resident smem, fused scattered epilogue (unchanged from R11).

#define BB   16
#define DF   1536
#define DD   1024
#define VV   6890
#define PDIM 256
#define HID  512
#define CC   133
#define NC   144
#define BROWS 136
#define NPERS 148

typedef unsigned long long u64;
typedef unsigned int u32;

__device__ float g_part[4 * BB * DD];
__device__ float g_tmp [4 * BB * DD];
__device__ float g_att [4 * BB * DD];
__device__ float g_a   [4 * BB * HID];
__device__ float g_P   [VV * HID];
__device__ int   g_idx [BB * VV];
__device__ int   g_cnt [BB];
__device__ __align__(16) __half g_Bimg[8 * BROWS * 64];
__device__ __align__(16) __nv_bfloat16 g_B1img[2 * 4 * 512 * 64];
__device__ int   g_bar_arrive;
__device__ unsigned int g_bar_gen;

__device__ __forceinline__ u64 pk2(float lo, float hi) {
    u64 r; asm("mov.b64 %0, {%1, %2};" : "=l"(r) : "f"(lo), "f"(hi)); return r;
}
__device__ __forceinline__ void upk2(u64 v, float& lo, float& hi) {
    asm("mov.b64 {%0, %1}, %2;" : "=f"(lo), "=f"(hi) : "l"(v));
}
__device__ __forceinline__ u64 ffma2(u64 a, u64 b, u64 c) {
    u64 d; asm("fma.rn.f32x2 %0, %1, %2, %3;" : "=l"(d) : "l"(a), "l"(b), "l"(c));
    return d;
}
__device__ __forceinline__ u32 smem_u32(const void* p) {
    u32 a; asm("{ .reg .u64 t; cvta.to.shared.u64 t, %1; cvt.u32.u64 %0, t; }"
               : "=r"(a) : "l"(p));
    return a;
}
__device__ __forceinline__ void ldm_x4(u32* r, u32 addr) {
    asm volatile("ldmatrix.sync.aligned.m8n8.x4.shared.b16 {%0,%1,%2,%3}, [%4];"
        : "=r"(r[0]), "=r"(r[1]), "=r"(r[2]), "=r"(r[3]) : "r"(addr));
}
__device__ __forceinline__ void ldm_x2(u32* r, u32 addr) {
    asm volatile("ldmatrix.sync.aligned.m8n8.x2.shared.b16 {%0,%1}, [%2];"
        : "=r"(r[0]), "=r"(r[1]) : "r"(addr));
}
__device__ __forceinline__ void mma_f16(float* d, const u32* a, const u32* b) {
    asm volatile("mma.sync.aligned.m16n8k16.row.col.f32.f16.f16.f32 "
        "{%0,%1,%2,%3}, {%4,%5,%6,%7}, {%8,%9}, {%0,%1,%2,%3};"
        : "+f"(d[0]), "+f"(d[1]), "+f"(d[2]), "+f"(d[3])
        : "r"(a[0]), "r"(a[1]), "r"(a[2]), "r"(a[3]), "r"(b[0]), "r"(b[1]));
}
__device__ __forceinline__ void mma_bf16(float* d, const u32* a, const u32* b) {
    asm volatile("mma.sync.aligned.m16n8k16.row.col.f32.bf16.bf16.f32 "
        "{%0,%1,%2,%3}, {%4,%5,%6,%7}, {%8,%9}, {%0,%1,%2,%3};"
        : "+f"(d[0]), "+f"(d[1]), "+f"(d[2]), "+f"(d[3])
        : "r"(a[0]), "r"(a[1]), "r"(a[2]), "r"(a[3]), "r"(b[0]), "r"(b[1]));
}
__device__ __forceinline__ u32 h2u(__half2 h) {
    u32 r; asm("mov.b32 %0, %1;" : "=r"(r) : "r"(*(u32*)&h)); return r;
}
__device__ __forceinline__ void cpasync16(u32 dst, const void* src) {
    asm volatile("cp.async.cg.shared.global [%0], [%1], 16;"
                 :: "r"(dst), "l"(src) : "memory");
}
__device__ __forceinline__ void cpasync_commit() {
    asm volatile("cp.async.commit_group;" ::: "memory");
}
__device__ __forceinline__ void cpasync_wait0() {
    asm volatile("cp.async.wait_group 0;" ::: "memory");
}

// device-wide barrier: grid=NPERS co-resident CTAs, generation counter
__device__ __forceinline__ void grid_bar() {
    __syncthreads();
    if (threadIdx.x == 0) {
        __threadfence();
        unsigned gen = atomicAdd(&g_bar_gen, 0u);
        int a = atomicAdd(&g_bar_arrive, 1);
        if (a == NPERS - 1) {
            g_bar_arrive = 0;
            __threadfence();
            atomicAdd(&g_bar_gen, 1u);
        } else {
            while (atomicAdd(&g_bar_gen, 0u) == gen) {}
        }
        __threadfence();
    }
    __syncthreads();
}

// k_sem smem layout (bytes)
#define SM_AS     0
#define SM_H(bf)  (2048 + (bf) * 18432)
#define SM_BALL   38912
#define SM_BC(ch) (SM_BALL + (ch) * 17408)
#define SM_TOT    178176
// k_P_mma smem layout (bytes)
#define SMP_HH 0
#define SMP_HL 16384
#define SMP_BH 32768
#define SMP_BL 40960
#define SMP_TOT 49152
// k_chain smem: in_s (128*18 f) + red (16*1024 f)
#define SMC_TOT ((128 * 18 + 16 * 1024) * 4)

// ---------------------------------------------------------------------------
// Fused misc: [0,8) prepW fp16 W_ft2 images; [8,16) prepW1 bf16 W_ft1 hi/lo;
// [16,528) zero sem.
// ---------------------------------------------------------------------------
__global__ void __launch_bounds__(256)
k_misc(const float* __restrict__ W2, __half* __restrict__ Bimg,
       const float* __restrict__ W1, __nv_bfloat16* __restrict__ B1,
       float4* __restrict__ zp, int n4)
{
    const int bx = blockIdx.x;
    const int tid = threadIdx.x;
    if (bx < 8) {
        const int img = bx;
        for (int e = tid; e < BROWS * 64; e += 256) {
            int n = e >> 6, k = e & 63;
            float w = (n < CC) ? W2[(size_t)(img * 64 + k) * CC + n] : 0.f;
            int off = (n << 6) + (((k >> 3) ^ (n & 7)) << 3) + (k & 7);
            Bimg[(size_t)img * (BROWS * 64) + off] = __float2half_rn(w);
        }
    } else if (bx < 16) {
        const int blk = bx - 8;
        const int plane = blk >> 2, ch = blk & 3;
        for (int e = tid; e < 512 * 64; e += 256) {
            int n = e >> 6, k = e & 63;
            float w = W1[(size_t)(DD + ch * 64 + k) * HID + n];
            __nv_bfloat16 h = __float2bfloat16(w);
            __nv_bfloat16 val = plane ? __float2bfloat16(w - __bfloat162float(h)) : h;
            int off = (n << 6) + (((k >> 3) ^ (n & 7)) << 3) + (k & 7);
            B1[(size_t)blk * (512 * 64) + off] = val;
        }
    } else {
        const int zb = bx - 16;
        for (int i = zb * 256 + tid; i < n4; i += 512 * 256)
            zp[i] = make_float4(0.f, 0.f, 0.f, 0.f);
    }
}

// ---------------------------------------------------------------------------
// Device fn: split-K skinny GEMM vblock. 512 thr = 32 cols x 16 K-slices.
// out[ky][16][N] partial over k range [ky*K/4, ...). Bias only in ky==0.
// ---------------------------------------------------------------------------
__device__ void skinny_dev(const float* __restrict__ in,
                           const float* __restrict__ W,
                           const float* __restrict__ bias,
                           float* __restrict__ out,
                           int K, int N, int nsum, int colb, int ky,
                           float* in_s, float* red)
{
    const int tid  = threadIdx.x;
    const int col  = tid & 31;
    const int slc  = tid >> 5;
    const int colg = colb * 32 + col;
    const int colc = colg < N ? colg : N - 1;
    const int kspan = K >> 2;
    const int kbase = ky * kspan;

    u64 acc2[8];
#pragma unroll
    for (int m = 0; m < 8; m++) acc2[m] = 0ull;

    for (int k0 = kbase; k0 < kbase + kspan; k0 += 128) {
        __syncthreads();
#pragma unroll
        for (int i = 0; i < 4; i++) {
            int e = tid + 512 * i;
            int b = e >> 7, k = e & 127;
            float s = 0.f;
            for (int sc = 0; sc < nsum; sc++)
                s += in[(size_t)sc * BB * K + b * K + k0 + k];
            in_s[k * 18 + b] = s;
        }
        __syncthreads();
#pragma unroll
        for (int kk = 0; kk < 8; kk++) {
            int k = slc * 8 + kk;
            float w = W[(size_t)(k0 + k) * N + colc];
            u64 w2 = pk2(w, w);
            const u64* ip = (const u64*)&in_s[k * 18];
#pragma unroll
            for (int m = 0; m < 8; m++)
                acc2[m] = ffma2(ip[m], w2, acc2[m]);
        }
    }
    float* rp = &red[slc * 512 + col * 16];
#pragma unroll
    for (int m = 0; m < 8; m++) {
        float lo, hi; upk2(acc2[m], lo, hi);
        rp[2 * m] = lo; rp[2 * m + 1] = hi;
    }
    __syncthreads();
    {
        int c = tid >> 4, b = tid & 15;   // 512 thr cover 32 cols x 16 b
        float s = 0.f;
#pragma unroll
        for (int sl = 0; sl < 16; sl++) s += red[sl * 512 + c * 16 + b];
        int cg = colb * 32 + c;
        if (cg < N) {
            float bb = (bias && ky == 0) ? bias[cg] : 0.f;
            out[(size_t)ky * BB * N + b * N + cg] = s + bb;
        }
    }
    __syncthreads();
}

// ---------------------------------------------------------------------------
// Device fn: cont vblock (64 cols). 512 thr = 32 col-pairs x 16 K-slices.
// cont = sigmoid(sum4(att) @ W_cls + b_cls).
// ---------------------------------------------------------------------------
__device__ void cont_dev(const float* __restrict__ att,
                         const float* __restrict__ Wc,
                         const float* __restrict__ bc,
                         float* __restrict__ out, int vb,
                         float* in_s, float* red)
{
    const int tid = threadIdx.x;
    const int cp  = tid & 31;
    const int slc = tid >> 5;
    const int col0 = vb * 64 + 2 * cp;
    const int colc = col0 <= VV - 2 ? col0 : VV - 2;

    u64 acc[2][8];
#pragma unroll
    for (int j = 0; j < 2; j++)
#pragma unroll
        for (int m = 0; m < 8; m++) acc[j][m] = 0ull;

    for (int k0 = 0; k0 < DD; k0 += 128) {
        __syncthreads();
#pragma unroll
        for (int i = 0; i < 4; i++) {
            int e = tid + 512 * i;
            int b = e >> 7, k = e & 127;
            float s = 0.f;
#pragma unroll
            for (int sc = 0; sc < 4; sc++)
                s += att[(size_t)sc * BB * DD + b * DD + k0 + k];
            in_s[k * 18 + b] = s;
        }
        __syncthreads();
#pragma unroll
        for (int kk = 0; kk < 8; kk++) {
            int k = slc * 8 + kk;
            float2 w = *(const float2*)&Wc[(size_t)(k0 + k) * VV + colc];
            u64 w0 = pk2(w.x, w.x), w1 = pk2(w.y, w.y);
            const u64* ip = (const u64*)&in_s[k * 18];
#pragma unroll
            for (int m = 0; m < 8; m++) {
                acc[0][m] = ffma2(ip[m], w0, acc[0][m]);
                acc[1][m] = ffma2(ip[m], w1, acc[1][m]);
            }
        }
    }
#pragma unroll
    for (int j = 0; j < 2; j++) {
        float* rp = &red[slc * 1024 + (2 * cp + j) * 16];
#pragma unroll
        for (int m = 0; m < 8; m++) {
            float lo, hi; upk2(acc[j][m], lo, hi);
            rp[2 * m] = lo; rp[2 * m + 1] = hi;
        }
    }
    __syncthreads();
    for (int o = tid; o < 1024; o += 512) {
        int c = o >> 4, b = o & 15;
        float s = 0.f;
#pragma unroll
        for (int sl = 0; sl < 16; sl++) s += red[sl * 1024 + c * 16 + b];
        int cg = vb * 64 + c;
        if (cg < VV)
            out[b * VV + cg] = 1.f / (1.f + expf(-(s + bc[cg])));
    }
    __syncthreads();
}

// ---------------------------------------------------------------------------
// Device fn: order-preserving compaction for one batch b (512 thr, 16 warps).
// ---------------------------------------------------------------------------
__device__ void compact_dev(const float* __restrict__ cont,
                            int* __restrict__ idx, int* __restrict__ cnt,
                            int b)
{
    const int tid = threadIdx.x;
    const int lane = tid & 31, wrp = tid >> 5;
    __shared__ int wexc[16];
    __shared__ int s_base, s_tot;
    if (tid == 0) s_base = 0;
    __syncthreads();
    for (int v0 = 0; v0 < VV; v0 += 512) {
        int v = v0 + tid;
        int m = (v < VV) && (cont[b * VV + v] > 0.5f);
        unsigned bal = __ballot_sync(0xffffffffu, m);
        int wsum = __popc(bal);
        int pw = __popc(bal & ((1u << lane) - 1u));
        if (lane == 0) wexc[wrp] = wsum;
        __syncthreads();
        if (tid < 16) {
            int sv = wexc[tid];
            int e = sv;
#pragma unroll
            for (int d = 1; d < 16; d <<= 1) {
                int t = __shfl_up_sync(0xffffu, e, d);
                if (tid >= d) e += t;
            }
            wexc[tid] = e - sv;
            if (tid == 15) s_tot = e;
        }
        __syncthreads();
        int pos = s_base + wexc[wrp] + pw;
        if (v < VV && m) idx[b * VV + pos] = v;
        __syncthreads();
        if (tid == 0) s_base += s_tot;
        __syncthreads();
    }
    if (tid == 0) cnt[b] = s_base;
}

// ---------------------------------------------------------------------------
// FUSED front-end chain: persistent grid=148, device-wide barriers.
// s1 part (128 vb) | s2 tmp (128) | s3 att (128) | s4 cont (108) |
// s5 a (64 vb) + compact (16 vb).
// ---------------------------------------------------------------------------
__global__ void __launch_bounds__(512, 1)
k_chain(const float* __restrict__ features,
        const float* __restrict__ W_contact, const float* __restrict__ b_contact,
        const float* __restrict__ Wv, const float* __restrict__ Wo,
        const float* __restrict__ W_cls, const float* __restrict__ b_cls,
        const float* __restrict__ W_ft1, const float* __restrict__ b_ft1,
        float* __restrict__ part, float* __restrict__ tmp,
        float* __restrict__ att, float* __restrict__ a,
        float* __restrict__ cont, int* __restrict__ idx, int* __restrict__ cnt)
{
    extern __shared__ float smc[];
    float* in_s = smc;                 // 128*18
    float* red  = smc + 128 * 18;      // 16*1024
    const int bid = blockIdx.x;

    if (bid < 128)
        skinny_dev(features, W_contact, b_contact, part, DF, DD, 1,
                   bid & 31, bid >> 5, in_s, red);
    grid_bar();
    if (bid < 128)
        skinny_dev(part, Wv, nullptr, tmp, DD, DD, 4, bid & 31, bid >> 5, in_s, red);
    grid_bar();
    if (bid < 128)
        skinny_dev(tmp, Wo, nullptr, att, DD, DD, 4, bid & 31, bid >> 5, in_s, red);
    grid_bar();
    if (bid < 108)
        cont_dev(att, W_cls, b_cls, cont, bid, in_s, red);
    grid_bar();
    if (bid < 64)
        skinny_dev(att, W_ft1, b_ft1, a, DD, HID, 4, bid & 15, bid >> 4, in_s, red);
    else if (bid < 80)
        compact_dev(cont, idx, cnt, bid - 64);
}

// ---------------------------------------------------------------------------
// P = pos_emb @ W_ft1[1024:] via bf16 HMMA 3-term. N=64/CTA, grid (54, 8).
// ---------------------------------------------------------------------------
__global__ void __launch_bounds__(256, 2)
k_P_mma(const float* __restrict__ pos, const __nv_bfloat16* __restrict__ B1,
        float* __restrict__ Pout)
{
    extern __shared__ char smem[];
    const u32 sb = smem_u32(smem);
    const int tid = threadIdx.x;
    const int wid = tid >> 5;
    const int l   = tid & 31;
    const int wm = wid & 3;
    const int wn = wid >> 2;
    const int vbase = blockIdx.x * 128;
    const int hbase = blockIdx.y * 64;

    const int r = tid & 127;
    const int half = tid >> 7;
    const int v = vbase + r;
    const int vc = v < VV ? v : VV - 1;
    const float* __restrict__ prow = pos + (size_t)vc * PDIM + half * 32;

    float acc[2][4][4];
#pragma unroll
    for (int i = 0; i < 2; i++)
#pragma unroll
        for (int j = 0; j < 4; j++)
#pragma unroll
            for (int q = 0; q < 4; q++) acc[i][j][q] = 0.f;

    for (int ch = 0; ch < 4; ch++) {
        float4 pf[8];
#pragma unroll
        for (int q = 0; q < 8; q++)
            pf[q] = *(const float4*)(prow + ch * 64 + 4 * q);
#pragma unroll
        for (int kb = 0; kb < 2; kb++) {
            float x[16];
#pragma unroll
            for (int q = 0; q < 4; q++) {
                float4 p4 = pf[kb * 4 + q];
                x[4*q+0] = p4.x; x[4*q+1] = p4.y; x[4*q+2] = p4.z; x[4*q+3] = p4.w;
            }
            u32 hw[8], lw[8];
#pragma unroll
            for (int i = 0; i < 8; i++) {
                __nv_bfloat16 h0 = __float2bfloat16(x[2*i]);
                __nv_bfloat16 h1 = __float2bfloat16(x[2*i+1]);
                __nv_bfloat16 l0 = __float2bfloat16(x[2*i]   - __bfloat162float(h0));
                __nv_bfloat16 l1 = __float2bfloat16(x[2*i+1] - __bfloat162float(h1));
                hw[i] = (u32)__bfloat16_as_ushort(h0) | ((u32)__bfloat16_as_ushort(h1) << 16);
                lw[i] = (u32)__bfloat16_as_ushort(l0) | ((u32)__bfloat16_as_ushort(l1) << 16);
            }
            const u32 c0 = (u32)(half * 4 + kb * 2);
            const u32 q7 = (u32)r & 7u;
            const u32 off0 = (u32)(r << 7) + ((c0 ^ q7) << 4);
            const u32 off1 = (u32)(r << 7) + (((c0 + 1u) ^ q7) << 4);
            asm volatile("st.shared.v4.b32 [%0], {%1,%2,%3,%4};"
                :: "r"(sb + SMP_HH + off0), "r"(hw[0]), "r"(hw[1]), "r"(hw[2]), "r"(hw[3]) : "memory");
            asm volatile("st.shared.v4.b32 [%0], {%1,%2,%3,%4};"
                :: "r"(sb + SMP_HH + off1), "r"(hw[4]), "r"(hw[5]), "r"(hw[6]), "r"(hw[7]) : "memory");
            asm volatile("st.shared.v4.b32 [%0], {%1,%2,%3,%4};"
                :: "r"(sb + SMP_HL + off0), "r"(lw[0]), "r"(lw[1]), "r"(lw[2]), "r"(lw[3]) : "memory");
            asm volatile("st.shared.v4.b32 [%0], {%1,%2,%3,%4};"
                :: "r"(sb + SMP_HL + off1), "r"(lw[4]), "r"(lw[5]), "r"(lw[6]), "r"(lw[7]) : "memory");
        }
        {
            const uint4* sH = (const uint4*)(B1 + (size_t)ch * 32768 + (size_t)hbase * 64);
            const uint4* sL = (const uint4*)(B1 + (size_t)(4 + ch) * 32768 + (size_t)hbase * 64);
            uint4* dH = (uint4*)(smem + SMP_BH);
            uint4* dL = (uint4*)(smem + SMP_BL);
#pragma unroll
            for (int i = 0; i < 2; i++) {
                int e = tid + 256 * i;
                dH[e] = sH[e]; dL[e] = sL[e];
            }
        }
        __syncthreads();
#pragma unroll
        for (int ks = 0; ks < 4; ks++) {
            u32 ah[2][4], al[2][4];
#pragma unroll
            for (int mt = 0; mt < 2; mt++) {
                int ra = wm * 32 + mt * 16 + (l & 15);
                u32 c = (u32)(l >> 4) + 2u * ks;
                u32 sw = ((c ^ ((u32)ra & 7u)) << 4);
                ldm_x4(ah[mt], sb + SMP_HH + (u32)(ra << 7) + sw);
                ldm_x4(al[mt], sb + SMP_HL + (u32)(ra << 7) + sw);
            }
#pragma unroll
            for (int p = 0; p < 2; p++) {
                int rb = wn * 32 + p * 16 + (l & 7) + ((l >> 4) & 1) * 8;
                u32 cf = 2u * ks + ((u32)(l >> 3) & 1u);
                u32 swb = ((cf ^ ((u32)rb & 7u)) << 4);
                u32 bh[4], bl[4];
                ldm_x4(bh, sb + SMP_BH + (u32)(rb << 7) + swb);
                ldm_x4(bl, sb + SMP_BL + (u32)(rb << 7) + swb);
#pragma unroll
                for (int mt = 0; mt < 2; mt++)
#pragma unroll
                    for (int t = 0; t < 2; t++) {
                        float* d = acc[mt][p * 2 + t];
                        mma_bf16(d, ah[mt], &bh[2 * t]);
                        mma_bf16(d, ah[mt], &bl[2 * t]);
                        mma_bf16(d, al[mt], &bh[2 * t]);
                    }
            }
        }
        __syncthreads();
    }

    const int g = l >> 2, tg = l & 3;
#pragma unroll
    for (int mt = 0; mt < 2; mt++) {
        const int i0 = vbase + wm * 32 + mt * 16 + g;
        const int i1 = i0 + 8;
#pragma unroll
        for (int nt = 0; nt < 4; nt++) {
            const int col = hbase + wn * 32 + nt * 8 + tg * 2;
            if (i0 < VV)
                *(float2*)&Pout[(size_t)i0 * HID + col]
                    = make_float2(acc[mt][nt][0], acc[mt][nt][1]);
            if (i1 < VV)
                *(float2*)&Pout[(size_t)i1 * HID + col]
                    = make_float2(acc[mt][nt][2], acc[mt][nt][3]);
        }
    }
}

// ---------------------------------------------------------------------------
// PERSISTENT main GEMM, 1-term fp16, all B chunks smem-resident,
// fused scattered epilogue (sem pre-zeroed). Unchanged from R11.
// ---------------------------------------------------------------------------
__global__ void __launch_bounds__(256, 1)
k_sem_mma(const float* __restrict__ A4,
          const float* __restrict__ P,
          const __half* __restrict__ Bimg,
          const float* __restrict__ b2,
          const int* __restrict__ idx,
          const int* __restrict__ cnt,
          float* __restrict__ sem)
{
    extern __shared__ char smem[];
    const u32 sb = smem_u32(smem);
    const int tid = threadIdx.x;
    const int wid = tid >> 5;
    const int l   = tid & 31;
    const int wm = wid & 3;
    const int wn = wid >> 2;
    const int r = tid & 127;
    const int half = tid >> 7;
    const u32 qr = ((u32)r >> 3) & 3;
    const u32 hbase_off = (u32)(r * 144);

    {
        const char* srcB = (const char*)(Bimg);
        u32 dstB = sb + SM_BALL;
        for (int e = tid; e < 8 * 1088; e += 256)
            cpasync16(dstB + e * 16, srcB + e * 16);
        cpasync_commit();
    }

    int offv[17];
    offv[0] = 0;
#pragma unroll
    for (int b = 0; b < 16; b++)
        offv[b + 1] = offv[b] + ((cnt[b] + 127) >> 7);
    const int total = offv[16];

    float* a_sm = (float*)(smem + SM_AS);
    cpasync_wait0();

    for (int w = blockIdx.x; w < total; w += NPERS) {
        int b = 0;
#pragma unroll
        for (int t = 0; t < 15; t++) if (w >= offv[b + 1]) b++;
        const int cntb = cnt[b];
        const int ibase = (w - offv[b]) << 7;

        for (int i = tid; i < HID; i += 256) {
            float s = 0.f;
#pragma unroll
            for (int sc = 0; sc < 4; sc++)
                s += A4[(size_t)sc * BB * HID + b * HID + i];
            a_sm[i] = s;
        }

        const int ig = ibase + r;
        const int vrow = idx[b * VV + (ig < cntb ? ig : cntb - 1)];
        const float* __restrict__ prow = P + (size_t)vrow * HID + half * 32;

        float acc[2][9][4];
#pragma unroll
        for (int i = 0; i < 2; i++)
#pragma unroll
            for (int j = 0; j < 9; j++)
#pragma unroll
                for (int q = 0; q < 4; q++) acc[i][j][q] = 0.f;

        float4 pf[8];
#pragma unroll
        for (int q = 0; q < 8; q++) pf[q] = *(const float4*)(prow + 4 * q);
        __syncthreads();

#pragma unroll
        for (int kb = 0; kb < 2; kb++) {
            float x[16];
#pragma unroll
            for (int q = 0; q < 4; q++) {
                float4 p4 = pf[kb * 4 + q];
                const float* ap = a_sm + half * 32 + kb * 16 + 4 * q;
                x[4*q+0] = fmaxf(p4.x + ap[0], 0.f);
                x[4*q+1] = fmaxf(p4.y + ap[1], 0.f);
                x[4*q+2] = fmaxf(p4.z + ap[2], 0.f);
                x[4*q+3] = fmaxf(p4.w + ap[3], 0.f);
            }
            u32 hw[8];
#pragma unroll
            for (int i = 0; i < 8; i++)
                hw[i] = h2u(__floats2half2_rn(x[2*i], x[2*i+1]));
            const u32 c0 = (u32)(half * 4 + kb * 2);
            const u32 off0 = hbase_off + ((c0 ^ qr) << 4);
            const u32 off1 = hbase_off + (((c0 + 1u) ^ qr) << 4);
            asm volatile("st.shared.v4.b32 [%0], {%1,%2,%3,%4};"
                :: "r"(sb + SM_H(0) + off0), "r"(hw[0]), "r"(hw[1]), "r"(hw[2]), "r"(hw[3]) : "memory");
            asm volatile("st.shared.v4.b32 [%0], {%1,%2,%3,%4};"
                :: "r"(sb + SM_H(0) + off1), "r"(hw[4]), "r"(hw[5]), "r"(hw[6]), "r"(hw[7]) : "memory");
        }

        int buf = 0;
        for (int ch = 0; ch < 8; ch++) {
            __syncthreads();
            const int nb = buf ^ 1;
            if (ch < 7) {
                const float* ps = prow + (ch + 1) * 64;
#pragma unroll
                for (int q = 0; q < 8; q++) pf[q] = *(const float4*)(ps + 4 * q);
            }

            const u32 hH = sb + SM_H(buf);
            const u32 bB = sb + SM_BC(ch);
#pragma unroll
            for (int ks = 0; ks < 4; ks++) {
                u32 ah[2][4];
#pragma unroll
                for (int mt = 0; mt < 2; mt++) {
                    int ra = wm * 32 + mt * 16 + (l & 15);
                    u32 qa = ((u32)ra >> 3) & 3;
                    u32 chk = (((u32)(l >> 4) + 2u * ks) ^ qa) << 4;
                    ldm_x4(ah[mt], hH + (u32)(ra * 144) + chk);
                }
#pragma unroll
                for (int p = 0; p < 4; p++) {
                    int rb = wn * 72 + p * 16 + (l & 7) + ((l >> 4) & 1) * 8;
                    u32 chunkf = 2u * ks + ((u32)(l >> 3) & 1u);
                    u32 bb[4];
                    ldm_x4(bb, bB + (u32)(rb << 7) + ((chunkf ^ ((u32)rb & 7u)) << 4));
#pragma unroll
                    for (int mt = 0; mt < 2; mt++)
#pragma unroll
                        for (int t = 0; t < 2; t++)
                            mma_f16(acc[mt][p * 2 + t], ah[mt], &bb[2 * t]);
                }
                {
                    int rb2 = 64 + (l & 7);
                    u32 chunkf = 2u * ks + ((u32)(l >> 3) & 1u);
                    u32 s2[2];
                    ldm_x2(s2, bB + (u32)(rb2 << 7) + ((chunkf ^ ((u32)rb2 & 7u)) << 4));
#pragma unroll
                    for (int mt = 0; mt < 2; mt++)
                        mma_f16(acc[mt][8], ah[mt], s2);
                }
            }

            if (ch < 7) {
#pragma unroll
                for (int kb = 0; kb < 2; kb++) {
                    float x[16];
#pragma unroll
                    for (int q = 0; q < 4; q++) {
                        float4 p4 = pf[kb * 4 + q];
                        const float* ap = a_sm + (ch + 1) * 64 + half * 32 + kb * 16 + 4 * q;
                        x[4*q+0] = fmaxf(p4.x + ap[0], 0.f);
                        x[4*q+1] = fmaxf(p4.y + ap[1], 0.f);
                        x[4*q+2] = fmaxf(p4.z + ap[2], 0.f);
                        x[4*q+3] = fmaxf(p4.w + ap[3], 0.f);
                    }
                    u32 hw[8];
#pragma unroll
                    for (int i = 0; i < 8; i++)
                        hw[i] = h2u(__floats2half2_rn(x[2*i], x[2*i+1]));
                    const u32 c0 = (u32)(half * 4 + kb * 2);
                    const u32 off0 = hbase_off + ((c0 ^ qr) << 4);
                    const u32 off1 = hbase_off + (((c0 + 1u) ^ qr) << 4);
                    asm volatile("st.shared.v4.b32 [%0], {%1,%2,%3,%4};"
                        :: "r"(sb + SM_H(nb) + off0), "r"(hw[0]), "r"(hw[1]), "r"(hw[2]), "r"(hw[3]) : "memory");
                    asm volatile("st.shared.v4.b32 [%0], {%1,%2,%3,%4};"
                        :: "r"(sb + SM_H(nb) + off1), "r"(hw[4]), "r"(hw[5]), "r"(hw[6]), "r"(hw[7]) : "memory");
                }
            }
            buf = nb;
        }

        const int g = l >> 2, tg = l & 3;
#pragma unroll
        for (int mt = 0; mt < 2; mt++) {
            const int i0 = ibase + wm * 32 + mt * 16 + g;
            const int i1 = i0 + 8;
            const bool ok0 = i0 < cntb, ok1 = i1 < cntb;
            const int v0 = ok0 ? idx[b * VV + i0] : 0;
            const int v1 = ok1 ? idx[b * VV + i1] : 0;
#pragma unroll
            for (int nt = 0; nt < 9; nt++) {
                const int cbase = wn * 72 + nt * 8 + tg * 2;
#pragma unroll
                for (int q = 0; q < 2; q++) {
                    const int col = cbase + q;
                    if (col >= CC) continue;
                    const float bias = __ldg(&b2[col]);
                    if (ok0) sem[((size_t)b * CC + col) * VV + v0] = acc[mt][nt][q] + bias;
                    if (ok1) sem[((size_t)b * CC + col) * VV + v1] = acc[mt][nt][2 + q] + bias;
                }
            }
        }
    }
}

// ---------------------------------------------------------------------------
extern "C" void kernel_launch(void* const* d_in, const int* in_sizes, int n_in,
                              void* d_out, int out_size)
{
    const float* features  = (const float*)d_in[0];
    const float* W_contact = (const float*)d_in[3];
    const float* b_contact = (const float*)d_in[4];
    const float* Wv        = (const float*)d_in[7];
    const float* Wo        = (const float*)d_in[8];
    const float* W_cls     = (const float*)d_in[9];
    const float* b_cls     = (const float*)d_in[10];
    const float* pos_emb   = (const float*)d_in[11];
    const float* W_ft1     = (const float*)d_in[12];
    const float* b_ft1     = (const float*)d_in[13];
    const float* W_ft2     = (const float*)d_in[14];
    const float* b_ft2     = (const float*)d_in[15];

    float* out  = (float*)d_out;
    float* cont = out;                  // [16, 6890]
    float* sem  = out + BB * VV;        // [16, 133, 6890]

    float *part, *tmp, *att, *a, *Pbuf;
    int *idx, *cnt;
    __half* Bimg;
    __nv_bfloat16* B1img;
    cudaGetSymbolAddress((void**)&part,  g_part);
    cudaGetSymbolAddress((void**)&tmp,   g_tmp);
    cudaGetSymbolAddress((void**)&att,   g_att);
    cudaGetSymbolAddress((void**)&a,     g_a);
    cudaGetSymbolAddress((void**)&Pbuf,  g_P);
    cudaGetSymbolAddress((void**)&idx,   g_idx);
    cudaGetSymbolAddress((void**)&cnt,   g_cnt);
    cudaGetSymbolAddress((void**)&Bimg,  g_Bimg);
    cudaGetSymbolAddress((void**)&B1img, g_B1img);

    cudaFuncSetAttribute(k_sem_mma, cudaFuncAttributeMaxDynamicSharedMemorySize, SM_TOT);
    cudaFuncSetAttribute(k_P_mma,  cudaFuncAttributeMaxDynamicSharedMemorySize, SMP_TOT);
    cudaFuncSetAttribute(k_chain,  cudaFuncAttributeMaxDynamicSharedMemorySize, SMC_TOT);

    // fused zero + weight-image prep
    k_misc<<<528, 256>>>(W_ft2, Bimg, W_ft1, B1img,
                         (float4*)sem, (BB * CC * VV) / 4);

    // P = pos_emb @ W_ft1[1024:] on HMMA bf16 3-term
    dim3 gP((VV + 127) / 128, 8);
    k_P_mma<<<gP, 256, SMP_TOT>>>(pos_emb, B1img, Pbuf);

    // FUSED front-end chain (part, tmp, att, cont, a, compact)
    k_chain<<<NPERS, 512, SMC_TOT>>>(features, W_contact, b_contact, Wv, Wo,
                                     W_cls, b_cls, W_ft1, b_ft1,
                                     part, tmp, att, a, cont, idx, cnt);

    // persistent 1-term main GEMM
    k_sem_mma<<<NPERS, 256, SM_TOT>>>(a, Pbuf, Bimg, b_ft2, idx, cnt, sem);
}

// round 13
// speedup vs baseline: 8.6192x; 1.0533x over previous
#include <cuda_runtime.h>
#include <cuda_fp16.h>
#include <cuda_bf16.h>
#include <math.h>

// DECO decomposed (len-1 softmax == 1 → Wq/Wk/W_scene dead):
//   att  = (feat @ W_contact + b_c) @ Wv @ Wo            [16,1024]
//   cont = sigmoid(att @ W_cls + b_cls)                  [16,6890]
//   a    = att @ W_ft1[:1024] + b_ft1                    [16,512]
//   P    = pos_emb @ W_ft1[1024:]   (HMMA bf16 3-term, stored FP16)
//   sem[b,c,v] = mask * (relu(a[b]+P[v]) @ W_ft2 + b2)[c]
// R13: k_sem 512 threads (16 warps, 36 acc/thr) + P stored fp16 (half DRAM).
// Front-end chain fused persistent kernel (R12). Fused scattered epilogue.

#define BB   16
#define DF   1536
#define DD   1024
#define VV   6890
#define PDIM 256
#define HID  512
#define CC   133
#define NC   144
#define BROWS 136
#define NPERS 148

typedef unsigned long long u64;
typedef unsigned int u32;

__device__ float g_part[4 * BB * DD];
__device__ float g_tmp [4 * BB * DD];
__device__ float g_att [4 * BB * DD];
__device__ float g_a   [4 * BB * HID];
__device__ __align__(16) __half g_Ph[VV * HID];     // P in fp16
__device__ int   g_idx [BB * VV];
__device__ int   g_cnt [BB];
__device__ __align__(16) __half g_Bimg[8 * BROWS * 64];
__device__ __align__(16) __nv_bfloat16 g_B1img[2 * 4 * 512 * 64];
__device__ int   g_bar_arrive;
__device__ unsigned int g_bar_gen;

__device__ __forceinline__ u64 pk2(float lo, float hi) {
    u64 r; asm("mov.b64 %0, {%1, %2};" : "=l"(r) : "f"(lo), "f"(hi)); return r;
}
__device__ __forceinline__ void upk2(u64 v, float& lo, float& hi) {
    asm("mov.b64 {%0, %1}, %2;" : "=f"(lo), "=f"(hi) : "l"(v));
}
__device__ __forceinline__ u64 ffma2(u64 a, u64 b, u64 c) {
    u64 d; asm("fma.rn.f32x2 %0, %1, %2, %3;" : "=l"(d) : "l"(a), "l"(b), "l"(c));
    return d;
}
__device__ __forceinline__ u32 smem_u32(const void* p) {
    u32 a; asm("{ .reg .u64 t; cvta.to.shared.u64 t, %1; cvt.u32.u64 %0, t; }"
               : "=r"(a) : "l"(p));
    return a;
}
__device__ __forceinline__ void ldm_x4(u32* r, u32 addr) {
    asm volatile("ldmatrix.sync.aligned.m8n8.x4.shared.b16 {%0,%1,%2,%3}, [%4];"
        : "=r"(r[0]), "=r"(r[1]), "=r"(r[2]), "=r"(r[3]) : "r"(addr));
}
__device__ __forceinline__ void ldm_x2(u32* r, u32 addr) {
    asm volatile("ldmatrix.sync.aligned.m8n8.x2.shared.b16 {%0,%1}, [%2];"
        : "=r"(r[0]), "=r"(r[1]) : "r"(addr));
}
__device__ __forceinline__ void mma_f16(float* d, const u32* a, const u32* b) {
    asm volatile("mma.sync.aligned.m16n8k16.row.col.f32.f16.f16.f32 "
        "{%0,%1,%2,%3}, {%4,%5,%6,%7}, {%8,%9}, {%0,%1,%2,%3};"
        : "+f"(d[0]), "+f"(d[1]), "+f"(d[2]), "+f"(d[3])
        : "r"(a[0]), "r"(a[1]), "r"(a[2]), "r"(a[3]), "r"(b[0]), "r"(b[1]));
}
__device__ __forceinline__ void mma_bf16(float* d, const u32* a, const u32* b) {
    asm volatile("mma.sync.aligned.m16n8k16.row.col.f32.bf16.bf16.f32 "
        "{%0,%1,%2,%3}, {%4,%5,%6,%7}, {%8,%9}, {%0,%1,%2,%3};"
        : "+f"(d[0]), "+f"(d[1]), "+f"(d[2]), "+f"(d[3])
        : "r"(a[0]), "r"(a[1]), "r"(a[2]), "r"(a[3]), "r"(b[0]), "r"(b[1]));
}
__device__ __forceinline__ u32 h2u(__half2 h) {
    u32 r; asm("mov.b32 %0, %1;" : "=r"(r) : "r"(*(u32*)&h)); return r;
}
__device__ __forceinline__ void cpasync16(u32 dst, const void* src) {
    asm volatile("cp.async.cg.shared.global [%0], [%1], 16;"
                 :: "r"(dst), "l"(src) : "memory");
}
__device__ __forceinline__ void cpasync_commit() {
    asm volatile("cp.async.commit_group;" ::: "memory");
}
__device__ __forceinline__ void cpasync_wait0() {
    asm volatile("cp.async.wait_group 0;" ::: "memory");
}

__device__ __forceinline__ void grid_bar() {
    __syncthreads();
    if (threadIdx.x == 0) {
        __threadfence();
        unsigned gen = atomicAdd(&g_bar_gen, 0u);
        int a = atomicAdd(&g_bar_arrive, 1);
        if (a == NPERS - 1) {
            g_bar_arrive = 0;
            __threadfence();
            atomicAdd(&g_bar_gen, 1u);
        } else {
            while (atomicAdd(&g_bar_gen, 0u) == gen) {}
        }
        __threadfence();
    }
    __syncthreads();
}

// k_sem smem layout (bytes)
#define SM_AS     0
#define SM_H(bf)  (2048 + (bf) * 18432)
#define SM_BALL   38912
#define SM_BC(ch) (SM_BALL + (ch) * 17408)
#define SM_TOT    178176
// k_P_mma smem layout (bytes)
#define SMP_HH 0
#define SMP_HL 16384
#define SMP_BH 32768
#define SMP_BL 40960
#define SMP_TOT 49152
// k_chain smem
#define SMC_TOT ((128 * 18 + 16 * 1024) * 4)

// ---------------------------------------------------------------------------
// Fused misc: [0,8) prepW; [8,16) prepW1; [16,528) zero sem.
// ---------------------------------------------------------------------------
__global__ void __launch_bounds__(256)
k_misc(const float* __restrict__ W2, __half* __restrict__ Bimg,
       const float* __restrict__ W1, __nv_bfloat16* __restrict__ B1,
       float4* __restrict__ zp, int n4)
{
    const int bx = blockIdx.x;
    const int tid = threadIdx.x;
    if (bx < 8) {
        const int img = bx;
        for (int e = tid; e < BROWS * 64; e += 256) {
            int n = e >> 6, k = e & 63;
            float w = (n < CC) ? W2[(size_t)(img * 64 + k) * CC + n] : 0.f;
            int off = (n << 6) + (((k >> 3) ^ (n & 7)) << 3) + (k & 7);
            Bimg[(size_t)img * (BROWS * 64) + off] = __float2half_rn(w);
        }
    } else if (bx < 16) {
        const int blk = bx - 8;
        const int plane = blk >> 2, ch = blk & 3;
        for (int e = tid; e < 512 * 64; e += 256) {
            int n = e >> 6, k = e & 63;
            float w = W1[(size_t)(DD + ch * 64 + k) * HID + n];
            __nv_bfloat16 h = __float2bfloat16(w);
            __nv_bfloat16 val = plane ? __float2bfloat16(w - __bfloat162float(h)) : h;
            int off = (n << 6) + (((k >> 3) ^ (n & 7)) << 3) + (k & 7);
            B1[(size_t)blk * (512 * 64) + off] = val;
        }
    } else {
        const int zb = bx - 16;
        for (int i = zb * 256 + tid; i < n4; i += 512 * 256)
            zp[i] = make_float4(0.f, 0.f, 0.f, 0.f);
    }
}

// ---------------------------------------------------------------------------
// Device fn: split-K skinny GEMM vblock (512 thr = 32 cols x 16 K-slices).
// ---------------------------------------------------------------------------
__device__ void skinny_dev(const float* __restrict__ in,
                           const float* __restrict__ W,
                           const float* __restrict__ bias,
                           float* __restrict__ out,
                           int K, int N, int nsum, int colb, int ky,
                           float* in_s, float* red)
{
    const int tid  = threadIdx.x;
    const int col  = tid & 31;
    const int slc  = tid >> 5;
    const int colg = colb * 32 + col;
    const int colc = colg < N ? colg : N - 1;
    const int kspan = K >> 2;
    const int kbase = ky * kspan;

    u64 acc2[8];
#pragma unroll
    for (int m = 0; m < 8; m++) acc2[m] = 0ull;

    for (int k0 = kbase; k0 < kbase + kspan; k0 += 128) {
        __syncthreads();
#pragma unroll
        for (int i = 0; i < 4; i++) {
            int e = tid + 512 * i;
            int b = e >> 7, k = e & 127;
            float s = 0.f;
            for (int sc = 0; sc < nsum; sc++)
                s += in[(size_t)sc * BB * K + b * K + k0 + k];
            in_s[k * 18 + b] = s;
        }
        __syncthreads();
#pragma unroll
        for (int kk = 0; kk < 8; kk++) {
            int k = slc * 8 + kk;
            float w = W[(size_t)(k0 + k) * N + colc];
            u64 w2 = pk2(w, w);
            const u64* ip = (const u64*)&in_s[k * 18];
#pragma unroll
            for (int m = 0; m < 8; m++)
                acc2[m] = ffma2(ip[m], w2, acc2[m]);
        }
    }
    float* rp = &red[slc * 512 + col * 16];
#pragma unroll
    for (int m = 0; m < 8; m++) {
        float lo, hi; upk2(acc2[m], lo, hi);
        rp[2 * m] = lo; rp[2 * m + 1] = hi;
    }
    __syncthreads();
    {
        int c = tid >> 4, b = tid & 15;
        float s = 0.f;
#pragma unroll
        for (int sl = 0; sl < 16; sl++) s += red[sl * 512 + c * 16 + b];
        int cg = colb * 32 + c;
        if (cg < N) {
            float bb = (bias && ky == 0) ? bias[cg] : 0.f;
            out[(size_t)ky * BB * N + b * N + cg] = s + bb;
        }
    }
    __syncthreads();
}

// ---------------------------------------------------------------------------
// Device fn: cont vblock (64 cols).
// ---------------------------------------------------------------------------
__device__ void cont_dev(const float* __restrict__ att,
                         const float* __restrict__ Wc,
                         const float* __restrict__ bc,
                         float* __restrict__ out, int vb,
                         float* in_s, float* red)
{
    const int tid = threadIdx.x;
    const int cp  = tid & 31;
    const int slc = tid >> 5;
    const int col0 = vb * 64 + 2 * cp;
    const int colc = col0 <= VV - 2 ? col0 : VV - 2;

    u64 acc[2][8];
#pragma unroll
    for (int j = 0; j < 2; j++)
#pragma unroll
        for (int m = 0; m < 8; m++) acc[j][m] = 0ull;

    for (int k0 = 0; k0 < DD; k0 += 128) {
        __syncthreads();
#pragma unroll
        for (int i = 0; i < 4; i++) {
            int e = tid + 512 * i;
            int b = e >> 7, k = e & 127;
            float s = 0.f;
#pragma unroll
            for (int sc = 0; sc < 4; sc++)
                s += att[(size_t)sc * BB * DD + b * DD + k0 + k];
            in_s[k * 18 + b] = s;
        }
        __syncthreads();
#pragma unroll
        for (int kk = 0; kk < 8; kk++) {
            int k = slc * 8 + kk;
            float2 w = *(const float2*)&Wc[(size_t)(k0 + k) * VV + colc];
            u64 w0 = pk2(w.x, w.x), w1 = pk2(w.y, w.y);
            const u64* ip = (const u64*)&in_s[k * 18];
#pragma unroll
            for (int m = 0; m < 8; m++) {
                acc[0][m] = ffma2(ip[m], w0, acc[0][m]);
                acc[1][m] = ffma2(ip[m], w1, acc[1][m]);
            }
        }
    }
#pragma unroll
    for (int j = 0; j < 2; j++) {
        float* rp = &red[slc * 1024 + (2 * cp + j) * 16];
#pragma unroll
        for (int m = 0; m < 8; m++) {
            float lo, hi; upk2(acc[j][m], lo, hi);
            rp[2 * m] = lo; rp[2 * m + 1] = hi;
        }
    }
    __syncthreads();
    for (int o = tid; o < 1024; o += 512) {
        int c = o >> 4, b = o & 15;
        float s = 0.f;
#pragma unroll
        for (int sl = 0; sl < 16; sl++) s += red[sl * 1024 + c * 16 + b];
        int cg = vb * 64 + c;
        if (cg < VV)
            out[b * VV + cg] = 1.f / (1.f + expf(-(s + bc[cg])));
    }
    __syncthreads();
}

// ---------------------------------------------------------------------------
// Device fn: order-preserving compaction for batch b.
// ---------------------------------------------------------------------------
__device__ void compact_dev(const float* __restrict__ cont,
                            int* __restrict__ idx, int* __restrict__ cnt,
                            int b)
{
    const int tid = threadIdx.x;
    const int lane = tid & 31, wrp = tid >> 5;
    __shared__ int wexc[16];
    __shared__ int s_base, s_tot;
    if (tid == 0) s_base = 0;
    __syncthreads();
    for (int v0 = 0; v0 < VV; v0 += 512) {
        int v = v0 + tid;
        int m = (v < VV) && (cont[b * VV + v] > 0.5f);
        unsigned bal = __ballot_sync(0xffffffffu, m);
        int wsum = __popc(bal);
        int pw = __popc(bal & ((1u << lane) - 1u));
        if (lane == 0) wexc[wrp] = wsum;
        __syncthreads();
        if (tid < 16) {
            int sv = wexc[tid];
            int e = sv;
#pragma unroll
            for (int d = 1; d < 16; d <<= 1) {
                int t = __shfl_up_sync(0xffffu, e, d);
                if (tid >= d) e += t;
            }
            wexc[tid] = e - sv;
            if (tid == 15) s_tot = e;
        }
        __syncthreads();
        int pos = s_base + wexc[wrp] + pw;
        if (v < VV && m) idx[b * VV + pos] = v;
        __syncthreads();
        if (tid == 0) s_base += s_tot;
        __syncthreads();
    }
    if (tid == 0) cnt[b] = s_base;
}

// ---------------------------------------------------------------------------
// FUSED front-end chain (R12): persistent grid=148, device-wide barriers.
// ---------------------------------------------------------------------------
__global__ void __launch_bounds__(512, 1)
k_chain(const float* __restrict__ features,
        const float* __restrict__ W_contact, const float* __restrict__ b_contact,
        const float* __restrict__ Wv, const float* __restrict__ Wo,
        const float* __restrict__ W_cls, const float* __restrict__ b_cls,
        const float* __restrict__ W_ft1, const float* __restrict__ b_ft1,
        float* __restrict__ part, float* __restrict__ tmp,
        float* __restrict__ att, float* __restrict__ a,
        float* __restrict__ cont, int* __restrict__ idx, int* __restrict__ cnt)
{
    extern __shared__ float smc[];
    float* in_s = smc;
    float* red  = smc + 128 * 18;
    const int bid = blockIdx.x;

    if (bid < 128)
        skinny_dev(features, W_contact, b_contact, part, DF, DD, 1,
                   bid & 31, bid >> 5, in_s, red);
    grid_bar();
    if (bid < 128)
        skinny_dev(part, Wv, nullptr, tmp, DD, DD, 4, bid & 31, bid >> 5, in_s, red);
    grid_bar();
    if (bid < 128)
        skinny_dev(tmp, Wo, nullptr, att, DD, DD, 4, bid & 31, bid >> 5, in_s, red);
    grid_bar();
    if (bid < 108)
        cont_dev(att, W_cls, b_cls, cont, bid, in_s, red);
    grid_bar();
    if (bid < 64)
        skinny_dev(att, W_ft1, b_ft1, a, DD, HID, 4, bid & 15, bid >> 4, in_s, red);
    else if (bid < 80)
        compact_dev(cont, idx, cnt, bid - 64);
}

// ---------------------------------------------------------------------------
// P = pos_emb @ W_ft1[1024:] via bf16 HMMA 3-term. Output stored FP16.
// ---------------------------------------------------------------------------
__global__ void __launch_bounds__(256, 2)
k_P_mma(const float* __restrict__ pos, const __nv_bfloat16* __restrict__ B1,
        __half* __restrict__ Pout)
{
    extern __shared__ char smem[];
    const u32 sb = smem_u32(smem);
    const int tid = threadIdx.x;
    const int wid = tid >> 5;
    const int l   = tid & 31;
    const int wm = wid & 3;
    const int wn = wid >> 2;
    const int vbase = blockIdx.x * 128;
    const int hbase = blockIdx.y * 64;

    const int r = tid & 127;
    const int half = tid >> 7;
    const int v = vbase + r;
    const int vc = v < VV ? v : VV - 1;
    const float* __restrict__ prow = pos + (size_t)vc * PDIM + half * 32;

    float acc[2][4][4];
#pragma unroll
    for (int i = 0; i < 2; i++)
#pragma unroll
        for (int j = 0; j < 4; j++)
#pragma unroll
            for (int q = 0; q < 4; q++) acc[i][j][q] = 0.f;

    for (int ch = 0; ch < 4; ch++) {
        float4 pf[8];
#pragma unroll
        for (int q = 0; q < 8; q++)
            pf[q] = *(const float4*)(prow + ch * 64 + 4 * q);
#pragma unroll
        for (int kb = 0; kb < 2; kb++) {
            float x[16];
#pragma unroll
            for (int q = 0; q < 4; q++) {
                float4 p4 = pf[kb * 4 + q];
                x[4*q+0] = p4.x; x[4*q+1] = p4.y; x[4*q+2] = p4.z; x[4*q+3] = p4.w;
            }
            u32 hw[8], lw[8];
#pragma unroll
            for (int i = 0; i < 8; i++) {
                __nv_bfloat16 h0 = __float2bfloat16(x[2*i]);
                __nv_bfloat16 h1 = __float2bfloat16(x[2*i+1]);
                __nv_bfloat16 l0 = __float2bfloat16(x[2*i]   - __bfloat162float(h0));
                __nv_bfloat16 l1 = __float2bfloat16(x[2*i+1] - __bfloat162float(h1));
                hw[i] = (u32)__bfloat16_as_ushort(h0) | ((u32)__bfloat16_as_ushort(h1) << 16);
                lw[i] = (u32)__bfloat16_as_ushort(l0) | ((u32)__bfloat16_as_ushort(l1) << 16);
            }
            const u32 c0 = (u32)(half * 4 + kb * 2);
            const u32 q7 = (u32)r & 7u;
            const u32 off0 = (u32)(r << 7) + ((c0 ^ q7) << 4);
            const u32 off1 = (u32)(r << 7) + (((c0 + 1u) ^ q7) << 4);
            asm volatile("st.shared.v4.b32 [%0], {%1,%2,%3,%4};"
                :: "r"(sb + SMP_HH + off0), "r"(hw[0]), "r"(hw[1]), "r"(hw[2]), "r"(hw[3]) : "memory");
            asm volatile("st.shared.v4.b32 [%0], {%1,%2,%3,%4};"
                :: "r"(sb + SMP_HH + off1), "r"(hw[4]), "r"(hw[5]), "r"(hw[6]), "r"(hw[7]) : "memory");
            asm volatile("st.shared.v4.b32 [%0], {%1,%2,%3,%4};"
                :: "r"(sb + SMP_HL + off0), "r"(lw[0]), "r"(lw[1]), "r"(lw[2]), "r"(lw[3]) : "memory");
            asm volatile("st.shared.v4.b32 [%0], {%1,%2,%3,%4};"
                :: "r"(sb + SMP_HL + off1), "r"(lw[4]), "r"(lw[5]), "r"(lw[6]), "r"(lw[7]) : "memory");
        }
        {
            const uint4* sH = (const uint4*)(B1 + (size_t)ch * 32768 + (size_t)hbase * 64);
            const uint4* sL = (const uint4*)(B1 + (size_t)(4 + ch) * 32768 + (size_t)hbase * 64);
            uint4* dH = (uint4*)(smem + SMP_BH);
            uint4* dL = (uint4*)(smem + SMP_BL);
#pragma unroll
            for (int i = 0; i < 2; i++) {
                int e = tid + 256 * i;
                dH[e] = sH[e]; dL[e] = sL[e];
            }
        }
        __syncthreads();
#pragma unroll
        for (int ks = 0; ks < 4; ks++) {
            u32 ah[2][4], al[2][4];
#pragma unroll
            for (int mt = 0; mt < 2; mt++) {
                int ra = wm * 32 + mt * 16 + (l & 15);
                u32 c = (u32)(l >> 4) + 2u * ks;
                u32 sw = ((c ^ ((u32)ra & 7u)) << 4);
                ldm_x4(ah[mt], sb + SMP_HH + (u32)(ra << 7) + sw);
                ldm_x4(al[mt], sb + SMP_HL + (u32)(ra << 7) + sw);
            }
#pragma unroll
            for (int p = 0; p < 2; p++) {
                int rb = wn * 32 + p * 16 + (l & 7) + ((l >> 4) & 1) * 8;
                u32 cf = 2u * ks + ((u32)(l >> 3) & 1u);
                u32 swb = ((cf ^ ((u32)rb & 7u)) << 4);
                u32 bh[4], bl[4];
                ldm_x4(bh, sb + SMP_BH + (u32)(rb << 7) + swb);
                ldm_x4(bl, sb + SMP_BL + (u32)(rb << 7) + swb);
#pragma unroll
                for (int mt = 0; mt < 2; mt++)
#pragma unroll
                    for (int t = 0; t < 2; t++) {
                        float* d = acc[mt][p * 2 + t];
                        mma_bf16(d, ah[mt], &bh[2 * t]);
                        mma_bf16(d, ah[mt], &bl[2 * t]);
                        mma_bf16(d, al[mt], &bh[2 * t]);
                    }
            }
        }
        __syncthreads();
    }

    const int g = l >> 2, tg = l & 3;
#pragma unroll
    for (int mt = 0; mt < 2; mt++) {
        const int i0 = vbase + wm * 32 + mt * 16 + g;
        const int i1 = i0 + 8;
#pragma unroll
        for (int nt = 0; nt < 4; nt++) {
            const int col = hbase + wn * 32 + nt * 8 + tg * 2;
            if (i0 < VV)
                *(__half2*)&Pout[(size_t)i0 * HID + col]
                    = __floats2half2_rn(acc[mt][nt][0], acc[mt][nt][1]);
            if (i1 < VV)
                *(__half2*)&Pout[(size_t)i1 * HID + col]
                    = __floats2half2_rn(acc[mt][nt][2], acc[mt][nt][3]);
        }
    }
}

// ---------------------------------------------------------------------------
// PERSISTENT main GEMM, 1-term fp16, 512 threads (16 warps: 8m x 2n),
// P read as fp16, all B chunks smem-resident, fused scattered epilogue.
// ---------------------------------------------------------------------------
__global__ void __launch_bounds__(512, 1)
k_sem_mma(const float* __restrict__ A4,
          const __half* __restrict__ Ph,
          const __half* __restrict__ Bimg,
          const float* __restrict__ b2,
          const int* __restrict__ idx,
          const int* __restrict__ cnt,
          float* __restrict__ sem)
{
    extern __shared__ char smem[];
    const u32 sb = smem_u32(smem);
    const int tid = threadIdx.x;
    const int wid = tid >> 5;
    const int l   = tid & 31;
    const int wm = wid & 7;          // m16 tile (rows wm*16..+16)
    const int wn = wid >> 3;         // 0/1: cols wn*72..+72
    const int r = tid & 127;         // producer row
    const int quarter = tid >> 7;    // producer k-segment (16 k each)
    const u32 qr = ((u32)r >> 3) & 3;
    const u32 hbase_off = (u32)(r * 144);

    // one-time: load ALL 8 B chunk images
    {
        const char* srcB = (const char*)(Bimg);
        u32 dstB = sb + SM_BALL;
        for (int e = tid; e < 8 * 1088; e += 512)
            cpasync16(dstB + e * 16, srcB + e * 16);
        cpasync_commit();
    }

    int offv[17];
    offv[0] = 0;
#pragma unroll
    for (int b = 0; b < 16; b++)
        offv[b + 1] = offv[b] + ((cnt[b] + 127) >> 7);
    const int total = offv[16];

    float* a_sm = (float*)(smem + SM_AS);
    cpasync_wait0();

    for (int w = blockIdx.x; w < total; w += NPERS) {
        int b = 0;
#pragma unroll
        for (int t = 0; t < 15; t++) if (w >= offv[b + 1]) b++;
        const int cntb = cnt[b];
        const int ibase = (w - offv[b]) << 7;

        // stage a[b] (sum of 4 partials) — 512 thr: one element each
        {
            float s = 0.f;
#pragma unroll
            for (int sc = 0; sc < 4; sc++)
                s += A4[(size_t)sc * BB * HID + b * HID + tid];
            a_sm[tid] = s;
        }

        const int ig = ibase + r;
        const int vrow = idx[b * VV + (ig < cntb ? ig : cntb - 1)];
        const __half* __restrict__ prow = Ph + (size_t)vrow * HID + quarter * 16;

        float acc[9][4];
#pragma unroll
        for (int j = 0; j < 9; j++)
#pragma unroll
            for (int q = 0; q < 4; q++) acc[j][q] = 0.f;

        uint4 pf[2];
        pf[0] = *(const uint4*)(prow);
        pf[1] = *(const uint4*)(prow + 8);
        __syncthreads();   // a_sm ready

        // produce H(0): 16 k values per thread
        {
            const float* ap = a_sm + quarter * 16;
            const __half2* ph = (const __half2*)pf;
            u32 hw[8];
#pragma unroll
            for (int i = 0; i < 8; i++) {
                float2 p2 = __half22float2(ph[i]);
                float x0 = fmaxf(p2.x + ap[2*i],     0.f);
                float x1 = fmaxf(p2.y + ap[2*i + 1], 0.f);
                hw[i] = h2u(__floats2half2_rn(x0, x1));
            }
            const u32 c0 = (u32)(quarter * 2);
            const u32 off0 = hbase_off + ((c0 ^ qr) << 4);
            const u32 off1 = hbase_off + (((c0 + 1u) ^ qr) << 4);
            asm volatile("st.shared.v4.b32 [%0], {%1,%2,%3,%4};"
                :: "r"(sb + SM_H(0) + off0), "r"(hw[0]), "r"(hw[1]), "r"(hw[2]), "r"(hw[3]) : "memory");
            asm volatile("st.shared.v4.b32 [%0], {%1,%2,%3,%4};"
                :: "r"(sb + SM_H(0) + off1), "r"(hw[4]), "r"(hw[5]), "r"(hw[6]), "r"(hw[7]) : "memory");
        }

        int buf = 0;
        for (int ch = 0; ch < 8; ch++) {
            __syncthreads();   // H(ch) visible
            const int nb = buf ^ 1;
            if (ch < 7) {
                const __half* ps = prow + (ch + 1) * 64;
                pf[0] = *(const uint4*)(ps);
                pf[1] = *(const uint4*)(ps + 8);
            }

            const u32 hH = sb + SM_H(buf);
            const u32 bB = sb + SM_BC(ch);
#pragma unroll
            for (int ks = 0; ks < 4; ks++) {
                u32 ah[4];
                {
                    int ra = wm * 16 + (l & 15);
                    u32 qa = ((u32)ra >> 3) & 3;
                    u32 chk = (((u32)(l >> 4) + 2u * ks) ^ qa) << 4;
                    ldm_x4(ah, hH + (u32)(ra * 144) + chk);
                }
#pragma unroll
                for (int p = 0; p < 4; p++) {
                    int rb = wn * 72 + p * 16 + (l & 7) + ((l >> 4) & 1) * 8;
                    u32 chunkf = 2u * ks + ((u32)(l >> 3) & 1u);
                    u32 bb[4];
                    ldm_x4(bb, bB + (u32)(rb << 7) + ((chunkf ^ ((u32)rb & 7u)) << 4));
#pragma unroll
                    for (int t = 0; t < 2; t++)
                        mma_f16(acc[p * 2 + t], ah, &bb[2 * t]);
                }
                {
                    int rb2 = 64 + (l & 7);
                    u32 chunkf = 2u * ks + ((u32)(l >> 3) & 1u);
                    u32 s2[2];
                    ldm_x2(s2, bB + (u32)(rb2 << 7) + ((chunkf ^ ((u32)rb2 & 7u)) << 4));
                    mma_f16(acc[8], ah, s2);
                }
            }

            if (ch < 7) {
                const float* ap = a_sm + (ch + 1) * 64 + quarter * 16;
                const __half2* ph = (const __half2*)pf;
                u32 hw[8];
#pragma unroll
                for (int i = 0; i < 8; i++) {
                    float2 p2 = __half22float2(ph[i]);
                    float x0 = fmaxf(p2.x + ap[2*i],     0.f);
                    float x1 = fmaxf(p2.y + ap[2*i + 1], 0.f);
                    hw[i] = h2u(__floats2half2_rn(x0, x1));
                }
                const u32 c0 = (u32)(quarter * 2);
                const u32 off0 = hbase_off + ((c0 ^ qr) << 4);
                const u32 off1 = hbase_off + (((c0 + 1u) ^ qr) << 4);
                asm volatile("st.shared.v4.b32 [%0], {%1,%2,%3,%4};"
                    :: "r"(sb + SM_H(nb) + off0), "r"(hw[0]), "r"(hw[1]), "r"(hw[2]), "r"(hw[3]) : "memory");
                asm volatile("st.shared.v4.b32 [%0], {%1,%2,%3,%4};"
                    :: "r"(sb + SM_H(nb) + off1), "r"(hw[4]), "r"(hw[5]), "r"(hw[6]), "r"(hw[7]) : "memory");
            }
            buf = nb;
        }

        // fused epilogue: bias + scattered store sem[b, col, idx[i]]
        const int g = l >> 2, tg = l & 3;
        const int i0 = ibase + wm * 16 + g;
        const int i1 = i0 + 8;
        const bool ok0 = i0 < cntb, ok1 = i1 < cntb;
        const int v0 = ok0 ? idx[b * VV + i0] : 0;
        const int v1 = ok1 ? idx[b * VV + i1] : 0;
#pragma unroll
        for (int nt = 0; nt < 9; nt++) {
            const int cbase = wn * 72 + nt * 8 + tg * 2;
#pragma unroll
            for (int q = 0; q < 2; q++) {
                const int col = cbase + q;
                if (col >= CC) continue;
                const float bias = __ldg(&b2[col]);
                if (ok0) sem[((size_t)b * CC + col) * VV + v0] = acc[nt][q] + bias;
                if (ok1) sem[((size_t)b * CC + col) * VV + v1] = acc[nt][2 + q] + bias;
            }
        }
    }
}

// ---------------------------------------------------------------------------
extern "C" void kernel_launch(void* const* d_in, const int* in_sizes, int n_in,
                              void* d_out, int out_size)
{
    const float* features  = (const float*)d_in[0];
    const float* W_contact = (const float*)d_in[3];
    const float* b_contact = (const float*)d_in[4];
    const float* Wv        = (const float*)d_in[7];
    const float* Wo        = (const float*)d_in[8];
    const float* W_cls     = (const float*)d_in[9];
    const float* b_cls     = (const float*)d_in[10];
    const float* pos_emb   = (const float*)d_in[11];
    const float* W_ft1     = (const float*)d_in[12];
    const float* b_ft1     = (const float*)d_in[13];
    const float* W_ft2     = (const float*)d_in[14];
    const float* b_ft2     = (const float*)d_in[15];

    float* out  = (float*)d_out;
    float* cont = out;                  // [16, 6890]
    float* sem  = out + BB * VV;        // [16, 133, 6890]

    float *part, *tmp, *att, *a;
    __half* Ph;
    int *idx, *cnt;
    __half* Bimg;
    __nv_bfloat16* B1img;
    cudaGetSymbolAddress((void**)&part,  g_part);
    cudaGetSymbolAddress((void**)&tmp,   g_tmp);
    cudaGetSymbolAddress((void**)&att,   g_att);
    cudaGetSymbolAddress((void**)&a,     g_a);
    cudaGetSymbolAddress((void**)&Ph,    g_Ph);
    cudaGetSymbolAddress((void**)&idx,   g_idx);
    cudaGetSymbolAddress((void**)&cnt,   g_cnt);
    cudaGetSymbolAddress((void**)&Bimg,  g_Bimg);
    cudaGetSymbolAddress((void**)&B1img, g_B1img);

    cudaFuncSetAttribute(k_sem_mma, cudaFuncAttributeMaxDynamicSharedMemorySize, SM_TOT);
    cudaFuncSetAttribute(k_P_mma,  cudaFuncAttributeMaxDynamicSharedMemorySize, SMP_TOT);
    cudaFuncSetAttribute(k_chain,  cudaFuncAttributeMaxDynamicSharedMemorySize, SMC_TOT);

    // fused zero + weight-image prep
    k_misc<<<528, 256>>>(W_ft2, Bimg, W_ft1, B1img,
                         (float4*)sem, (BB * CC * VV) / 4);

    // P (fp16) = pos_emb @ W_ft1[1024:] on HMMA bf16 3-term
    dim3 gP((VV + 127) / 128, 8);
    k_P_mma<<<gP, 256, SMP_TOT>>>(pos_emb, B1img, Ph);

    // FUSED front-end chain
    k_chain<<<NPERS, 512, SMC_TOT>>>(features, W_contact, b_contact, Wv, Wo,
                                     W_cls, b_cls, W_ft1, b_ft1,
                                     part, tmp, att, a, cont, idx, cnt);

    // persistent 1-term main GEMM (512 thr, fp16 P)
    k_sem_mma<<<NPERS, 512, SM_TOT>>>(a, Ph, Bimg, b_ft2, idx, cnt, sem);
}